// round 9
// baseline (speedup 1.0000x reference)
#include <cuda_runtime.h>
#include <cuda_bf16.h>
#include <cuda_fp16.h>
#include <math.h>
#include <stdint.h>

// Problem constants
#define TT   2048
#define DD   768
#define HH   12
#define DHH  64
#define LL   6
#define FFD  3072
#define VV   32000
#define QKV3 (3*DD)

// ---------------- scratch ----------------
__device__ float g_h  [TT*DD];
__device__ float g_hn [TT*DD];
__device__ float g_qkv[TT*QKV3];
__device__ float g_ctx[TT*DD];
__device__ float g_ff [TT*FFD];
__device__ float g_nll[TT];
__device__ float g_val[TT];

// ---------------- helpers ----------------
__device__ __forceinline__ uint32_t smem_u32(const void* p){
    uint32_t a;
    asm("{ .reg .u64 t; cvta.to.shared.u64 t, %1; cvt.u32.u64 %0, t; }" : "=r"(a) : "l"(p));
    return a;
}
__device__ __forceinline__ uint32_t packbf(float x0, float x1){
    uint32_t r;
    asm("cvt.rn.bf16x2.f32 %0, %1, %2;" : "=r"(r) : "f"(x1), "f"(x0));
    return r;
}
__device__ __forceinline__ uint32_t packhf(float x0, float x1){
    uint32_t r;
    asm("cvt.rn.f16x2.f32 %0, %1, %2;" : "=r"(r) : "f"(x1), "f"(x0));
    return r;
}
__device__ __forceinline__ float h2f_lo(uint32_t p){
    float f; asm("{ .reg .b16 h, dummy; mov.b32 {h, dummy}, %1; cvt.f32.f16 %0, h; }" : "=f"(f) : "r"(p));
    return f;
}
__device__ __forceinline__ float h2f_hi(uint32_t p){
    float f; asm("{ .reg .b16 h, dummy; mov.b32 {dummy, h}, %1; cvt.f32.f16 %0, h; }" : "=f"(f) : "r"(p));
    return f;
}
__device__ __forceinline__ float ex2f(float x){
    float y; asm("ex2.approx.f32 %0, %1;" : "=f"(y) : "f"(x)); return y;
}
__device__ __forceinline__ void ldsm4(uint32_t &r0, uint32_t &r1, uint32_t &r2, uint32_t &r3,
                                      uint32_t addr){
    asm volatile("ldmatrix.sync.aligned.m8n8.x4.shared.b16 {%0,%1,%2,%3}, [%4];"
        : "=r"(r0), "=r"(r1), "=r"(r2), "=r"(r3) : "r"(addr));
}
__device__ __forceinline__ void ldsm4t(uint32_t &r0, uint32_t &r1, uint32_t &r2, uint32_t &r3,
                                       uint32_t addr){
    asm volatile("ldmatrix.sync.aligned.m8n8.x4.trans.shared.b16 {%0,%1,%2,%3}, [%4];"
        : "=r"(r0), "=r"(r1), "=r"(r2), "=r"(r3) : "r"(addr));
}
__device__ __forceinline__ void mma16816(float* d, const uint32_t* a, const uint32_t* b){
    asm volatile("mma.sync.aligned.m16n8k16.row.col.f32.bf16.bf16.f32 "
        "{%0,%1,%2,%3}, {%4,%5,%6,%7}, {%8,%9}, {%0,%1,%2,%3};"
        : "+f"(d[0]), "+f"(d[1]), "+f"(d[2]), "+f"(d[3])
        : "r"(a[0]), "r"(a[1]), "r"(a[2]), "r"(a[3]), "r"(b[0]), "r"(b[1]));
}
__device__ __forceinline__ void mma16816h(float* d, const uint32_t* a, const uint32_t* b){
    asm volatile("mma.sync.aligned.m16n8k16.row.col.f32.f16.f16.f32 "
        "{%0,%1,%2,%3}, {%4,%5,%6,%7}, {%8,%9}, {%0,%1,%2,%3};"
        : "+f"(d[0]), "+f"(d[1]), "+f"(d[2]), "+f"(d[3])
        : "r"(a[0]), "r"(a[1]), "r"(a[2]), "r"(a[3]), "r"(b[0]), "r"(b[1]));
}

// ---------------- reductions ----------------
__device__ __forceinline__ float warpSum(float v){
#pragma unroll
    for (int o = 16; o; o >>= 1) v += __shfl_xor_sync(0xffffffffu, v, o);
    return v;
}
__device__ __forceinline__ float warpMax(float v){
#pragma unroll
    for (int o = 16; o; o >>= 1) v = fmaxf(v, __shfl_xor_sync(0xffffffffu, v, o));
    return v;
}
__device__ float blockSum(float v){
    __shared__ float s[9];
    __syncthreads();
    int lane = threadIdx.x & 31, w = threadIdx.x >> 5;
    v = warpSum(v);
    if (lane == 0) s[w] = v;
    __syncthreads();
    if (w == 0){
        float x = (lane < (int)(blockDim.x >> 5)) ? s[lane] : 0.f;
        x = warpSum(x);
        if (lane == 0) s[8] = x;
    }
    __syncthreads();
    return s[8];
}
__device__ float blockMax(float v){
    __shared__ float s[9];
    __syncthreads();
    int lane = threadIdx.x & 31, w = threadIdx.x >> 5;
    v = warpMax(v);
    if (lane == 0) s[w] = v;
    __syncthreads();
    if (w == 0){
        float x = (lane < (int)(blockDim.x >> 5)) ? s[lane] : -INFINITY;
        x = warpMax(x);
        if (lane == 0) s[8] = x;
    }
    __syncthreads();
    return s[8];
}

// ---------------- embedding ----------------
__global__ void embed_kernel(const int* __restrict__ x,
                             const float* __restrict__ tok,
                             const float* __restrict__ pos){
    int t  = blockIdx.x;
    int id = x[t];
    const float* tr = tok + (size_t)id * DD;
    const float* pr = pos + (size_t)t  * DD;
    for (int d = threadIdx.x; d < DD; d += blockDim.x)
        g_h[t*DD + d] = tr[d] + pr[d];
}

// ---------------- layernorm ----------------
__global__ void ln_kernel(const float* __restrict__ in, float* __restrict__ out,
                          const float* __restrict__ g, const float* __restrict__ b){
    __shared__ float row[DD];
    int t = blockIdx.x;
    const float* r = in + (size_t)t * DD;
    float s = 0.f;
    for (int d = threadIdx.x; d < DD; d += blockDim.x){ float v = r[d]; row[d] = v; s += v; }
    s = blockSum(s);
    float mean = s * (1.f / DD);
    float q = 0.f;
    for (int d = threadIdx.x; d < DD; d += blockDim.x){ float v = row[d] - mean; q += v*v; }
    q = blockSum(q);
    float rstd = rsqrtf(q * (1.f / DD) + 1e-5f);
    for (int d = threadIdx.x; d < DD; d += blockDim.x)
        out[t*DD + d] = (row[d] - mean) * rstd * g[d] + b[d];
}

// ================== fp16 2-product tensor-core GEMM, 3-stage, 2 CTAs/SM ==========
// C[M,N] = A[M,K] @ B[N,K]^T (+bias)(+gelu)(+res), fp32 in/out.
// 128x128 CTA tile, BK=32, 8 warps (2x4), warp tile 64x32.
// A = fp16 hi + lo residual (exact to ~2^-22), B single fp16.
// stage: Ahi[10240] Alo[10240] Bh[10240] = 30720 B; 3 stages = 92160 B.
// 2 CTAs/SM (184KB smem, regs capped at 128).
#define ROWB 80
#define STAGE_B 30720
#define G_SMEM (3*STAGE_B)

__device__ __forceinline__ void sts_chunk(uint32_t dsA, uint32_t dsB,
                                          const float4* aR, const float4* bR){
#pragma unroll
    for (int j = 0; j < 4; j++){
        uint32_t h0 = packhf(aR[j].x, aR[j].y), h1 = packhf(aR[j].z, aR[j].w);
        float l0 = aR[j].x - h2f_lo(h0);
        float l1 = aR[j].y - h2f_hi(h0);
        float l2 = aR[j].z - h2f_lo(h1);
        float l3 = aR[j].w - h2f_hi(h1);
        asm volatile("st.shared.v2.b32 [%0], {%1,%2};" :: "r"(dsA + (j << 3)), "r"(h0), "r"(h1) : "memory");
        asm volatile("st.shared.v2.b32 [%0], {%1,%2};" :: "r"(dsA + 10240 + (j << 3)),
                     "r"(packhf(l0, l1)), "r"(packhf(l2, l3)) : "memory");
        asm volatile("st.shared.v2.b32 [%0], {%1,%2};" :: "r"(dsB + (j << 3)),
                     "r"(packhf(bR[j].x, bR[j].y)), "r"(packhf(bR[j].z, bR[j].w)) : "memory");
    }
}

template<int BIASF, int GELUF, int RESF>
__global__ __launch_bounds__(256, 2)
void gemm_mma(const float* __restrict__ A, const float* __restrict__ B,
              const float* __restrict__ bias, const float* __restrict__ res,
              float* __restrict__ C, int M, int N, int K)
{
    extern __shared__ char smem[];
    const uint32_t sb = smem_u32(smem);
    const int tid = threadIdx.x, wid = tid >> 5, lane = tid & 31;
    const int m0 = blockIdx.x << 7, n0 = blockIdx.y << 7;
    const int wm = (wid >> 2) << 6;
    const int wn = (wid & 3) << 5;

    const int lrow = tid >> 1;
    const int j0   = (tid & 1) << 2;
    const float* Ap = A + (size_t)(m0 + lrow) * K + (j0 << 2);
    const float* Bp = B + (size_t)(n0 + lrow) * K + (j0 << 2);
    const uint32_t stsOff = (uint32_t)(lrow * ROWB + (j0 << 3));

    float acc[4][4][4];
#pragma unroll
    for (int i = 0; i < 4; i++)
#pragma unroll
        for (int j = 0; j < 4; j++)
#pragma unroll
            for (int k = 0; k < 4; k++) acc[i][j][k] = 0.f;

    const int NC = K >> 5;
    float4 aR[4], bR[4];

    // prologue: chunk0 -> regs -> stage0; chunk1 -> regs
#pragma unroll
    for (int j = 0; j < 4; j++){
        aR[j] = *(const float4*)(Ap + (j << 2));
        bR[j] = *(const float4*)(Bp + (j << 2));
    }
    sts_chunk(sb + stsOff, sb + stsOff + 20480, aR, bR);
    if (NC > 1){
#pragma unroll
        for (int j = 0; j < 4; j++){
            aR[j] = *(const float4*)(Ap + 32 + (j << 2));
            bR[j] = *(const float4*)(Bp + 32 + (j << 2));
        }
    }
    __syncthreads();

    const int g  = lane >> 3, lr = lane & 7;
    const int arow_off = ((g & 1) << 3) + lr;
    const int akb      = (g >> 1) << 4;
    const int brow_off = ((g >> 1) << 3) + lr;
    const int bkb      = (g & 1) << 4;

    int st_c = 0;
    for (int c = 0; c < NC; c++){
        const uint32_t st = sb + st_c * STAGE_B;
        int st_n = (st_c == 2) ? 0 : st_c + 1;

        // store chunk c+1 (already in regs) into next stage
        if (c + 1 < NC){
            uint32_t d = sb + st_n * STAGE_B + stsOff;
            sts_chunk(d, d + 20480, aR, bR);
        }
        // load chunk c+2 into regs
        if (c + 2 < NC){
#pragma unroll
            for (int j = 0; j < 4; j++){
                aR[j] = *(const float4*)(Ap + (size_t)(c + 2) * 32 + (j << 2));
                bR[j] = *(const float4*)(Bp + (size_t)(c + 2) * 32 + (j << 2));
            }
        }

        // compute on stage st
#pragma unroll
        for (int h = 0; h < 2; h++){
            uint32_t Ah[4][4], Al[4][4], Bh[4][2];
#pragma unroll
            for (int mt = 0; mt < 4; mt++){
                uint32_t ad = st + (uint32_t)((wm + (mt << 4) + arow_off) * ROWB + (h << 5) + akb);
                ldsm4(Ah[mt][0], Ah[mt][1], Ah[mt][2], Ah[mt][3], ad);
                ldsm4(Al[mt][0], Al[mt][1], Al[mt][2], Al[mt][3], ad + 10240);
            }
#pragma unroll
            for (int nt2 = 0; nt2 < 2; nt2++){
                uint32_t bd = st + 20480 + (uint32_t)((wn + (nt2 << 4) + brow_off) * ROWB + (h << 5) + bkb);
                uint32_t r0, r1, r2, r3;
                ldsm4(r0, r1, r2, r3, bd);
                Bh[2*nt2][0] = r0; Bh[2*nt2][1] = r1; Bh[2*nt2+1][0] = r2; Bh[2*nt2+1][1] = r3;
            }
#pragma unroll
            for (int mt = 0; mt < 4; mt++)
#pragma unroll
                for (int nt = 0; nt < 4; nt++){
                    mma16816h(acc[mt][nt], Ah[mt], Bh[nt]);
                    mma16816h(acc[mt][nt], Al[mt], Bh[nt]);
                }
        }
        __syncthreads();
        st_c = st_n;
    }

    const int qr = lane >> 2, qc = lane & 3;
#pragma unroll
    for (int mt = 0; mt < 4; mt++){
#pragma unroll
        for (int p = 0; p < 2; p++){
            int m = m0 + wm + (mt << 4) + qr + (p << 3);
            size_t rowbase = (size_t)m * N;
#pragma unroll
            for (int nt = 0; nt < 4; nt++){
                int n = n0 + wn + (nt << 3) + (qc << 1);
                float v0 = acc[mt][nt][2*p], v1 = acc[mt][nt][2*p + 1];
                if (BIASF){ v0 += bias[n]; v1 += bias[n + 1]; }
                if (GELUF){
                    v0 = 0.5f * v0 * (1.f + erff(v0 * 0.70710678118654752f));
                    v1 = 0.5f * v1 * (1.f + erff(v1 * 0.70710678118654752f));
                }
                if (RESF){
                    float2 rr = *(const float2*)&res[rowbase + n];
                    v0 += rr.x; v1 += rr.y;
                }
                *(float2*)&C[rowbase + n] = make_float2(v0, v1);
            }
        }
    }
}

// ================== tensor-core flash attention ==================
#define AROWB 144
#define KOFF_LO  9216
#define VOFF_HI 18432
#define VOFF_LO 27648
#define ATT_STAGE 36864
#define ATT_SMEM (2*ATT_STAGE)

__global__ __launch_bounds__(256)
void attn_tc(){
    extern __shared__ char smc[];
    const uint32_t sb = smem_u32(smc);
    const int tid = threadIdx.x, wid = tid >> 5, lane = tid & 31;
    const int qb = gridDim.x - 1 - (int)blockIdx.x;
    const int hh = blockIdx.y;
    const int q0 = qb << 7;
    const int wq = q0 + (wid << 4);

    const float SCL = 0.125f * 1.4426950408889634f;
    uint32_t qh[4][4], ql[4][4];
    {
        int r0 = wq + (lane >> 2);
        int c0 = (lane & 3) << 1;
        const float* base = g_qkv + hh * DHH;
#pragma unroll
        for (int kt = 0; kt < 4; kt++){
#pragma unroll
            for (int rr = 0; rr < 2; rr++){
                const float* p = base + (size_t)(r0 + (rr << 3)) * QKV3 + (kt << 4) + c0;
                float2 f0 = *(const float2*)p;
                float2 f1 = *(const float2*)(p + 8);
                float x0 = f0.x*SCL, x1 = f0.y*SCL, x2 = f1.x*SCL, x3 = f1.y*SCL;
                uint32_t h0 = packbf(x0, x1), h1 = packbf(x2, x3);
                qh[kt][rr]     = h0;
                qh[kt][rr + 2] = h1;
                ql[kt][rr]     = packbf(x0 - __uint_as_float(h0 << 16),
                                        x1 - __uint_as_float(h0 & 0xffff0000u));
                ql[kt][rr + 2] = packbf(x2 - __uint_as_float(h1 << 16),
                                        x3 - __uint_as_float(h1 & 0xffff0000u));
            }
        }
    }

    float o[8][4];
#pragma unroll
    for (int i = 0; i < 8; i++){ o[i][0]=0.f; o[i][1]=0.f; o[i][2]=0.f; o[i][3]=0.f; }
    float mr0 = -INFINITY, mr1 = -INFINITY, lr0 = 0.f, lr1 = 0.f;

    const int jmax = (q0 >> 6) + 1;

    const int ldr = tid >> 2;
    const int ldc = (tid & 3) << 4;
    const float* kgp = g_qkv + (size_t)ldr * QKV3 + DD     + hh * DHH + ldc;
    const float* vgp = g_qkv + (size_t)ldr * QKV3 + 2 * DD + hh * DHH + ldc;

    float4 kf[4], vf[4];
#pragma unroll
    for (int t = 0; t < 4; t++){
        kf[t] = *(const float4*)(kgp + (t << 2));
        vf[t] = *(const float4*)(vgp + (t << 2));
    }

    const int g  = lane >> 3, lr8 = lane & 7;
    const int brow_off = ((g >> 1) << 3) + lr8;
    const int bkb      = (g & 1) << 4;
    const uint32_t sts_base = (uint32_t)(ldr * AROWB + (ldc << 1));

    for (int j = 0; j <= jmax; j++){
        const uint32_t st = sb + (j & 1) * ATT_STAGE;
        {
            *(uint4*)(smc + (st - sb) + sts_base) =
                make_uint4(packbf(kf[0].x,kf[0].y), packbf(kf[0].z,kf[0].w),
                           packbf(kf[1].x,kf[1].y), packbf(kf[1].z,kf[1].w));
            *(uint4*)(smc + (st - sb) + sts_base + 16) =
                make_uint4(packbf(kf[2].x,kf[2].y), packbf(kf[2].z,kf[2].w),
                           packbf(kf[3].x,kf[3].y), packbf(kf[3].z,kf[3].w));
            uint32_t kl0[4], l[4];
#pragma unroll
            for (int t = 0; t < 4; t++){
                uint32_t hh0 = packbf(kf[t].x, kf[t].y), hh1 = packbf(kf[t].z, kf[t].w);
                kl0[t] = packbf(kf[t].x - __uint_as_float(hh0 << 16),
                                kf[t].y - __uint_as_float(hh0 & 0xffff0000u));
                l[t]   = packbf(kf[t].z - __uint_as_float(hh1 << 16),
                                kf[t].w - __uint_as_float(hh1 & 0xffff0000u));
            }
            *(uint4*)(smc + (st - sb) + KOFF_LO + sts_base)      = make_uint4(kl0[0], l[0], kl0[1], l[1]);
            *(uint4*)(smc + (st - sb) + KOFF_LO + sts_base + 16) = make_uint4(kl0[2], l[2], kl0[3], l[3]);
            *(uint4*)(smc + (st - sb) + VOFF_HI + sts_base) =
                make_uint4(packbf(vf[0].x,vf[0].y), packbf(vf[0].z,vf[0].w),
                           packbf(vf[1].x,vf[1].y), packbf(vf[1].z,vf[1].w));
            *(uint4*)(smc + (st - sb) + VOFF_HI + sts_base + 16) =
                make_uint4(packbf(vf[2].x,vf[2].y), packbf(vf[2].z,vf[2].w),
                           packbf(vf[3].x,vf[3].y), packbf(vf[3].z,vf[3].w));
            uint32_t vl0[4], vl1[4];
#pragma unroll
            for (int t = 0; t < 4; t++){
                uint32_t hh0 = packbf(vf[t].x, vf[t].y), hh1 = packbf(vf[t].z, vf[t].w);
                vl0[t] = packbf(vf[t].x - __uint_as_float(hh0 << 16),
                                vf[t].y - __uint_as_float(hh0 & 0xffff0000u));
                vl1[t] = packbf(vf[t].z - __uint_as_float(hh1 << 16),
                                vf[t].w - __uint_as_float(hh1 & 0xffff0000u));
            }
            *(uint4*)(smc + (st - sb) + VOFF_LO + sts_base)      = make_uint4(vl0[0], vl1[0], vl0[1], vl1[1]);
            *(uint4*)(smc + (st - sb) + VOFF_LO + sts_base + 16) = make_uint4(vl0[2], vl1[2], vl0[3], vl1[3]);
        }
        __syncthreads();

        if (j < jmax){
            const float* kp2 = kgp + (size_t)((j + 1) << 6) * QKV3;
            const float* vp2 = vgp + (size_t)((j + 1) << 6) * QKV3;
#pragma unroll
            for (int t = 0; t < 4; t++){
                kf[t] = *(const float4*)(kp2 + (t << 2));
                vf[t] = *(const float4*)(vp2 + (t << 2));
            }
        }

        if ((j << 6) <= wq + 15){
            float s[8][4];
#pragma unroll
            for (int i = 0; i < 8; i++){ s[i][0]=0.f; s[i][1]=0.f; s[i][2]=0.f; s[i][3]=0.f; }
#pragma unroll
            for (int ks = 0; ks < 4; ks++){
                uint32_t kh[8][2], kl[8][2];
#pragma unroll
                for (int nt2 = 0; nt2 < 4; nt2++){
                    uint32_t ad = st + (uint32_t)(((nt2 << 4) + brow_off) * AROWB + (ks << 5) + bkb);
                    uint32_t r0, r1, r2, r3;
                    ldsm4(r0, r1, r2, r3, ad);
                    kh[2*nt2][0]=r0; kh[2*nt2][1]=r1; kh[2*nt2+1][0]=r2; kh[2*nt2+1][1]=r3;
                    ldsm4(r0, r1, r2, r3, ad + KOFF_LO);
                    kl[2*nt2][0]=r0; kl[2*nt2][1]=r1; kl[2*nt2+1][0]=r2; kl[2*nt2+1][1]=r3;
                }
#pragma unroll
                for (int nt = 0; nt < 8; nt++){
                    mma16816(s[nt], qh[ks], kh[nt]);
                    mma16816(s[nt], qh[ks], kl[nt]);
                    mma16816(s[nt], ql[ks], kh[nt]);
                }
            }
            if ((j << 6) + 63 > wq){
                int qr0 = wq + (lane >> 2);
#pragma unroll
                for (int nt = 0; nt < 8; nt++){
                    int kp = (j << 6) + (nt << 3) + ((lane & 3) << 1);
#pragma unroll
                    for (int e = 0; e < 4; e++){
                        int kpos = kp + (e & 1);
                        int qrow = qr0 + ((e >> 1) << 3);
                        if (kpos > qrow) s[nt][e] = -INFINITY;
                    }
                }
            }
            float mx0 = -INFINITY, mx1 = -INFINITY;
#pragma unroll
            for (int nt = 0; nt < 8; nt++){
                mx0 = fmaxf(mx0, fmaxf(s[nt][0], s[nt][1]));
                mx1 = fmaxf(mx1, fmaxf(s[nt][2], s[nt][3]));
            }
            mx0 = fmaxf(mx0, __shfl_xor_sync(0xffffffffu, mx0, 1));
            mx0 = fmaxf(mx0, __shfl_xor_sync(0xffffffffu, mx0, 2));
            mx1 = fmaxf(mx1, __shfl_xor_sync(0xffffffffu, mx1, 1));
            mx1 = fmaxf(mx1, __shfl_xor_sync(0xffffffffu, mx1, 2));
            float mn0 = fmaxf(mr0, mx0), mn1 = fmaxf(mr1, mx1);
            float a0 = ex2f(mr0 - mn0), a1 = ex2f(mr1 - mn1);
            mr0 = mn0; mr1 = mn1;
            lr0 *= a0; lr1 *= a1;
#pragma unroll
            for (int nt = 0; nt < 8; nt++){
                o[nt][0] *= a0; o[nt][1] *= a0; o[nt][2] *= a1; o[nt][3] *= a1;
            }
            float sum0 = 0.f, sum1 = 0.f;
#pragma unroll
            for (int nt = 0; nt < 8; nt++){
                s[nt][0] = ex2f(s[nt][0] - mn0);
                s[nt][1] = ex2f(s[nt][1] - mn0);
                s[nt][2] = ex2f(s[nt][2] - mn1);
                s[nt][3] = ex2f(s[nt][3] - mn1);
                sum0 += s[nt][0] + s[nt][1];
                sum1 += s[nt][2] + s[nt][3];
            }
            lr0 += sum0; lr1 += sum1;
#pragma unroll
            for (int kt = 0; kt < 4; kt++){
                uint32_t ph[4], pl[4];
                {
                    float p00 = s[2*kt][0],   p01 = s[2*kt][1];
                    float p10 = s[2*kt][2],   p11 = s[2*kt][3];
                    float p20 = s[2*kt+1][0], p21 = s[2*kt+1][1];
                    float p30 = s[2*kt+1][2], p31 = s[2*kt+1][3];
                    ph[0] = packbf(p00, p01); ph[1] = packbf(p10, p11);
                    ph[2] = packbf(p20, p21); ph[3] = packbf(p30, p31);
                    pl[0] = packbf(p00 - __uint_as_float(ph[0] << 16),
                                   p01 - __uint_as_float(ph[0] & 0xffff0000u));
                    pl[1] = packbf(p10 - __uint_as_float(ph[1] << 16),
                                   p11 - __uint_as_float(ph[1] & 0xffff0000u));
                    pl[2] = packbf(p20 - __uint_as_float(ph[2] << 16),
                                   p21 - __uint_as_float(ph[2] & 0xffff0000u));
                    pl[3] = packbf(p30 - __uint_as_float(ph[3] << 16),
                                   p31 - __uint_as_float(ph[3] & 0xffff0000u));
                }
#pragma unroll
                for (int nt2 = 0; nt2 < 4; nt2++){
                    uint32_t va = st + VOFF_HI +
                        (uint32_t)(((kt << 4) + (lane & 15)) * AROWB + (((nt2 << 4) + ((lane >> 4) << 3)) << 1));
                    uint32_t r0, r1, r2, r3;
                    ldsm4t(r0, r1, r2, r3, va);
                    uint32_t bh0[2] = {r0, r1}, bh1[2] = {r2, r3};
                    ldsm4t(r0, r1, r2, r3, va + (VOFF_LO - VOFF_HI));
                    uint32_t bl0[2] = {r0, r1}, bl1[2] = {r2, r3};
                    mma16816(o[2*nt2],   ph, bh0);
                    mma16816(o[2*nt2],   pl, bh0);
                    mma16816(o[2*nt2],   ph, bl0);
                    mma16816(o[2*nt2+1], ph, bh1);
                    mma16816(o[2*nt2+1], pl, bh1);
                    mma16816(o[2*nt2+1], ph, bl1);
                }
            }
        }
        __syncthreads();
    }

    lr0 += __shfl_xor_sync(0xffffffffu, lr0, 1);
    lr0 += __shfl_xor_sync(0xffffffffu, lr0, 2);
    lr1 += __shfl_xor_sync(0xffffffffu, lr1, 1);
    lr1 += __shfl_xor_sync(0xffffffffu, lr1, 2);
    float inv0 = 1.f / lr0, inv1 = 1.f / lr1;
    int qrow = wq + (lane >> 2);
    int cc = hh * DHH + ((lane & 3) << 1);
#pragma unroll
    for (int nt = 0; nt < 8; nt++){
        *(float2*)&g_ctx[(size_t)qrow * DD + cc + (nt << 3)] =
            make_float2(o[nt][0] * inv0, o[nt][1] * inv0);
        *(float2*)&g_ctx[(size_t)(qrow + 8) * DD + cc + (nt << 3)] =
            make_float2(o[nt][2] * inv1, o[nt][3] * inv1);
    }
}

// ---------------- loss ----------------
__global__ void row_lse_kernel(const float* __restrict__ logits, const int* __restrict__ tgt){
    int t = blockIdx.x;
    const float* row = logits + (size_t)t * VV;
    float mx = -INFINITY;
    for (int i = threadIdx.x; i < VV; i += blockDim.x) mx = fmaxf(mx, row[i]);
    mx = blockMax(mx);
    float s = 0.f;
    for (int i = threadIdx.x; i < VV; i += blockDim.x) s += expf(row[i] - mx);
    s = blockSum(s);
    if (threadIdx.x == 0){
        int tg = tgt[t];
        float lse = mx + logf(s);
        float nll = lse - row[tg];
        g_nll[t] = (tg != 0) ? nll : 0.f;
        g_val[t] = (tg != 0) ? 1.f : 0.f;
    }
}

__global__ void loss_reduce_kernel(float* __restrict__ out_loss){
    float a = 0.f, b = 0.f;
    for (int t = threadIdx.x; t < TT; t += blockDim.x){ a += g_nll[t]; b += g_val[t]; }
    a = blockSum(a);
    b = blockSum(b);
    if (threadIdx.x == 0) *out_loss = a / fmaxf(b, 1.f);
}

// ---------------- launch ----------------
extern "C" void kernel_launch(void* const* d_in, const int* in_sizes, int n_in,
                              void* d_out, int out_size){
    (void)in_sizes; (void)n_in;
    const int*   x     = (const int*)  d_in[0];
    const int*   tgt   = (const int*)  d_in[1];
    const float* tok   = (const float*)d_in[2];
    const float* pos   = (const float*)d_in[3];
    const float* Wqkv  = (const float*)d_in[4];
    const float* Wo    = (const float*)d_in[5];
    const float* ln1g  = (const float*)d_in[6];
    const float* ln1b  = (const float*)d_in[7];
    const float* ln2g  = (const float*)d_in[8];
    const float* ln2b  = (const float*)d_in[9];
    const float* W1    = (const float*)d_in[10];
    const float* b1    = (const float*)d_in[11];
    const float* W2    = (const float*)d_in[12];
    const float* b2    = (const float*)d_in[13];
    const float* lnfg  = (const float*)d_in[14];
    const float* lnfb  = (const float*)d_in[15];
    float* out = (float*)d_out;

    float *ph, *phn, *pqkv, *pctx, *pff;
    cudaGetSymbolAddress((void**)&ph,   g_h);
    cudaGetSymbolAddress((void**)&phn,  g_hn);
    cudaGetSymbolAddress((void**)&pqkv, g_qkv);
    cudaGetSymbolAddress((void**)&pctx, g_ctx);
    cudaGetSymbolAddress((void**)&pff,  g_ff);

    cudaFuncSetAttribute(gemm_mma<0,0,0>, cudaFuncAttributeMaxDynamicSharedMemorySize, G_SMEM);
    cudaFuncSetAttribute(gemm_mma<0,0,1>, cudaFuncAttributeMaxDynamicSharedMemorySize, G_SMEM);
    cudaFuncSetAttribute(gemm_mma<1,1,0>, cudaFuncAttributeMaxDynamicSharedMemorySize, G_SMEM);
    cudaFuncSetAttribute(gemm_mma<1,0,1>, cudaFuncAttributeMaxDynamicSharedMemorySize, G_SMEM);
    cudaFuncSetAttribute(attn_tc, cudaFuncAttributeMaxDynamicSharedMemorySize, ATT_SMEM);

    embed_kernel<<<TT, 256>>>(x, tok, pos);

    for (int l = 0; l < LL; l++){
        ln_kernel<<<TT, 256>>>(ph, phn, ln1g + l*DD, ln1b + l*DD);
        gemm_mma<0,0,0><<<dim3(TT/128, QKV3/128), 256, G_SMEM>>>(
            phn, Wqkv + (size_t)l*QKV3*DD, nullptr, nullptr, pqkv, TT, QKV3, DD);
        attn_tc<<<dim3(TT/128, HH), 256, ATT_SMEM>>>();
        gemm_mma<0,0,1><<<dim3(TT/128, DD/128), 256, G_SMEM>>>(
            pctx, Wo + (size_t)l*DD*DD, nullptr, ph, ph, TT, DD, DD);
        ln_kernel<<<TT, 256>>>(ph, phn, ln2g + l*DD, ln2b + l*DD);
        gemm_mma<1,1,0><<<dim3(TT/128, FFD/128), 256, G_SMEM>>>(
            phn, W1 + (size_t)l*FFD*DD, b1 + (size_t)l*FFD, nullptr, pff, TT, FFD, DD);
        gemm_mma<1,0,1><<<dim3(TT/128, DD/128), 256, G_SMEM>>>(
            pff, W2 + (size_t)l*DD*FFD, b2 + (size_t)l*DD, ph, ph, TT, DD, FFD);
    }

    ln_kernel<<<TT, 256>>>(ph, phn, lnfg, lnfb);
    gemm_mma<0,0,0><<<dim3(TT/128, VV/128), 256, G_SMEM>>>(
        phn, tok, nullptr, nullptr, out, TT, VV, DD);

    row_lse_kernel<<<TT, 256>>>(out, tgt);
    if (out_size > TT * VV)
        loss_reduce_kernel<<<1, 256>>>(out + (size_t)TT * VV);
}

// round 10
// speedup vs baseline: 1.1665x; 1.1665x over previous
#include <cuda_runtime.h>
#include <cuda_bf16.h>
#include <cuda_fp16.h>
#include <math.h>
#include <stdint.h>

// Problem constants
#define TT   2048
#define DD   768
#define HH   12
#define DHH  64
#define LL   6
#define FFD  3072
#define VV   32000
#define QKV3 (3*DD)

// ---------------- scratch ----------------
__device__ float  g_h  [TT*DD];
__device__ float  g_qkv[TT*QKV3];
__device__ float  g_nll[TT];
__device__ float  g_val[TT];
__device__ __half g_hn_hi [TT*DD];
__device__ __half g_hn_lo [TT*DD];
__device__ __half g_ctx_hi[TT*DD];
__device__ __half g_ctx_lo[TT*DD];
__device__ __half g_ff_hi [TT*FFD];
__device__ __half g_ff_lo [TT*FFD];
// fp16 weights (converted once per launch)
__device__ __half w_qkv_h[LL*QKV3*DD];
__device__ __half w_o_h  [LL*DD*DD];
__device__ __half w_1_h  [LL*FFD*DD];
__device__ __half w_2_h  [LL*DD*FFD];
__device__ __half w_tok_h[(size_t)VV*DD];

// ---------------- helpers ----------------
__device__ __forceinline__ uint32_t smem_u32(const void* p){
    uint32_t a;
    asm("{ .reg .u64 t; cvta.to.shared.u64 t, %1; cvt.u32.u64 %0, t; }" : "=r"(a) : "l"(p));
    return a;
}
__device__ __forceinline__ uint32_t packbf(float x0, float x1){
    uint32_t r;
    asm("cvt.rn.bf16x2.f32 %0, %1, %2;" : "=r"(r) : "f"(x1), "f"(x0));
    return r;
}
__device__ __forceinline__ uint32_t packhf(float x0, float x1){
    uint32_t r;
    asm("cvt.rn.f16x2.f32 %0, %1, %2;" : "=r"(r) : "f"(x1), "f"(x0));
    return r;
}
__device__ __forceinline__ float h2f_lo(uint32_t p){
    float f; asm("{ .reg .b16 h, dummy; mov.b32 {h, dummy}, %1; cvt.f32.f16 %0, h; }" : "=f"(f) : "r"(p));
    return f;
}
__device__ __forceinline__ float h2f_hi(uint32_t p){
    float f; asm("{ .reg .b16 h, dummy; mov.b32 {dummy, h}, %1; cvt.f32.f16 %0, h; }" : "=f"(f) : "r"(p));
    return f;
}
__device__ __forceinline__ float ex2f(float x){
    float y; asm("ex2.approx.f32 %0, %1;" : "=f"(y) : "f"(x)); return y;
}
__device__ __forceinline__ void ldsm4(uint32_t &r0, uint32_t &r1, uint32_t &r2, uint32_t &r3,
                                      uint32_t addr){
    asm volatile("ldmatrix.sync.aligned.m8n8.x4.shared.b16 {%0,%1,%2,%3}, [%4];"
        : "=r"(r0), "=r"(r1), "=r"(r2), "=r"(r3) : "r"(addr));
}
__device__ __forceinline__ void ldsm4t(uint32_t &r0, uint32_t &r1, uint32_t &r2, uint32_t &r3,
                                       uint32_t addr){
    asm volatile("ldmatrix.sync.aligned.m8n8.x4.trans.shared.b16 {%0,%1,%2,%3}, [%4];"
        : "=r"(r0), "=r"(r1), "=r"(r2), "=r"(r3) : "r"(addr));
}
__device__ __forceinline__ void mma16816(float* d, const uint32_t* a, const uint32_t* b){
    asm volatile("mma.sync.aligned.m16n8k16.row.col.f32.bf16.bf16.f32 "
        "{%0,%1,%2,%3}, {%4,%5,%6,%7}, {%8,%9}, {%0,%1,%2,%3};"
        : "+f"(d[0]), "+f"(d[1]), "+f"(d[2]), "+f"(d[3])
        : "r"(a[0]), "r"(a[1]), "r"(a[2]), "r"(a[3]), "r"(b[0]), "r"(b[1]));
}
__device__ __forceinline__ void mma16816h(float* d, const uint32_t* a, const uint32_t* b){
    asm volatile("mma.sync.aligned.m16n8k16.row.col.f32.f16.f16.f32 "
        "{%0,%1,%2,%3}, {%4,%5,%6,%7}, {%8,%9}, {%0,%1,%2,%3};"
        : "+f"(d[0]), "+f"(d[1]), "+f"(d[2]), "+f"(d[3])
        : "r"(a[0]), "r"(a[1]), "r"(a[2]), "r"(a[3]), "r"(b[0]), "r"(b[1]));
}
#define CP_ASYNC16(dst, src) \
    asm volatile("cp.async.cg.shared.global [%0], [%1], 16;" :: "r"(dst), "l"(src) : "memory")
#define CP_COMMIT() asm volatile("cp.async.commit_group;" ::: "memory")
#define CP_WAIT1()  asm volatile("cp.async.wait_group 1;" ::: "memory")

// ---------------- reductions ----------------
__device__ __forceinline__ float warpSum(float v){
#pragma unroll
    for (int o = 16; o; o >>= 1) v += __shfl_xor_sync(0xffffffffu, v, o);
    return v;
}
__device__ __forceinline__ float warpMax(float v){
#pragma unroll
    for (int o = 16; o; o >>= 1) v = fmaxf(v, __shfl_xor_sync(0xffffffffu, v, o));
    return v;
}
__device__ float blockSum(float v){
    __shared__ float s[9];
    __syncthreads();
    int lane = threadIdx.x & 31, w = threadIdx.x >> 5;
    v = warpSum(v);
    if (lane == 0) s[w] = v;
    __syncthreads();
    if (w == 0){
        float x = (lane < (int)(blockDim.x >> 5)) ? s[lane] : 0.f;
        x = warpSum(x);
        if (lane == 0) s[8] = x;
    }
    __syncthreads();
    return s[8];
}
__device__ float blockMax(float v){
    __shared__ float s[9];
    __syncthreads();
    int lane = threadIdx.x & 31, w = threadIdx.x >> 5;
    v = warpMax(v);
    if (lane == 0) s[w] = v;
    __syncthreads();
    if (w == 0){
        float x = (lane < (int)(blockDim.x >> 5)) ? s[lane] : -INFINITY;
        x = warpMax(x);
        if (lane == 0) s[8] = x;
    }
    __syncthreads();
    return s[8];
}

// ---------------- fp32 -> fp16 weight conversion ----------------
__global__ void cvt_kernel(const float* __restrict__ src, __half* __restrict__ dst, int n){
    int i = (blockIdx.x * blockDim.x + threadIdx.x) << 2;
    int stride = (gridDim.x * blockDim.x) << 2;
    for (; i < n; i += stride){
        float4 f = *(const float4*)(src + i);
        *(uint2*)&dst[i] = make_uint2(packhf(f.x, f.y), packhf(f.z, f.w));
    }
}

// ---------------- embedding ----------------
__global__ void embed_kernel(const int* __restrict__ x,
                             const float* __restrict__ tok,
                             const float* __restrict__ pos){
    int t  = blockIdx.x;
    int id = x[t];
    const float* tr = tok + (size_t)id * DD;
    const float* pr = pos + (size_t)t  * DD;
    for (int d = threadIdx.x; d < DD; d += blockDim.x)
        g_h[t*DD + d] = tr[d] + pr[d];
}

// ---------------- layernorm -> fp16 hi/lo ----------------
__global__ void ln_kernel_hl(const float* __restrict__ in,
                             __half* __restrict__ ohi, __half* __restrict__ olo,
                             const float* __restrict__ g, const float* __restrict__ b){
    __shared__ float row[DD];
    int t = blockIdx.x;
    const float* r = in + (size_t)t * DD;
    float s = 0.f;
    for (int d = threadIdx.x; d < DD; d += blockDim.x){ float v = r[d]; row[d] = v; s += v; }
    s = blockSum(s);
    float mean = s * (1.f / DD);
    float q = 0.f;
    for (int d = threadIdx.x; d < DD; d += blockDim.x){ float v = row[d] - mean; q += v*v; }
    q = blockSum(q);
    float rstd = rsqrtf(q * (1.f / DD) + 1e-5f);
    for (int d = threadIdx.x; d < (DD >> 1); d += blockDim.x){
        int i0 = d << 1;
        float v0 = (row[i0]     - mean) * rstd * g[i0]     + b[i0];
        float v1 = (row[i0 + 1] - mean) * rstd * g[i0 + 1] + b[i0 + 1];
        uint32_t hh = packhf(v0, v1);
        uint32_t ll = packhf(v0 - h2f_lo(hh), v1 - h2f_hi(hh));
        *(uint32_t*)&ohi[t*DD + i0] = hh;
        *(uint32_t*)&olo[t*DD + i0] = ll;
    }
}

// ================== fp16 2-product GEMM, cp.async 3-stage, 2 CTAs/SM ==========
// C[M,N] = A[M,K] @ B[N,K]^T (+bias)(+gelu)(+res), A = fp16 hi+lo, B = fp16.
// 128x128 CTA tile, BK=32, 8 warps (2x4), warp tile 64x32.
// stage: Ahi[10240] Alo[10240] B[10240] = 30720 B; 3 stages = 92160 B.
#define ROWB 80
#define STAGE_B 30720
#define G_SMEM (3*STAGE_B)

template<int BIASF, int GELUF, int RESF, int OUTHL>
__global__ __launch_bounds__(256, 2)
void gemm_mma(const __half* __restrict__ Ahi, const __half* __restrict__ Alo,
              const __half* __restrict__ Bw,
              const float* __restrict__ bias, const float* __restrict__ res,
              float* __restrict__ C, __half* __restrict__ Chi, __half* __restrict__ Clo,
              int M, int N, int K)
{
    extern __shared__ char smem[];
    const uint32_t sb = smem_u32(smem);
    const int tid = threadIdx.x, wid = tid >> 5, lane = tid & 31;
    const int m0 = blockIdx.x << 7, n0 = blockIdx.y << 7;
    const int wm = (wid >> 2) << 6;
    const int wn = (wid & 3) << 5;

    // cp.async loader mapping: row = tid>>2 (0..63, +64 variant), 16B chunk = tid&3
    const int lrow = tid >> 2;
    const int k16  = tid & 3;
    const __half* aHp = Ahi + (size_t)(m0 + lrow) * K + (k16 << 3);
    const __half* aLp = Alo + (size_t)(m0 + lrow) * K + (k16 << 3);
    const __half* bP  = Bw  + (size_t)(n0 + lrow) * K + (k16 << 3);
    const uint32_t dOff = (uint32_t)(lrow * ROWB + (k16 << 4));

    float acc[4][4][4];
#pragma unroll
    for (int i = 0; i < 4; i++)
#pragma unroll
        for (int j = 0; j < 4; j++)
#pragma unroll
            for (int k = 0; k < 4; k++) acc[i][j][k] = 0.f;

    const int NC = K >> 5;

    // issue one chunk into one stage
    auto issue = [&](int c, int s){
        uint32_t d = sb + s * STAGE_B + dOff;
        const __half* a0 = aHp + (size_t)c * 32;
        const __half* a1 = aLp + (size_t)c * 32;
        const __half* b0 = bP  + (size_t)c * 32;
        CP_ASYNC16(d,                a0);
        CP_ASYNC16(d + 5120,         a0 + (size_t)64 * K);
        CP_ASYNC16(d + 10240,        a1);
        CP_ASYNC16(d + 10240 + 5120, a1 + (size_t)64 * K);
        CP_ASYNC16(d + 20480,        b0);
        CP_ASYNC16(d + 20480 + 5120, b0 + (size_t)64 * K);
    };

    issue(0, 0); CP_COMMIT();
    if (NC > 1){ issue(1, 1); CP_COMMIT(); }

    const int g  = lane >> 3, lr = lane & 7;
    const int arow_off = ((g & 1) << 3) + lr;
    const int akb      = (g >> 1) << 4;
    const int brow_off = ((g >> 1) << 3) + lr;
    const int bkb      = (g & 1) << 4;

    int st_c = 0;
    for (int c = 0; c < NC; c++){
        CP_WAIT1();
        __syncthreads();

        int st_n2 = st_c + 2; if (st_n2 >= 3) st_n2 -= 3;
        if (c + 2 < NC) issue(c + 2, st_n2);
        CP_COMMIT();

        const uint32_t st = sb + st_c * STAGE_B;
#pragma unroll
        for (int h = 0; h < 2; h++){
            uint32_t Bh[4][2];
#pragma unroll
            for (int nt2 = 0; nt2 < 2; nt2++){
                uint32_t bd = st + 20480 + (uint32_t)((wn + (nt2 << 4) + brow_off) * ROWB + (h << 5) + bkb);
                uint32_t r0, r1, r2, r3;
                ldsm4(r0, r1, r2, r3, bd);
                Bh[2*nt2][0] = r0; Bh[2*nt2][1] = r1; Bh[2*nt2+1][0] = r2; Bh[2*nt2+1][1] = r3;
            }
#pragma unroll
            for (int mt = 0; mt < 4; mt++){
                uint32_t Ah[4], Al[4];
                uint32_t ad = st + (uint32_t)((wm + (mt << 4) + arow_off) * ROWB + (h << 5) + akb);
                ldsm4(Ah[0], Ah[1], Ah[2], Ah[3], ad);
                ldsm4(Al[0], Al[1], Al[2], Al[3], ad + 10240);
#pragma unroll
                for (int nt = 0; nt < 4; nt++){
                    mma16816h(acc[mt][nt], Ah, Bh[nt]);
                    mma16816h(acc[mt][nt], Al, Bh[nt]);
                }
            }
        }
        st_c = st_c + 1; if (st_c >= 3) st_c = 0;
    }

    const int qr = lane >> 2, qc = lane & 3;
#pragma unroll
    for (int mt = 0; mt < 4; mt++){
#pragma unroll
        for (int p = 0; p < 2; p++){
            int m = m0 + wm + (mt << 4) + qr + (p << 3);
            size_t rowbase = (size_t)m * N;
#pragma unroll
            for (int nt = 0; nt < 4; nt++){
                int n = n0 + wn + (nt << 3) + (qc << 1);
                float v0 = acc[mt][nt][2*p], v1 = acc[mt][nt][2*p + 1];
                if (BIASF){ v0 += bias[n]; v1 += bias[n + 1]; }
                if (GELUF){
                    v0 = 0.5f * v0 * (1.f + erff(v0 * 0.70710678118654752f));
                    v1 = 0.5f * v1 * (1.f + erff(v1 * 0.70710678118654752f));
                }
                if (RESF){
                    float2 rr = *(const float2*)&res[rowbase + n];
                    v0 += rr.x; v1 += rr.y;
                }
                if (OUTHL){
                    uint32_t hh = packhf(v0, v1);
                    uint32_t ll = packhf(v0 - h2f_lo(hh), v1 - h2f_hi(hh));
                    *(uint32_t*)&Chi[rowbase + n] = hh;
                    *(uint32_t*)&Clo[rowbase + n] = ll;
                } else {
                    *(float2*)&C[rowbase + n] = make_float2(v0, v1);
                }
            }
        }
    }
}

// ================== tensor-core flash attention (epilogue -> fp16 hi/lo) ==========
#define AROWB 144
#define KOFF_LO  9216
#define VOFF_HI 18432
#define VOFF_LO 27648
#define ATT_STAGE 36864
#define ATT_SMEM (2*ATT_STAGE)

__global__ __launch_bounds__(256)
void attn_tc(){
    extern __shared__ char smc[];
    const uint32_t sb = smem_u32(smc);
    const int tid = threadIdx.x, wid = tid >> 5, lane = tid & 31;
    const int qb = gridDim.x - 1 - (int)blockIdx.x;
    const int hh = blockIdx.y;
    const int q0 = qb << 7;
    const int wq = q0 + (wid << 4);

    const float SCL = 0.125f * 1.4426950408889634f;
    uint32_t qh[4][4], ql[4][4];
    {
        int r0 = wq + (lane >> 2);
        int c0 = (lane & 3) << 1;
        const float* base = g_qkv + hh * DHH;
#pragma unroll
        for (int kt = 0; kt < 4; kt++){
#pragma unroll
            for (int rr = 0; rr < 2; rr++){
                const float* p = base + (size_t)(r0 + (rr << 3)) * QKV3 + (kt << 4) + c0;
                float2 f0 = *(const float2*)p;
                float2 f1 = *(const float2*)(p + 8);
                float x0 = f0.x*SCL, x1 = f0.y*SCL, x2 = f1.x*SCL, x3 = f1.y*SCL;
                uint32_t h0 = packbf(x0, x1), h1 = packbf(x2, x3);
                qh[kt][rr]     = h0;
                qh[kt][rr + 2] = h1;
                ql[kt][rr]     = packbf(x0 - __uint_as_float(h0 << 16),
                                        x1 - __uint_as_float(h0 & 0xffff0000u));
                ql[kt][rr + 2] = packbf(x2 - __uint_as_float(h1 << 16),
                                        x3 - __uint_as_float(h1 & 0xffff0000u));
            }
        }
    }

    float o[8][4];
#pragma unroll
    for (int i = 0; i < 8; i++){ o[i][0]=0.f; o[i][1]=0.f; o[i][2]=0.f; o[i][3]=0.f; }
    float mr0 = -INFINITY, mr1 = -INFINITY, lr0 = 0.f, lr1 = 0.f;

    const int jmax = (q0 >> 6) + 1;

    const int ldr = tid >> 2;
    const int ldc = (tid & 3) << 4;
    const float* kgp = g_qkv + (size_t)ldr * QKV3 + DD     + hh * DHH + ldc;
    const float* vgp = g_qkv + (size_t)ldr * QKV3 + 2 * DD + hh * DHH + ldc;

    float4 kf[4], vf[4];
#pragma unroll
    for (int t = 0; t < 4; t++){
        kf[t] = *(const float4*)(kgp + (t << 2));
        vf[t] = *(const float4*)(vgp + (t << 2));
    }

    const int g  = lane >> 3, lr8 = lane & 7;
    const int brow_off = ((g >> 1) << 3) + lr8;
    const int bkb      = (g & 1) << 4;
    const uint32_t sts_base = (uint32_t)(ldr * AROWB + (ldc << 1));

    for (int j = 0; j <= jmax; j++){
        const uint32_t st = sb + (j & 1) * ATT_STAGE;
        {
            *(uint4*)(smc + (st - sb) + sts_base) =
                make_uint4(packbf(kf[0].x,kf[0].y), packbf(kf[0].z,kf[0].w),
                           packbf(kf[1].x,kf[1].y), packbf(kf[1].z,kf[1].w));
            *(uint4*)(smc + (st - sb) + sts_base + 16) =
                make_uint4(packbf(kf[2].x,kf[2].y), packbf(kf[2].z,kf[2].w),
                           packbf(kf[3].x,kf[3].y), packbf(kf[3].z,kf[3].w));
            uint32_t kl0[4], l[4];
#pragma unroll
            for (int t = 0; t < 4; t++){
                uint32_t hh0 = packbf(kf[t].x, kf[t].y), hh1 = packbf(kf[t].z, kf[t].w);
                kl0[t] = packbf(kf[t].x - __uint_as_float(hh0 << 16),
                                kf[t].y - __uint_as_float(hh0 & 0xffff0000u));
                l[t]   = packbf(kf[t].z - __uint_as_float(hh1 << 16),
                                kf[t].w - __uint_as_float(hh1 & 0xffff0000u));
            }
            *(uint4*)(smc + (st - sb) + KOFF_LO + sts_base)      = make_uint4(kl0[0], l[0], kl0[1], l[1]);
            *(uint4*)(smc + (st - sb) + KOFF_LO + sts_base + 16) = make_uint4(kl0[2], l[2], kl0[3], l[3]);
            *(uint4*)(smc + (st - sb) + VOFF_HI + sts_base) =
                make_uint4(packbf(vf[0].x,vf[0].y), packbf(vf[0].z,vf[0].w),
                           packbf(vf[1].x,vf[1].y), packbf(vf[1].z,vf[1].w));
            *(uint4*)(smc + (st - sb) + VOFF_HI + sts_base + 16) =
                make_uint4(packbf(vf[2].x,vf[2].y), packbf(vf[2].z,vf[2].w),
                           packbf(vf[3].x,vf[3].y), packbf(vf[3].z,vf[3].w));
            uint32_t vl0[4], vl1[4];
#pragma unroll
            for (int t = 0; t < 4; t++){
                uint32_t hh0 = packbf(vf[t].x, vf[t].y), hh1 = packbf(vf[t].z, vf[t].w);
                vl0[t] = packbf(vf[t].x - __uint_as_float(hh0 << 16),
                                vf[t].y - __uint_as_float(hh0 & 0xffff0000u));
                vl1[t] = packbf(vf[t].z - __uint_as_float(hh1 << 16),
                                vf[t].w - __uint_as_float(hh1 & 0xffff0000u));
            }
            *(uint4*)(smc + (st - sb) + VOFF_LO + sts_base)      = make_uint4(vl0[0], vl1[0], vl0[1], vl1[1]);
            *(uint4*)(smc + (st - sb) + VOFF_LO + sts_base + 16) = make_uint4(vl0[2], vl1[2], vl0[3], vl1[3]);
        }
        __syncthreads();

        if (j < jmax){
            const float* kp2 = kgp + (size_t)((j + 1) << 6) * QKV3;
            const float* vp2 = vgp + (size_t)((j + 1) << 6) * QKV3;
#pragma unroll
            for (int t = 0; t < 4; t++){
                kf[t] = *(const float4*)(kp2 + (t << 2));
                vf[t] = *(const float4*)(vp2 + (t << 2));
            }
        }

        if ((j << 6) <= wq + 15){
            float s[8][4];
#pragma unroll
            for (int i = 0; i < 8; i++){ s[i][0]=0.f; s[i][1]=0.f; s[i][2]=0.f; s[i][3]=0.f; }
#pragma unroll
            for (int ks = 0; ks < 4; ks++){
                uint32_t kh[8][2], kl[8][2];
#pragma unroll
                for (int nt2 = 0; nt2 < 4; nt2++){
                    uint32_t ad = st + (uint32_t)(((nt2 << 4) + brow_off) * AROWB + (ks << 5) + bkb);
                    uint32_t r0, r1, r2, r3;
                    ldsm4(r0, r1, r2, r3, ad);
                    kh[2*nt2][0]=r0; kh[2*nt2][1]=r1; kh[2*nt2+1][0]=r2; kh[2*nt2+1][1]=r3;
                    ldsm4(r0, r1, r2, r3, ad + KOFF_LO);
                    kl[2*nt2][0]=r0; kl[2*nt2][1]=r1; kl[2*nt2+1][0]=r2; kl[2*nt2+1][1]=r3;
                }
#pragma unroll
                for (int nt = 0; nt < 8; nt++){
                    mma16816(s[nt], qh[ks], kh[nt]);
                    mma16816(s[nt], qh[ks], kl[nt]);
                    mma16816(s[nt], ql[ks], kh[nt]);
                }
            }
            if ((j << 6) + 63 > wq){
                int qr0 = wq + (lane >> 2);
#pragma unroll
                for (int nt = 0; nt < 8; nt++){
                    int kp = (j << 6) + (nt << 3) + ((lane & 3) << 1);
#pragma unroll
                    for (int e = 0; e < 4; e++){
                        int kpos = kp + (e & 1);
                        int qrow = qr0 + ((e >> 1) << 3);
                        if (kpos > qrow) s[nt][e] = -INFINITY;
                    }
                }
            }
            float mx0 = -INFINITY, mx1 = -INFINITY;
#pragma unroll
            for (int nt = 0; nt < 8; nt++){
                mx0 = fmaxf(mx0, fmaxf(s[nt][0], s[nt][1]));
                mx1 = fmaxf(mx1, fmaxf(s[nt][2], s[nt][3]));
            }
            mx0 = fmaxf(mx0, __shfl_xor_sync(0xffffffffu, mx0, 1));
            mx0 = fmaxf(mx0, __shfl_xor_sync(0xffffffffu, mx0, 2));
            mx1 = fmaxf(mx1, __shfl_xor_sync(0xffffffffu, mx1, 1));
            mx1 = fmaxf(mx1, __shfl_xor_sync(0xffffffffu, mx1, 2));
            float mn0 = fmaxf(mr0, mx0), mn1 = fmaxf(mr1, mx1);
            float a0 = ex2f(mr0 - mn0), a1 = ex2f(mr1 - mn1);
            mr0 = mn0; mr1 = mn1;
            lr0 *= a0; lr1 *= a1;
#pragma unroll
            for (int nt = 0; nt < 8; nt++){
                o[nt][0] *= a0; o[nt][1] *= a0; o[nt][2] *= a1; o[nt][3] *= a1;
            }
            float sum0 = 0.f, sum1 = 0.f;
#pragma unroll
            for (int nt = 0; nt < 8; nt++){
                s[nt][0] = ex2f(s[nt][0] - mn0);
                s[nt][1] = ex2f(s[nt][1] - mn0);
                s[nt][2] = ex2f(s[nt][2] - mn1);
                s[nt][3] = ex2f(s[nt][3] - mn1);
                sum0 += s[nt][0] + s[nt][1];
                sum1 += s[nt][2] + s[nt][3];
            }
            lr0 += sum0; lr1 += sum1;
#pragma unroll
            for (int kt = 0; kt < 4; kt++){
                uint32_t ph[4], pl[4];
                {
                    float p00 = s[2*kt][0],   p01 = s[2*kt][1];
                    float p10 = s[2*kt][2],   p11 = s[2*kt][3];
                    float p20 = s[2*kt+1][0], p21 = s[2*kt+1][1];
                    float p30 = s[2*kt+1][2], p31 = s[2*kt+1][3];
                    ph[0] = packbf(p00, p01); ph[1] = packbf(p10, p11);
                    ph[2] = packbf(p20, p21); ph[3] = packbf(p30, p31);
                    pl[0] = packbf(p00 - __uint_as_float(ph[0] << 16),
                                   p01 - __uint_as_float(ph[0] & 0xffff0000u));
                    pl[1] = packbf(p10 - __uint_as_float(ph[1] << 16),
                                   p11 - __uint_as_float(ph[1] & 0xffff0000u));
                    pl[2] = packbf(p20 - __uint_as_float(ph[2] << 16),
                                   p21 - __uint_as_float(ph[2] & 0xffff0000u));
                    pl[3] = packbf(p30 - __uint_as_float(ph[3] << 16),
                                   p31 - __uint_as_float(ph[3] & 0xffff0000u));
                }
#pragma unroll
                for (int nt2 = 0; nt2 < 4; nt2++){
                    uint32_t va = st + VOFF_HI +
                        (uint32_t)(((kt << 4) + (lane & 15)) * AROWB + (((nt2 << 4) + ((lane >> 4) << 3)) << 1));
                    uint32_t r0, r1, r2, r3;
                    ldsm4t(r0, r1, r2, r3, va);
                    uint32_t bh0[2] = {r0, r1}, bh1[2] = {r2, r3};
                    ldsm4t(r0, r1, r2, r3, va + (VOFF_LO - VOFF_HI));
                    uint32_t bl0[2] = {r0, r1}, bl1[2] = {r2, r3};
                    mma16816(o[2*nt2],   ph, bh0);
                    mma16816(o[2*nt2],   pl, bh0);
                    mma16816(o[2*nt2],   ph, bl0);
                    mma16816(o[2*nt2+1], ph, bh1);
                    mma16816(o[2*nt2+1], pl, bh1);
                    mma16816(o[2*nt2+1], ph, bl1);
                }
            }
        }
        __syncthreads();
    }

    lr0 += __shfl_xor_sync(0xffffffffu, lr0, 1);
    lr0 += __shfl_xor_sync(0xffffffffu, lr0, 2);
    lr1 += __shfl_xor_sync(0xffffffffu, lr1, 1);
    lr1 += __shfl_xor_sync(0xffffffffu, lr1, 2);
    float inv0 = 1.f / lr0, inv1 = 1.f / lr1;
    int qrow = wq + (lane >> 2);
    int cc = hh * DHH + ((lane & 3) << 1);
#pragma unroll
    for (int nt = 0; nt < 8; nt++){
        {
            float v0 = o[nt][0] * inv0, v1 = o[nt][1] * inv0;
            uint32_t hh0 = packhf(v0, v1);
            uint32_t ll0 = packhf(v0 - h2f_lo(hh0), v1 - h2f_hi(hh0));
            size_t idx = (size_t)qrow * DD + cc + (nt << 3);
            *(uint32_t*)&g_ctx_hi[idx] = hh0;
            *(uint32_t*)&g_ctx_lo[idx] = ll0;
        }
        {
            float v0 = o[nt][2] * inv1, v1 = o[nt][3] * inv1;
            uint32_t hh0 = packhf(v0, v1);
            uint32_t ll0 = packhf(v0 - h2f_lo(hh0), v1 - h2f_hi(hh0));
            size_t idx = (size_t)(qrow + 8) * DD + cc + (nt << 3);
            *(uint32_t*)&g_ctx_hi[idx] = hh0;
            *(uint32_t*)&g_ctx_lo[idx] = ll0;
        }
    }
}

// ---------------- loss ----------------
__global__ void row_lse_kernel(const float* __restrict__ logits, const int* __restrict__ tgt){
    int t = blockIdx.x;
    const float* row = logits + (size_t)t * VV;
    float mx = -INFINITY;
    for (int i = threadIdx.x; i < VV; i += blockDim.x) mx = fmaxf(mx, row[i]);
    mx = blockMax(mx);
    float s = 0.f;
    for (int i = threadIdx.x; i < VV; i += blockDim.x) s += expf(row[i] - mx);
    s = blockSum(s);
    if (threadIdx.x == 0){
        int tg = tgt[t];
        float lse = mx + logf(s);
        float nll = lse - row[tg];
        g_nll[t] = (tg != 0) ? nll : 0.f;
        g_val[t] = (tg != 0) ? 1.f : 0.f;
    }
}

__global__ void loss_reduce_kernel(float* __restrict__ out_loss){
    float a = 0.f, b = 0.f;
    for (int t = threadIdx.x; t < TT; t += blockDim.x){ a += g_nll[t]; b += g_val[t]; }
    a = blockSum(a);
    b = blockSum(b);
    if (threadIdx.x == 0) *out_loss = a / fmaxf(b, 1.f);
}

// ---------------- launch ----------------
extern "C" void kernel_launch(void* const* d_in, const int* in_sizes, int n_in,
                              void* d_out, int out_size){
    (void)in_sizes; (void)n_in;
    const int*   x     = (const int*)  d_in[0];
    const int*   tgt   = (const int*)  d_in[1];
    const float* tok   = (const float*)d_in[2];
    const float* pos   = (const float*)d_in[3];
    const float* Wqkv  = (const float*)d_in[4];
    const float* Wo    = (const float*)d_in[5];
    const float* ln1g  = (const float*)d_in[6];
    const float* ln1b  = (const float*)d_in[7];
    const float* ln2g  = (const float*)d_in[8];
    const float* ln2b  = (const float*)d_in[9];
    const float* W1    = (const float*)d_in[10];
    const float* b1    = (const float*)d_in[11];
    const float* W2    = (const float*)d_in[12];
    const float* b2    = (const float*)d_in[13];
    const float* lnfg  = (const float*)d_in[14];
    const float* lnfb  = (const float*)d_in[15];
    float* out = (float*)d_out;

    float *ph, *pqkv;
    __half *phn_hi, *phn_lo, *pctx_hi, *pctx_lo, *pff_hi, *pff_lo;
    __half *pwqkv, *pwo, *pw1, *pw2, *ptok;
    cudaGetSymbolAddress((void**)&ph,      g_h);
    cudaGetSymbolAddress((void**)&pqkv,    g_qkv);
    cudaGetSymbolAddress((void**)&phn_hi,  g_hn_hi);
    cudaGetSymbolAddress((void**)&phn_lo,  g_hn_lo);
    cudaGetSymbolAddress((void**)&pctx_hi, g_ctx_hi);
    cudaGetSymbolAddress((void**)&pctx_lo, g_ctx_lo);
    cudaGetSymbolAddress((void**)&pff_hi,  g_ff_hi);
    cudaGetSymbolAddress((void**)&pff_lo,  g_ff_lo);
    cudaGetSymbolAddress((void**)&pwqkv,   w_qkv_h);
    cudaGetSymbolAddress((void**)&pwo,     w_o_h);
    cudaGetSymbolAddress((void**)&pw1,     w_1_h);
    cudaGetSymbolAddress((void**)&pw2,     w_2_h);
    cudaGetSymbolAddress((void**)&ptok,    w_tok_h);

    cudaFuncSetAttribute(gemm_mma<0,0,0,0>, cudaFuncAttributeMaxDynamicSharedMemorySize, G_SMEM);
    cudaFuncSetAttribute(gemm_mma<0,0,1,0>, cudaFuncAttributeMaxDynamicSharedMemorySize, G_SMEM);
    cudaFuncSetAttribute(gemm_mma<1,1,0,1>, cudaFuncAttributeMaxDynamicSharedMemorySize, G_SMEM);
    cudaFuncSetAttribute(gemm_mma<1,0,1,0>, cudaFuncAttributeMaxDynamicSharedMemorySize, G_SMEM);
    cudaFuncSetAttribute(attn_tc, cudaFuncAttributeMaxDynamicSharedMemorySize, ATT_SMEM);

    // one-time weight conversions (graph-captured each launch; ~70us total)
    cvt_kernel<<<1024, 256>>>(Wqkv, pwqkv, LL*QKV3*DD);
    cvt_kernel<<<1024, 256>>>(Wo,   pwo,   LL*DD*DD);
    cvt_kernel<<<1024, 256>>>(W1,   pw1,   LL*FFD*DD);
    cvt_kernel<<<1024, 256>>>(W2,   pw2,   LL*DD*FFD);
    cvt_kernel<<<2048, 256>>>(tok,  ptok,  VV*DD);

    embed_kernel<<<TT, 256>>>(x, tok, pos);

    for (int l = 0; l < LL; l++){
        ln_kernel_hl<<<TT, 256>>>(ph, phn_hi, phn_lo, ln1g + l*DD, ln1b + l*DD);
        gemm_mma<0,0,0,0><<<dim3(TT/128, QKV3/128), 256, G_SMEM>>>(
            phn_hi, phn_lo, pwqkv + (size_t)l*QKV3*DD, nullptr, nullptr,
            pqkv, nullptr, nullptr, TT, QKV3, DD);
        attn_tc<<<dim3(TT/128, HH), 256, ATT_SMEM>>>();
        gemm_mma<0,0,1,0><<<dim3(TT/128, DD/128), 256, G_SMEM>>>(
            pctx_hi, pctx_lo, pwo + (size_t)l*DD*DD, nullptr, ph,
            ph, nullptr, nullptr, TT, DD, DD);
        ln_kernel_hl<<<TT, 256>>>(ph, phn_hi, phn_lo, ln2g + l*DD, ln2b + l*DD);
        gemm_mma<1,1,0,1><<<dim3(TT/128, FFD/128), 256, G_SMEM>>>(
            phn_hi, phn_lo, pw1 + (size_t)l*FFD*DD, b1 + (size_t)l*FFD, nullptr,
            nullptr, pff_hi, pff_lo, TT, FFD, DD);
        gemm_mma<1,0,1,0><<<dim3(TT/128, DD/128), 256, G_SMEM>>>(
            pff_hi, pff_lo, pw2 + (size_t)l*DD*FFD, b2 + (size_t)l*DD, ph,
            ph, nullptr, nullptr, TT, DD, FFD);
    }

    ln_kernel_hl<<<TT, 256>>>(ph, phn_hi, phn_lo, lnfg, lnfb);
    gemm_mma<0,0,0,0><<<dim3(TT/128, VV/128), 256, G_SMEM>>>(
        phn_hi, phn_lo, ptok, nullptr, nullptr,
        out, nullptr, nullptr, TT, VV, DD);

    row_lse_kernel<<<TT, 256>>>(out, tgt);
    if (out_size > TT * VV)
        loss_reduce_kernel<<<1, 256>>>(out + (size_t)TT * VV);
}

// round 11
// speedup vs baseline: 1.1894x; 1.0197x over previous
#include <cuda_runtime.h>
#include <cuda_bf16.h>
#include <cuda_fp16.h>
#include <math.h>
#include <stdint.h>

// Problem constants
#define TT   2048
#define DD   768
#define HH   12
#define DHH  64
#define LL   6
#define FFD  3072
#define VV   32000
#define QKV3 (3*DD)

// ---------------- scratch ----------------
__device__ float  g_h  [TT*DD];
__device__ float  g_nll[TT];
__device__ float  g_val[TT];
__device__ __half g_qkv_hi[TT*QKV3];
__device__ __half g_qkv_lo[TT*QKV3];
__device__ __half g_hn_hi [TT*DD];
__device__ __half g_hn_lo [TT*DD];
__device__ __half g_ctx_hi[TT*DD];
__device__ __half g_ctx_lo[TT*DD];
__device__ __half g_ff_hi [TT*FFD];
__device__ __half g_ff_lo [TT*FFD];
// fp16 weights (converted once per launch)
__device__ __half w_qkv_h[LL*QKV3*DD];
__device__ __half w_o_h  [LL*DD*DD];
__device__ __half w_1_h  [LL*FFD*DD];
__device__ __half w_2_h  [LL*DD*FFD];
__device__ __half w_tok_h[(size_t)VV*DD];

// ---------------- helpers ----------------
__device__ __forceinline__ uint32_t smem_u32(const void* p){
    uint32_t a;
    asm("{ .reg .u64 t; cvta.to.shared.u64 t, %1; cvt.u32.u64 %0, t; }" : "=r"(a) : "l"(p));
    return a;
}
__device__ __forceinline__ uint32_t packhf(float x0, float x1){
    uint32_t r;
    asm("cvt.rn.f16x2.f32 %0, %1, %2;" : "=r"(r) : "f"(x1), "f"(x0));
    return r;
}
__device__ __forceinline__ float h2f_lo(uint32_t p){
    float f; asm("{ .reg .b16 h, dummy; mov.b32 {h, dummy}, %1; cvt.f32.f16 %0, h; }" : "=f"(f) : "r"(p));
    return f;
}
__device__ __forceinline__ float h2f_hi(uint32_t p){
    float f; asm("{ .reg .b16 h, dummy; mov.b32 {dummy, h}, %1; cvt.f32.f16 %0, h; }" : "=f"(f) : "r"(p));
    return f;
}
__device__ __forceinline__ float ex2f(float x){
    float y; asm("ex2.approx.f32 %0, %1;" : "=f"(y) : "f"(x)); return y;
}
__device__ __forceinline__ void ldsm4(uint32_t &r0, uint32_t &r1, uint32_t &r2, uint32_t &r3,
                                      uint32_t addr){
    asm volatile("ldmatrix.sync.aligned.m8n8.x4.shared.b16 {%0,%1,%2,%3}, [%4];"
        : "=r"(r0), "=r"(r1), "=r"(r2), "=r"(r3) : "r"(addr));
}
__device__ __forceinline__ void ldsm4t(uint32_t &r0, uint32_t &r1, uint32_t &r2, uint32_t &r3,
                                       uint32_t addr){
    asm volatile("ldmatrix.sync.aligned.m8n8.x4.trans.shared.b16 {%0,%1,%2,%3}, [%4];"
        : "=r"(r0), "=r"(r1), "=r"(r2), "=r"(r3) : "r"(addr));
}
__device__ __forceinline__ void mma16816h(float* d, const uint32_t* a, const uint32_t* b){
    asm volatile("mma.sync.aligned.m16n8k16.row.col.f32.f16.f16.f32 "
        "{%0,%1,%2,%3}, {%4,%5,%6,%7}, {%8,%9}, {%0,%1,%2,%3};"
        : "+f"(d[0]), "+f"(d[1]), "+f"(d[2]), "+f"(d[3])
        : "r"(a[0]), "r"(a[1]), "r"(a[2]), "r"(a[3]), "r"(b[0]), "r"(b[1]));
}
#define CP_ASYNC16(dst, src) \
    asm volatile("cp.async.cg.shared.global [%0], [%1], 16;" :: "r"(dst), "l"(src) : "memory")
#define CP_COMMIT() asm volatile("cp.async.commit_group;" ::: "memory")
#define CP_WAIT1()  asm volatile("cp.async.wait_group 1;" ::: "memory")
#define CP_WAIT0()  asm volatile("cp.async.wait_group 0;" ::: "memory")

// ---------------- reductions ----------------
__device__ __forceinline__ float warpSum(float v){
#pragma unroll
    for (int o = 16; o; o >>= 1) v += __shfl_xor_sync(0xffffffffu, v, o);
    return v;
}
__device__ __forceinline__ float warpMax(float v){
#pragma unroll
    for (int o = 16; o; o >>= 1) v = fmaxf(v, __shfl_xor_sync(0xffffffffu, v, o));
    return v;
}
__device__ float blockSum(float v){
    __shared__ float s[9];
    __syncthreads();
    int lane = threadIdx.x & 31, w = threadIdx.x >> 5;
    v = warpSum(v);
    if (lane == 0) s[w] = v;
    __syncthreads();
    if (w == 0){
        float x = (lane < (int)(blockDim.x >> 5)) ? s[lane] : 0.f;
        x = warpSum(x);
        if (lane == 0) s[8] = x;
    }
    __syncthreads();
    return s[8];
}
__device__ float blockMax(float v){
    __shared__ float s[9];
    __syncthreads();
    int lane = threadIdx.x & 31, w = threadIdx.x >> 5;
    v = warpMax(v);
    if (lane == 0) s[w] = v;
    __syncthreads();
    if (w == 0){
        float x = (lane < (int)(blockDim.x >> 5)) ? s[lane] : -INFINITY;
        x = warpMax(x);
        if (lane == 0) s[8] = x;
    }
    __syncthreads();
    return s[8];
}

// ---------------- fp32 -> fp16 weight conversion ----------------
__global__ void cvt_kernel(const float* __restrict__ src, __half* __restrict__ dst, int n){
    int i = (blockIdx.x * blockDim.x + threadIdx.x) << 2;
    int stride = (gridDim.x * blockDim.x) << 2;
    for (; i < n; i += stride){
        float4 f = *(const float4*)(src + i);
        *(uint2*)&dst[i] = make_uint2(packhf(f.x, f.y), packhf(f.z, f.w));
    }
}

// ---------------- embedding ----------------
__global__ void embed_kernel(const int* __restrict__ x,
                             const float* __restrict__ tok,
                             const float* __restrict__ pos){
    int t  = blockIdx.x;
    int id = x[t];
    const float* tr = tok + (size_t)id * DD;
    const float* pr = pos + (size_t)t  * DD;
    for (int d = threadIdx.x; d < DD; d += blockDim.x)
        g_h[t*DD + d] = tr[d] + pr[d];
}

// ---------------- layernorm -> fp16 hi/lo ----------------
__global__ void ln_kernel_hl(const float* __restrict__ in,
                             __half* __restrict__ ohi, __half* __restrict__ olo,
                             const float* __restrict__ g, const float* __restrict__ b){
    __shared__ float row[DD];
    int t = blockIdx.x;
    const float* r = in + (size_t)t * DD;
    float s = 0.f;
    for (int d = threadIdx.x; d < DD; d += blockDim.x){ float v = r[d]; row[d] = v; s += v; }
    s = blockSum(s);
    float mean = s * (1.f / DD);
    float q = 0.f;
    for (int d = threadIdx.x; d < DD; d += blockDim.x){ float v = row[d] - mean; q += v*v; }
    q = blockSum(q);
    float rstd = rsqrtf(q * (1.f / DD) + 1e-5f);
    for (int d = threadIdx.x; d < (DD >> 1); d += blockDim.x){
        int i0 = d << 1;
        float v0 = (row[i0]     - mean) * rstd * g[i0]     + b[i0];
        float v1 = (row[i0 + 1] - mean) * rstd * g[i0 + 1] + b[i0 + 1];
        uint32_t hh = packhf(v0, v1);
        uint32_t ll = packhf(v0 - h2f_lo(hh), v1 - h2f_hi(hh));
        *(uint32_t*)&ohi[t*DD + i0] = hh;
        *(uint32_t*)&olo[t*DD + i0] = ll;
    }
}

// ================== fp16 2-product GEMM, cp.async 3-stage, 2 CTAs/SM ==========
#define ROWB 80
#define STAGE_B 30720
#define G_SMEM (3*STAGE_B)

template<int BIASF, int GELUF, int RESF, int OUTHL>
__global__ __launch_bounds__(256, 2)
void gemm_mma(const __half* __restrict__ Ahi, const __half* __restrict__ Alo,
              const __half* __restrict__ Bw,
              const float* __restrict__ bias, const float* __restrict__ res,
              float* __restrict__ C, __half* __restrict__ Chi, __half* __restrict__ Clo,
              int M, int N, int K)
{
    extern __shared__ char smem[];
    const uint32_t sb = smem_u32(smem);
    const int tid = threadIdx.x, wid = tid >> 5, lane = tid & 31;
    const int m0 = blockIdx.x << 7, n0 = blockIdx.y << 7;
    const int wm = (wid >> 2) << 6;
    const int wn = (wid & 3) << 5;

    const int lrow = tid >> 2;
    const int k16  = tid & 3;
    const __half* aHp = Ahi + (size_t)(m0 + lrow) * K + (k16 << 3);
    const __half* aLp = Alo + (size_t)(m0 + lrow) * K + (k16 << 3);
    const __half* bP  = Bw  + (size_t)(n0 + lrow) * K + (k16 << 3);
    const uint32_t dOff = (uint32_t)(lrow * ROWB + (k16 << 4));

    float acc[4][4][4];
#pragma unroll
    for (int i = 0; i < 4; i++)
#pragma unroll
        for (int j = 0; j < 4; j++)
#pragma unroll
            for (int k = 0; k < 4; k++) acc[i][j][k] = 0.f;

    const int NC = K >> 5;

    auto issue = [&](int c, int s){
        uint32_t d = sb + s * STAGE_B + dOff;
        const __half* a0 = aHp + (size_t)c * 32;
        const __half* a1 = aLp + (size_t)c * 32;
        const __half* b0 = bP  + (size_t)c * 32;
        CP_ASYNC16(d,                a0);
        CP_ASYNC16(d + 5120,         a0 + (size_t)64 * K);
        CP_ASYNC16(d + 10240,        a1);
        CP_ASYNC16(d + 10240 + 5120, a1 + (size_t)64 * K);
        CP_ASYNC16(d + 20480,        b0);
        CP_ASYNC16(d + 20480 + 5120, b0 + (size_t)64 * K);
    };

    issue(0, 0); CP_COMMIT();
    if (NC > 1){ issue(1, 1); CP_COMMIT(); }

    const int g  = lane >> 3, lr = lane & 7;
    const int arow_off = ((g & 1) << 3) + lr;
    const int akb      = (g >> 1) << 4;
    const int brow_off = ((g >> 1) << 3) + lr;
    const int bkb      = (g & 1) << 4;

    int st_c = 0;
    for (int c = 0; c < NC; c++){
        CP_WAIT1();
        __syncthreads();

        int st_n2 = st_c + 2; if (st_n2 >= 3) st_n2 -= 3;
        if (c + 2 < NC) issue(c + 2, st_n2);
        CP_COMMIT();

        const uint32_t st = sb + st_c * STAGE_B;
#pragma unroll
        for (int h = 0; h < 2; h++){
            uint32_t Bh[4][2];
#pragma unroll
            for (int nt2 = 0; nt2 < 2; nt2++){
                uint32_t bd = st + 20480 + (uint32_t)((wn + (nt2 << 4) + brow_off) * ROWB + (h << 5) + bkb);
                uint32_t r0, r1, r2, r3;
                ldsm4(r0, r1, r2, r3, bd);
                Bh[2*nt2][0] = r0; Bh[2*nt2][1] = r1; Bh[2*nt2+1][0] = r2; Bh[2*nt2+1][1] = r3;
            }
#pragma unroll
            for (int mt = 0; mt < 4; mt++){
                uint32_t Ah[4], Al[4];
                uint32_t ad = st + (uint32_t)((wm + (mt << 4) + arow_off) * ROWB + (h << 5) + akb);
                ldsm4(Ah[0], Ah[1], Ah[2], Ah[3], ad);
                ldsm4(Al[0], Al[1], Al[2], Al[3], ad + 10240);
#pragma unroll
                for (int nt = 0; nt < 4; nt++){
                    mma16816h(acc[mt][nt], Ah, Bh[nt]);
                    mma16816h(acc[mt][nt], Al, Bh[nt]);
                }
            }
        }
        st_c = st_c + 1; if (st_c >= 3) st_c = 0;
    }

    const int qr = lane >> 2, qc = lane & 3;
#pragma unroll
    for (int mt = 0; mt < 4; mt++){
#pragma unroll
        for (int p = 0; p < 2; p++){
            int m = m0 + wm + (mt << 4) + qr + (p << 3);
            size_t rowbase = (size_t)m * N;
#pragma unroll
            for (int nt = 0; nt < 4; nt++){
                int n = n0 + wn + (nt << 3) + (qc << 1);
                float v0 = acc[mt][nt][2*p], v1 = acc[mt][nt][2*p + 1];
                if (BIASF){ v0 += bias[n]; v1 += bias[n + 1]; }
                if (GELUF){
                    v0 = 0.5f * v0 * (1.f + erff(v0 * 0.70710678118654752f));
                    v1 = 0.5f * v1 * (1.f + erff(v1 * 0.70710678118654752f));
                }
                if (RESF){
                    float2 rr = *(const float2*)&res[rowbase + n];
                    v0 += rr.x; v1 += rr.y;
                }
                if (OUTHL){
                    uint32_t hh = packhf(v0, v1);
                    uint32_t ll = packhf(v0 - h2f_lo(hh), v1 - h2f_hi(hh));
                    *(uint32_t*)&Chi[rowbase + n] = hh;
                    *(uint32_t*)&Clo[rowbase + n] = ll;
                } else {
                    *(float2*)&C[rowbase + n] = make_float2(v0, v1);
                }
            }
        }
    }
}

// ================== tensor-core flash attention, fp16 tiles via cp.async ==========
// stage: Khi[64x144B]=9216, Klo=9216, Vhi=9216 -> 27648; 2 stages = 55296 B.
#define AROWB 144
#define KOFF_LO  9216
#define VOFF_HI 18432
#define ATT_STAGE 27648
#define ATT_SMEM (2*ATT_STAGE)

__global__ __launch_bounds__(256)
void attn_tc(){
    extern __shared__ char smc[];
    const uint32_t sb = smem_u32(smc);
    const int tid = threadIdx.x, wid = tid >> 5, lane = tid & 31;
    const int qb = gridDim.x - 1 - (int)blockIdx.x;
    const int hh = blockIdx.y;
    const int q0 = qb << 7;
    const int wq = q0 + (wid << 4);

    // ---- Q fragments: reconstruct fp32 from hi/lo, scale, resplit to fp16 hi/lo ----
    const float SCL = 0.125f * 1.4426950408889634f;
    uint32_t qh[4][4], ql[4][4];
    {
        int r0 = wq + (lane >> 2);
        int c0 = (lane & 3) << 1;
#pragma unroll
        for (int kt = 0; kt < 4; kt++){
#pragma unroll
            for (int rr = 0; rr < 2; rr++){
                size_t idx = (size_t)(r0 + (rr << 3)) * QKV3 + hh * DHH + (kt << 4) + c0;
                uint32_t uh0 = *(const uint32_t*)&g_qkv_hi[idx];
                uint32_t ul0 = *(const uint32_t*)&g_qkv_lo[idx];
                uint32_t uh1 = *(const uint32_t*)&g_qkv_hi[idx + 8];
                uint32_t ul1 = *(const uint32_t*)&g_qkv_lo[idx + 8];
                float x0 = (h2f_lo(uh0) + h2f_lo(ul0)) * SCL;
                float x1 = (h2f_hi(uh0) + h2f_hi(ul0)) * SCL;
                float x2 = (h2f_lo(uh1) + h2f_lo(ul1)) * SCL;
                float x3 = (h2f_hi(uh1) + h2f_hi(ul1)) * SCL;
                uint32_t h0 = packhf(x0, x1), h1 = packhf(x2, x3);
                qh[kt][rr]     = h0;
                qh[kt][rr + 2] = h1;
                ql[kt][rr]     = packhf(x0 - h2f_lo(h0), x1 - h2f_hi(h0));
                ql[kt][rr + 2] = packhf(x2 - h2f_lo(h1), x3 - h2f_hi(h1));
            }
        }
    }

    float o[8][4];
#pragma unroll
    for (int i = 0; i < 8; i++){ o[i][0]=0.f; o[i][1]=0.f; o[i][2]=0.f; o[i][3]=0.f; }
    float mr0 = -INFINITY, mr1 = -INFINITY, lr0 = 0.f, lr1 = 0.f;

    const int jmax = (q0 >> 6) + 1;

    // cp.async loader: row = tid>>2 (0..63), 16B chunks k16 and k16+4
    const int ldr = tid >> 2;
    const int k16 = tid & 3;
    const __half* kHp = g_qkv_hi + (size_t)ldr * QKV3 + DD     + hh * DHH + (k16 << 3);
    const __half* kLp = g_qkv_lo + (size_t)ldr * QKV3 + DD     + hh * DHH + (k16 << 3);
    const __half* vHp = g_qkv_hi + (size_t)ldr * QKV3 + 2 * DD + hh * DHH + (k16 << 3);
    const uint32_t dOff = (uint32_t)(ldr * AROWB + (k16 << 4));

    auto issue = [&](int j, int s){
        uint32_t d = sb + s * ATT_STAGE + dOff;
        size_t adv = (size_t)(j << 6) * QKV3;
        CP_ASYNC16(d,                 kHp + adv);
        CP_ASYNC16(d + 64,            kHp + adv + 32);
        CP_ASYNC16(d + KOFF_LO,       kLp + adv);
        CP_ASYNC16(d + KOFF_LO + 64,  kLp + adv + 32);
        CP_ASYNC16(d + VOFF_HI,       vHp + adv);
        CP_ASYNC16(d + VOFF_HI + 64,  vHp + adv + 32);
    };

    issue(0, 0); CP_COMMIT();

    const int g  = lane >> 3, lr8 = lane & 7;
    const int brow_off = ((g >> 1) << 3) + lr8;
    const int bkb      = (g & 1) << 4;

    for (int j = 0; j <= jmax; j++){
        if (j < jmax){ issue(j + 1, (j + 1) & 1); CP_COMMIT(); CP_WAIT1(); }
        else { CP_WAIT0(); }
        __syncthreads();

        const uint32_t st = sb + (j & 1) * ATT_STAGE;

        if ((j << 6) <= wq + 15){
            // ---- S = Q K^T (fp16 3-product: QhKh + QlKh + QhKl) ----
            float s[8][4];
#pragma unroll
            for (int i = 0; i < 8; i++){ s[i][0]=0.f; s[i][1]=0.f; s[i][2]=0.f; s[i][3]=0.f; }
#pragma unroll
            for (int ks = 0; ks < 4; ks++){
                uint32_t kh[8][2], kl[8][2];
#pragma unroll
                for (int nt2 = 0; nt2 < 4; nt2++){
                    uint32_t ad = st + (uint32_t)(((nt2 << 4) + brow_off) * AROWB + (ks << 5) + bkb);
                    uint32_t r0, r1, r2, r3;
                    ldsm4(r0, r1, r2, r3, ad);
                    kh[2*nt2][0]=r0; kh[2*nt2][1]=r1; kh[2*nt2+1][0]=r2; kh[2*nt2+1][1]=r3;
                    ldsm4(r0, r1, r2, r3, ad + KOFF_LO);
                    kl[2*nt2][0]=r0; kl[2*nt2][1]=r1; kl[2*nt2+1][0]=r2; kl[2*nt2+1][1]=r3;
                }
#pragma unroll
                for (int nt = 0; nt < 8; nt++){
                    mma16816h(s[nt], qh[ks], kh[nt]);
                    mma16816h(s[nt], ql[ks], kh[nt]);
                    mma16816h(s[nt], qh[ks], kl[nt]);
                }
            }
            // ---- causal mask ----
            if ((j << 6) + 63 > wq){
                int qr0 = wq + (lane >> 2);
#pragma unroll
                for (int nt = 0; nt < 8; nt++){
                    int kp = (j << 6) + (nt << 3) + ((lane & 3) << 1);
#pragma unroll
                    for (int e = 0; e < 4; e++){
                        int kpos = kp + (e & 1);
                        int qrow = qr0 + ((e >> 1) << 3);
                        if (kpos > qrow) s[nt][e] = -INFINITY;
                    }
                }
            }
            // ---- online softmax (log2 domain) ----
            float mx0 = -INFINITY, mx1 = -INFINITY;
#pragma unroll
            for (int nt = 0; nt < 8; nt++){
                mx0 = fmaxf(mx0, fmaxf(s[nt][0], s[nt][1]));
                mx1 = fmaxf(mx1, fmaxf(s[nt][2], s[nt][3]));
            }
            mx0 = fmaxf(mx0, __shfl_xor_sync(0xffffffffu, mx0, 1));
            mx0 = fmaxf(mx0, __shfl_xor_sync(0xffffffffu, mx0, 2));
            mx1 = fmaxf(mx1, __shfl_xor_sync(0xffffffffu, mx1, 1));
            mx1 = fmaxf(mx1, __shfl_xor_sync(0xffffffffu, mx1, 2));
            float mn0 = fmaxf(mr0, mx0), mn1 = fmaxf(mr1, mx1);
            float a0 = ex2f(mr0 - mn0), a1 = ex2f(mr1 - mn1);
            mr0 = mn0; mr1 = mn1;
            lr0 *= a0; lr1 *= a1;
#pragma unroll
            for (int nt = 0; nt < 8; nt++){
                o[nt][0] *= a0; o[nt][1] *= a0; o[nt][2] *= a1; o[nt][3] *= a1;
            }
            float sum0 = 0.f, sum1 = 0.f;
#pragma unroll
            for (int nt = 0; nt < 8; nt++){
                s[nt][0] = ex2f(s[nt][0] - mn0);
                s[nt][1] = ex2f(s[nt][1] - mn0);
                s[nt][2] = ex2f(s[nt][2] - mn1);
                s[nt][3] = ex2f(s[nt][3] - mn1);
                sum0 += s[nt][0] + s[nt][1];
                sum1 += s[nt][2] + s[nt][3];
            }
            lr0 += sum0; lr1 += sum1;
            // ---- O += P V (fp16 2-product: P hi/lo x V-hi) ----
#pragma unroll
            for (int kt = 0; kt < 4; kt++){
                uint32_t ph[4], pl[4];
                {
                    float p00 = s[2*kt][0],   p01 = s[2*kt][1];
                    float p10 = s[2*kt][2],   p11 = s[2*kt][3];
                    float p20 = s[2*kt+1][0], p21 = s[2*kt+1][1];
                    float p30 = s[2*kt+1][2], p31 = s[2*kt+1][3];
                    ph[0] = packhf(p00, p01); ph[1] = packhf(p10, p11);
                    ph[2] = packhf(p20, p21); ph[3] = packhf(p30, p31);
                    pl[0] = packhf(p00 - h2f_lo(ph[0]), p01 - h2f_hi(ph[0]));
                    pl[1] = packhf(p10 - h2f_lo(ph[1]), p11 - h2f_hi(ph[1]));
                    pl[2] = packhf(p20 - h2f_lo(ph[2]), p21 - h2f_hi(ph[2]));
                    pl[3] = packhf(p30 - h2f_lo(ph[3]), p31 - h2f_hi(ph[3]));
                }
#pragma unroll
                for (int nt2 = 0; nt2 < 4; nt2++){
                    uint32_t va = st + VOFF_HI +
                        (uint32_t)(((kt << 4) + (lane & 15)) * AROWB + (((nt2 << 4) + ((lane >> 4) << 3)) << 1));
                    uint32_t r0, r1, r2, r3;
                    ldsm4t(r0, r1, r2, r3, va);
                    uint32_t bh0[2] = {r0, r1}, bh1[2] = {r2, r3};
                    mma16816h(o[2*nt2],   ph, bh0);
                    mma16816h(o[2*nt2],   pl, bh0);
                    mma16816h(o[2*nt2+1], ph, bh1);
                    mma16816h(o[2*nt2+1], pl, bh1);
                }
            }
        }
        __syncthreads();
    }

    // ---- finalize -> fp16 hi/lo ctx ----
    lr0 += __shfl_xor_sync(0xffffffffu, lr0, 1);
    lr0 += __shfl_xor_sync(0xffffffffu, lr0, 2);
    lr1 += __shfl_xor_sync(0xffffffffu, lr1, 1);
    lr1 += __shfl_xor_sync(0xffffffffu, lr1, 2);
    float inv0 = 1.f / lr0, inv1 = 1.f / lr1;
    int qrow = wq + (lane >> 2);
    int cc = hh * DHH + ((lane & 3) << 1);
#pragma unroll
    for (int nt = 0; nt < 8; nt++){
        {
            float v0 = o[nt][0] * inv0, v1 = o[nt][1] * inv0;
            uint32_t hh0 = packhf(v0, v1);
            uint32_t ll0 = packhf(v0 - h2f_lo(hh0), v1 - h2f_hi(hh0));
            size_t idx = (size_t)qrow * DD + cc + (nt << 3);
            *(uint32_t*)&g_ctx_hi[idx] = hh0;
            *(uint32_t*)&g_ctx_lo[idx] = ll0;
        }
        {
            float v0 = o[nt][2] * inv1, v1 = o[nt][3] * inv1;
            uint32_t hh0 = packhf(v0, v1);
            uint32_t ll0 = packhf(v0 - h2f_lo(hh0), v1 - h2f_hi(hh0));
            size_t idx = (size_t)(qrow + 8) * DD + cc + (nt << 3);
            *(uint32_t*)&g_ctx_hi[idx] = hh0;
            *(uint32_t*)&g_ctx_lo[idx] = ll0;
        }
    }
}

// ---------------- loss ----------------
__global__ void row_lse_kernel(const float* __restrict__ logits, const int* __restrict__ tgt){
    int t = blockIdx.x;
    const float* row = logits + (size_t)t * VV;
    float mx = -INFINITY;
    for (int i = threadIdx.x; i < VV; i += blockDim.x) mx = fmaxf(mx, row[i]);
    mx = blockMax(mx);
    float s = 0.f;
    for (int i = threadIdx.x; i < VV; i += blockDim.x) s += expf(row[i] - mx);
    s = blockSum(s);
    if (threadIdx.x == 0){
        int tg = tgt[t];
        float lse = mx + logf(s);
        float nll = lse - row[tg];
        g_nll[t] = (tg != 0) ? nll : 0.f;
        g_val[t] = (tg != 0) ? 1.f : 0.f;
    }
}

__global__ void loss_reduce_kernel(float* __restrict__ out_loss){
    float a = 0.f, b = 0.f;
    for (int t = threadIdx.x; t < TT; t += blockDim.x){ a += g_nll[t]; b += g_val[t]; }
    a = blockSum(a);
    b = blockSum(b);
    if (threadIdx.x == 0) *out_loss = a / fmaxf(b, 1.f);
}

// ---------------- launch ----------------
extern "C" void kernel_launch(void* const* d_in, const int* in_sizes, int n_in,
                              void* d_out, int out_size){
    (void)in_sizes; (void)n_in;
    const int*   x     = (const int*)  d_in[0];
    const int*   tgt   = (const int*)  d_in[1];
    const float* tok   = (const float*)d_in[2];
    const float* pos   = (const float*)d_in[3];
    const float* Wqkv  = (const float*)d_in[4];
    const float* Wo    = (const float*)d_in[5];
    const float* ln1g  = (const float*)d_in[6];
    const float* ln1b  = (const float*)d_in[7];
    const float* ln2g  = (const float*)d_in[8];
    const float* ln2b  = (const float*)d_in[9];
    const float* W1    = (const float*)d_in[10];
    const float* b1    = (const float*)d_in[11];
    const float* W2    = (const float*)d_in[12];
    const float* b2    = (const float*)d_in[13];
    const float* lnfg  = (const float*)d_in[14];
    const float* lnfb  = (const float*)d_in[15];
    float* out = (float*)d_out;

    float *ph;
    __half *pqkv_hi, *pqkv_lo, *phn_hi, *phn_lo, *pctx_hi, *pctx_lo, *pff_hi, *pff_lo;
    __half *pwqkv, *pwo, *pw1, *pw2, *ptok;
    cudaGetSymbolAddress((void**)&ph,      g_h);
    cudaGetSymbolAddress((void**)&pqkv_hi, g_qkv_hi);
    cudaGetSymbolAddress((void**)&pqkv_lo, g_qkv_lo);
    cudaGetSymbolAddress((void**)&phn_hi,  g_hn_hi);
    cudaGetSymbolAddress((void**)&phn_lo,  g_hn_lo);
    cudaGetSymbolAddress((void**)&pctx_hi, g_ctx_hi);
    cudaGetSymbolAddress((void**)&pctx_lo, g_ctx_lo);
    cudaGetSymbolAddress((void**)&pff_hi,  g_ff_hi);
    cudaGetSymbolAddress((void**)&pff_lo,  g_ff_lo);
    cudaGetSymbolAddress((void**)&pwqkv,   w_qkv_h);
    cudaGetSymbolAddress((void**)&pwo,     w_o_h);
    cudaGetSymbolAddress((void**)&pw1,     w_1_h);
    cudaGetSymbolAddress((void**)&pw2,     w_2_h);
    cudaGetSymbolAddress((void**)&ptok,    w_tok_h);

    cudaFuncSetAttribute(gemm_mma<0,0,0,1>, cudaFuncAttributeMaxDynamicSharedMemorySize, G_SMEM);
    cudaFuncSetAttribute(gemm_mma<0,0,1,0>, cudaFuncAttributeMaxDynamicSharedMemorySize, G_SMEM);
    cudaFuncSetAttribute(gemm_mma<1,1,0,1>, cudaFuncAttributeMaxDynamicSharedMemorySize, G_SMEM);
    cudaFuncSetAttribute(gemm_mma<1,0,1,0>, cudaFuncAttributeMaxDynamicSharedMemorySize, G_SMEM);
    cudaFuncSetAttribute(gemm_mma<0,0,0,0>, cudaFuncAttributeMaxDynamicSharedMemorySize, G_SMEM);
    cudaFuncSetAttribute(attn_tc, cudaFuncAttributeMaxDynamicSharedMemorySize, ATT_SMEM);

    cvt_kernel<<<1024, 256>>>(Wqkv, pwqkv, LL*QKV3*DD);
    cvt_kernel<<<1024, 256>>>(Wo,   pwo,   LL*DD*DD);
    cvt_kernel<<<1024, 256>>>(W1,   pw1,   LL*FFD*DD);
    cvt_kernel<<<1024, 256>>>(W2,   pw2,   LL*DD*FFD);
    cvt_kernel<<<2048, 256>>>(tok,  ptok,  VV*DD);

    embed_kernel<<<TT, 256>>>(x, tok, pos);

    for (int l = 0; l < LL; l++){
        ln_kernel_hl<<<TT, 256>>>(ph, phn_hi, phn_lo, ln1g + l*DD, ln1b + l*DD);
        gemm_mma<0,0,0,1><<<dim3(TT/128, QKV3/128), 256, G_SMEM>>>(
            phn_hi, phn_lo, pwqkv + (size_t)l*QKV3*DD, nullptr, nullptr,
            nullptr, pqkv_hi, pqkv_lo, TT, QKV3, DD);
        attn_tc<<<dim3(TT/128, HH), 256, ATT_SMEM>>>();
        gemm_mma<0,0,1,0><<<dim3(TT/128, DD/128), 256, G_SMEM>>>(
            pctx_hi, pctx_lo, pwo + (size_t)l*DD*DD, nullptr, ph,
            ph, nullptr, nullptr, TT, DD, DD);
        ln_kernel_hl<<<TT, 256>>>(ph, phn_hi, phn_lo, ln2g + l*DD, ln2b + l*DD);
        gemm_mma<1,1,0,1><<<dim3(TT/128, FFD/128), 256, G_SMEM>>>(
            phn_hi, phn_lo, pw1 + (size_t)l*FFD*DD, b1 + (size_t)l*FFD, nullptr,
            nullptr, pff_hi, pff_lo, TT, FFD, DD);
        gemm_mma<1,0,1,0><<<dim3(TT/128, DD/128), 256, G_SMEM>>>(
            pff_hi, pff_lo, pw2 + (size_t)l*DD*FFD, b2 + (size_t)l*DD, ph,
            ph, nullptr, nullptr, TT, DD, FFD);
    }

    ln_kernel_hl<<<TT, 256>>>(ph, phn_hi, phn_lo, lnfg, lnfb);
    gemm_mma<0,0,0,0><<<dim3(TT/128, VV/128), 256, G_SMEM>>>(
        phn_hi, phn_lo, ptok, nullptr, nullptr,
        out, nullptr, nullptr, TT, VV, DD);

    row_lse_kernel<<<TT, 256>>>(out, tgt);
    if (out_size > TT * VV)
        loss_reduce_kernel<<<1, 256>>>(out + (size_t)TT * VV);
}

// round 12
// speedup vs baseline: 1.2136x; 1.0203x over previous
#include <cuda_runtime.h>
#include <cuda_bf16.h>
#include <cuda_fp16.h>
#include <math.h>
#include <stdint.h>

// Problem constants
#define TT   2048
#define DD   768
#define HH   12
#define DHH  64
#define LL   6
#define FFD  3072
#define VV   32000
#define QKV3 (3*DD)

// ---------------- scratch ----------------
__device__ float  g_h  [TT*DD];
__device__ float  g_nll[TT];
__device__ float  g_val[TT];
__device__ __half g_qkv_hi[TT*QKV3];
__device__ __half g_qkv_lo[TT*QKV3];
__device__ __half g_hn_hi [TT*DD];
__device__ __half g_hn_lo [TT*DD];
__device__ __half g_ctx_hi[TT*DD];
__device__ __half g_ctx_lo[TT*DD];
__device__ __half g_ff_hi [TT*FFD];
__device__ __half g_ff_lo [TT*FFD];
// fp16 weights (converted once per launch)
__device__ __half w_qkv_h[LL*QKV3*DD];
__device__ __half w_o_h  [LL*DD*DD];
__device__ __half w_1_h  [LL*FFD*DD];
__device__ __half w_2_h  [LL*DD*FFD];
__device__ __half w_tok_h[(size_t)VV*DD];

// ---------------- helpers ----------------
__device__ __forceinline__ uint32_t smem_u32(const void* p){
    uint32_t a;
    asm("{ .reg .u64 t; cvta.to.shared.u64 t, %1; cvt.u32.u64 %0, t; }" : "=r"(a) : "l"(p));
    return a;
}
__device__ __forceinline__ uint32_t packhf(float x0, float x1){
    uint32_t r;
    asm("cvt.rn.f16x2.f32 %0, %1, %2;" : "=r"(r) : "f"(x1), "f"(x0));
    return r;
}
__device__ __forceinline__ float h2f_lo(uint32_t p){
    float f; asm("{ .reg .b16 h, dummy; mov.b32 {h, dummy}, %1; cvt.f32.f16 %0, h; }" : "=f"(f) : "r"(p));
    return f;
}
__device__ __forceinline__ float h2f_hi(uint32_t p){
    float f; asm("{ .reg .b16 h, dummy; mov.b32 {dummy, h}, %1; cvt.f32.f16 %0, h; }" : "=f"(f) : "r"(p));
    return f;
}
__device__ __forceinline__ float ex2f(float x){
    float y; asm("ex2.approx.f32 %0, %1;" : "=f"(y) : "f"(x)); return y;
}
__device__ __forceinline__ void ldsm4(uint32_t &r0, uint32_t &r1, uint32_t &r2, uint32_t &r3,
                                      uint32_t addr){
    asm volatile("ldmatrix.sync.aligned.m8n8.x4.shared.b16 {%0,%1,%2,%3}, [%4];"
        : "=r"(r0), "=r"(r1), "=r"(r2), "=r"(r3) : "r"(addr));
}
__device__ __forceinline__ void ldsm4t(uint32_t &r0, uint32_t &r1, uint32_t &r2, uint32_t &r3,
                                       uint32_t addr){
    asm volatile("ldmatrix.sync.aligned.m8n8.x4.trans.shared.b16 {%0,%1,%2,%3}, [%4];"
        : "=r"(r0), "=r"(r1), "=r"(r2), "=r"(r3) : "r"(addr));
}
__device__ __forceinline__ void mma16816h(float* d, const uint32_t* a, const uint32_t* b){
    asm volatile("mma.sync.aligned.m16n8k16.row.col.f32.f16.f16.f32 "
        "{%0,%1,%2,%3}, {%4,%5,%6,%7}, {%8,%9}, {%0,%1,%2,%3};"
        : "+f"(d[0]), "+f"(d[1]), "+f"(d[2]), "+f"(d[3])
        : "r"(a[0]), "r"(a[1]), "r"(a[2]), "r"(a[3]), "r"(b[0]), "r"(b[1]));
}
#define CP_ASYNC16(dst, src) \
    asm volatile("cp.async.cg.shared.global [%0], [%1], 16;" :: "r"(dst), "l"(src) : "memory")
#define CP_COMMIT() asm volatile("cp.async.commit_group;" ::: "memory")
#define CP_WAIT1()  asm volatile("cp.async.wait_group 1;" ::: "memory")
#define CP_WAIT0()  asm volatile("cp.async.wait_group 0;" ::: "memory")

// ---------------- reductions ----------------
__device__ __forceinline__ float warpSum(float v){
#pragma unroll
    for (int o = 16; o; o >>= 1) v += __shfl_xor_sync(0xffffffffu, v, o);
    return v;
}
__device__ __forceinline__ float warpMax(float v){
#pragma unroll
    for (int o = 16; o; o >>= 1) v = fmaxf(v, __shfl_xor_sync(0xffffffffu, v, o));
    return v;
}
__device__ float blockSum(float v){
    __shared__ float s[9];
    __syncthreads();
    int lane = threadIdx.x & 31, w = threadIdx.x >> 5;
    v = warpSum(v);
    if (lane == 0) s[w] = v;
    __syncthreads();
    if (w == 0){
        float x = (lane < (int)(blockDim.x >> 5)) ? s[lane] : 0.f;
        x = warpSum(x);
        if (lane == 0) s[8] = x;
    }
    __syncthreads();
    return s[8];
}
__device__ float blockMax(float v){
    __shared__ float s[9];
    __syncthreads();
    int lane = threadIdx.x & 31, w = threadIdx.x >> 5;
    v = warpMax(v);
    if (lane == 0) s[w] = v;
    __syncthreads();
    if (w == 0){
        float x = (lane < (int)(blockDim.x >> 5)) ? s[lane] : -INFINITY;
        x = warpMax(x);
        if (lane == 0) s[8] = x;
    }
    __syncthreads();
    return s[8];
}

// ---------------- fp32 -> fp16 weight conversion ----------------
__global__ void cvt_kernel(const float* __restrict__ src, __half* __restrict__ dst, int n){
    int i = (blockIdx.x * blockDim.x + threadIdx.x) << 2;
    int stride = (gridDim.x * blockDim.x) << 2;
    for (; i < n; i += stride){
        float4 f = *(const float4*)(src + i);
        *(uint2*)&dst[i] = make_uint2(packhf(f.x, f.y), packhf(f.z, f.w));
    }
}

// ---------------- embedding ----------------
__global__ void embed_kernel(const int* __restrict__ x,
                             const float* __restrict__ tok,
                             const float* __restrict__ pos){
    int t  = blockIdx.x;
    int id = x[t];
    const float* tr = tok + (size_t)id * DD;
    const float* pr = pos + (size_t)t  * DD;
    for (int d = threadIdx.x; d < DD; d += blockDim.x)
        g_h[t*DD + d] = tr[d] + pr[d];
}

// ---------------- layernorm -> fp16 hi/lo ----------------
__global__ void ln_kernel_hl(const float* __restrict__ in,
                             __half* __restrict__ ohi, __half* __restrict__ olo,
                             const float* __restrict__ g, const float* __restrict__ b){
    __shared__ float row[DD];
    int t = blockIdx.x;
    const float* r = in + (size_t)t * DD;
    float s = 0.f;
    for (int d = threadIdx.x; d < DD; d += blockDim.x){ float v = r[d]; row[d] = v; s += v; }
    s = blockSum(s);
    float mean = s * (1.f / DD);
    float q = 0.f;
    for (int d = threadIdx.x; d < DD; d += blockDim.x){ float v = row[d] - mean; q += v*v; }
    q = blockSum(q);
    float rstd = rsqrtf(q * (1.f / DD) + 1e-5f);
    for (int d = threadIdx.x; d < (DD >> 1); d += blockDim.x){
        int i0 = d << 1;
        float v0 = (row[i0]     - mean) * rstd * g[i0]     + b[i0];
        float v1 = (row[i0 + 1] - mean) * rstd * g[i0 + 1] + b[i0 + 1];
        uint32_t hh = packhf(v0, v1);
        uint32_t ll = packhf(v0 - h2f_lo(hh), v1 - h2f_hi(hh));
        *(uint32_t*)&ohi[t*DD + i0] = hh;
        *(uint32_t*)&olo[t*DD + i0] = ll;
    }
}

// ================== fp16 2-product GEMM, cp.async 3-stage, 2 CTAs/SM ==========
#define ROWB 80
#define STAGE_B 30720
#define G_SMEM (3*STAGE_B)

template<int BIASF, int GELUF, int RESF, int OUTHL>
__global__ __launch_bounds__(256, 2)
void gemm_mma(const __half* __restrict__ Ahi, const __half* __restrict__ Alo,
              const __half* __restrict__ Bw,
              const float* __restrict__ bias, const float* __restrict__ res,
              float* __restrict__ C, __half* __restrict__ Chi, __half* __restrict__ Clo,
              int M, int N, int K)
{
    extern __shared__ char smem[];
    const uint32_t sb = smem_u32(smem);
    const int tid = threadIdx.x, wid = tid >> 5, lane = tid & 31;
    const int m0 = blockIdx.x << 7, n0 = blockIdx.y << 7;
    const int wm = (wid >> 2) << 6;
    const int wn = (wid & 3) << 5;

    const int lrow = tid >> 2;
    const int k16  = tid & 3;
    const __half* aHp = Ahi + (size_t)(m0 + lrow) * K + (k16 << 3);
    const __half* aLp = Alo + (size_t)(m0 + lrow) * K + (k16 << 3);
    const __half* bP  = Bw  + (size_t)(n0 + lrow) * K + (k16 << 3);
    const uint32_t dOff = (uint32_t)(lrow * ROWB + (k16 << 4));

    float acc[4][4][4];
#pragma unroll
    for (int i = 0; i < 4; i++)
#pragma unroll
        for (int j = 0; j < 4; j++)
#pragma unroll
            for (int k = 0; k < 4; k++) acc[i][j][k] = 0.f;

    const int NC = K >> 5;

    auto issue = [&](int c, int s){
        uint32_t d = sb + s * STAGE_B + dOff;
        const __half* a0 = aHp + (size_t)c * 32;
        const __half* a1 = aLp + (size_t)c * 32;
        const __half* b0 = bP  + (size_t)c * 32;
        CP_ASYNC16(d,                a0);
        CP_ASYNC16(d + 5120,         a0 + (size_t)64 * K);
        CP_ASYNC16(d + 10240,        a1);
        CP_ASYNC16(d + 10240 + 5120, a1 + (size_t)64 * K);
        CP_ASYNC16(d + 20480,        b0);
        CP_ASYNC16(d + 20480 + 5120, b0 + (size_t)64 * K);
    };

    issue(0, 0); CP_COMMIT();
    if (NC > 1){ issue(1, 1); CP_COMMIT(); }

    const int g  = lane >> 3, lr = lane & 7;
    const int arow_off = ((g & 1) << 3) + lr;
    const int akb      = (g >> 1) << 4;
    const int brow_off = ((g >> 1) << 3) + lr;
    const int bkb      = (g & 1) << 4;

    int st_c = 0;
    for (int c = 0; c < NC; c++){
        CP_WAIT1();
        __syncthreads();

        int st_n2 = st_c + 2; if (st_n2 >= 3) st_n2 -= 3;
        if (c + 2 < NC) issue(c + 2, st_n2);
        CP_COMMIT();

        const uint32_t st = sb + st_c * STAGE_B;
#pragma unroll
        for (int h = 0; h < 2; h++){
            uint32_t Bh[4][2];
#pragma unroll
            for (int nt2 = 0; nt2 < 2; nt2++){
                uint32_t bd = st + 20480 + (uint32_t)((wn + (nt2 << 4) + brow_off) * ROWB + (h << 5) + bkb);
                uint32_t r0, r1, r2, r3;
                ldsm4(r0, r1, r2, r3, bd);
                Bh[2*nt2][0] = r0; Bh[2*nt2][1] = r1; Bh[2*nt2+1][0] = r2; Bh[2*nt2+1][1] = r3;
            }
#pragma unroll
            for (int mt = 0; mt < 4; mt++){
                uint32_t Ah[4], Al[4];
                uint32_t ad = st + (uint32_t)((wm + (mt << 4) + arow_off) * ROWB + (h << 5) + akb);
                ldsm4(Ah[0], Ah[1], Ah[2], Ah[3], ad);
                ldsm4(Al[0], Al[1], Al[2], Al[3], ad + 10240);
#pragma unroll
                for (int nt = 0; nt < 4; nt++){
                    mma16816h(acc[mt][nt], Ah, Bh[nt]);
                    mma16816h(acc[mt][nt], Al, Bh[nt]);
                }
            }
        }
        st_c = st_c + 1; if (st_c >= 3) st_c = 0;
    }

    const int qr = lane >> 2, qc = lane & 3;
#pragma unroll
    for (int mt = 0; mt < 4; mt++){
#pragma unroll
        for (int p = 0; p < 2; p++){
            int m = m0 + wm + (mt << 4) + qr + (p << 3);
            size_t rowbase = (size_t)m * N;
#pragma unroll
            for (int nt = 0; nt < 4; nt++){
                int n = n0 + wn + (nt << 3) + (qc << 1);
                float v0 = acc[mt][nt][2*p], v1 = acc[mt][nt][2*p + 1];
                if (BIASF){ v0 += bias[n]; v1 += bias[n + 1]; }
                if (GELUF){
                    v0 = 0.5f * v0 * (1.f + erff(v0 * 0.70710678118654752f));
                    v1 = 0.5f * v1 * (1.f + erff(v1 * 0.70710678118654752f));
                }
                if (RESF){
                    float2 rr = *(const float2*)&res[rowbase + n];
                    v0 += rr.x; v1 += rr.y;
                }
                if (OUTHL){
                    uint32_t hh = packhf(v0, v1);
                    uint32_t ll = packhf(v0 - h2f_lo(hh), v1 - h2f_hi(hh));
                    *(uint32_t*)&Chi[rowbase + n] = hh;
                    *(uint32_t*)&Clo[rowbase + n] = ll;
                } else {
                    *(float2*)&C[rowbase + n] = make_float2(v0, v1);
                }
            }
        }
    }
}

// ================== 64x128-tile variant (for N=768 GEMMs: more CTAs) ==========
// stage: Ahi[64x80]=5120, Alo=5120, B[128x80]=10240 -> 20480; 3 stages = 61440.
#define STAGE64_B 20480
#define G64_SMEM (3*STAGE64_B)

template<int BIASF, int RESF>
__global__ __launch_bounds__(256, 2)
void gemm_mma64(const __half* __restrict__ Ahi, const __half* __restrict__ Alo,
                const __half* __restrict__ Bw,
                const float* __restrict__ bias, const float* __restrict__ res,
                float* __restrict__ C, int M, int N, int K)
{
    extern __shared__ char smem[];
    const uint32_t sb = smem_u32(smem);
    const int tid = threadIdx.x, wid = tid >> 5, lane = tid & 31;
    const int m0 = blockIdx.x << 6, n0 = blockIdx.y << 7;
    const int wm = (wid >> 2) << 5;     // 0 or 32
    const int wn = (wid & 3) << 5;      // 0..96

    const int lrow = tid >> 2;          // 0..63
    const int k16  = tid & 3;
    const __half* aHp = Ahi + (size_t)(m0 + lrow) * K + (k16 << 3);
    const __half* aLp = Alo + (size_t)(m0 + lrow) * K + (k16 << 3);
    const __half* bP  = Bw  + (size_t)(n0 + lrow) * K + (k16 << 3);
    const uint32_t dOff = (uint32_t)(lrow * ROWB + (k16 << 4));

    float acc[2][4][4];
#pragma unroll
    for (int i = 0; i < 2; i++)
#pragma unroll
        for (int j = 0; j < 4; j++)
#pragma unroll
            for (int k = 0; k < 4; k++) acc[i][j][k] = 0.f;

    const int NC = K >> 5;

    auto issue = [&](int c, int s){
        uint32_t d = sb + s * STAGE64_B + dOff;
        const __half* a0 = aHp + (size_t)c * 32;
        const __half* a1 = aLp + (size_t)c * 32;
        const __half* b0 = bP  + (size_t)c * 32;
        CP_ASYNC16(d,                a0);
        CP_ASYNC16(d + 5120,         a1);
        CP_ASYNC16(d + 10240,        b0);
        CP_ASYNC16(d + 10240 + 5120, b0 + (size_t)64 * K);
    };

    issue(0, 0); CP_COMMIT();
    if (NC > 1){ issue(1, 1); CP_COMMIT(); }

    const int g  = lane >> 3, lr = lane & 7;
    const int arow_off = ((g & 1) << 3) + lr;
    const int akb      = (g >> 1) << 4;
    const int brow_off = ((g >> 1) << 3) + lr;
    const int bkb      = (g & 1) << 4;

    int st_c = 0;
    for (int c = 0; c < NC; c++){
        CP_WAIT1();
        __syncthreads();

        int st_n2 = st_c + 2; if (st_n2 >= 3) st_n2 -= 3;
        if (c + 2 < NC) issue(c + 2, st_n2);
        CP_COMMIT();

        const uint32_t st = sb + st_c * STAGE64_B;
#pragma unroll
        for (int h = 0; h < 2; h++){
            uint32_t Bh[4][2];
#pragma unroll
            for (int nt2 = 0; nt2 < 2; nt2++){
                uint32_t bd = st + 10240 + (uint32_t)((wn + (nt2 << 4) + brow_off) * ROWB + (h << 5) + bkb);
                uint32_t r0, r1, r2, r3;
                ldsm4(r0, r1, r2, r3, bd);
                Bh[2*nt2][0] = r0; Bh[2*nt2][1] = r1; Bh[2*nt2+1][0] = r2; Bh[2*nt2+1][1] = r3;
            }
#pragma unroll
            for (int mt = 0; mt < 2; mt++){
                uint32_t Ah[4], Al[4];
                uint32_t ad = st + (uint32_t)((wm + (mt << 4) + arow_off) * ROWB + (h << 5) + akb);
                ldsm4(Ah[0], Ah[1], Ah[2], Ah[3], ad);
                ldsm4(Al[0], Al[1], Al[2], Al[3], ad + 5120);
#pragma unroll
                for (int nt = 0; nt < 4; nt++){
                    mma16816h(acc[mt][nt], Ah, Bh[nt]);
                    mma16816h(acc[mt][nt], Al, Bh[nt]);
                }
            }
        }
        st_c = st_c + 1; if (st_c >= 3) st_c = 0;
    }

    const int qr = lane >> 2, qc = lane & 3;
#pragma unroll
    for (int mt = 0; mt < 2; mt++){
#pragma unroll
        for (int p = 0; p < 2; p++){
            int m = m0 + wm + (mt << 4) + qr + (p << 3);
            size_t rowbase = (size_t)m * N;
#pragma unroll
            for (int nt = 0; nt < 4; nt++){
                int n = n0 + wn + (nt << 3) + (qc << 1);
                float v0 = acc[mt][nt][2*p], v1 = acc[mt][nt][2*p + 1];
                if (BIASF){ v0 += bias[n]; v1 += bias[n + 1]; }
                if (RESF){
                    float2 rr = *(const float2*)&res[rowbase + n];
                    v0 += rr.x; v1 += rr.y;
                }
                *(float2*)&C[rowbase + n] = make_float2(v0, v1);
            }
        }
    }
}

// ================== tensor-core flash attention, fp16 tiles via cp.async ==========
#define AROWB 144
#define KOFF_LO  9216
#define VOFF_HI 18432
#define ATT_STAGE 27648
#define ATT_SMEM (2*ATT_STAGE)

__global__ __launch_bounds__(256)
void attn_tc(){
    extern __shared__ char smc[];
    const uint32_t sb = smem_u32(smc);
    const int tid = threadIdx.x, wid = tid >> 5, lane = tid & 31;
    const int qb = gridDim.x - 1 - (int)blockIdx.x;
    const int hh = blockIdx.y;
    const int q0 = qb << 7;
    const int wq = q0 + (wid << 4);

    const float SCL = 0.125f * 1.4426950408889634f;
    uint32_t qh[4][4], ql[4][4];
    {
        int r0 = wq + (lane >> 2);
        int c0 = (lane & 3) << 1;
#pragma unroll
        for (int kt = 0; kt < 4; kt++){
#pragma unroll
            for (int rr = 0; rr < 2; rr++){
                size_t idx = (size_t)(r0 + (rr << 3)) * QKV3 + hh * DHH + (kt << 4) + c0;
                uint32_t uh0 = *(const uint32_t*)&g_qkv_hi[idx];
                uint32_t ul0 = *(const uint32_t*)&g_qkv_lo[idx];
                uint32_t uh1 = *(const uint32_t*)&g_qkv_hi[idx + 8];
                uint32_t ul1 = *(const uint32_t*)&g_qkv_lo[idx + 8];
                float x0 = (h2f_lo(uh0) + h2f_lo(ul0)) * SCL;
                float x1 = (h2f_hi(uh0) + h2f_hi(ul0)) * SCL;
                float x2 = (h2f_lo(uh1) + h2f_lo(ul1)) * SCL;
                float x3 = (h2f_hi(uh1) + h2f_hi(ul1)) * SCL;
                uint32_t h0 = packhf(x0, x1), h1 = packhf(x2, x3);
                qh[kt][rr]     = h0;
                qh[kt][rr + 2] = h1;
                ql[kt][rr]     = packhf(x0 - h2f_lo(h0), x1 - h2f_hi(h0));
                ql[kt][rr + 2] = packhf(x2 - h2f_lo(h1), x3 - h2f_hi(h1));
            }
        }
    }

    float o[8][4];
#pragma unroll
    for (int i = 0; i < 8; i++){ o[i][0]=0.f; o[i][1]=0.f; o[i][2]=0.f; o[i][3]=0.f; }
    float mr0 = -INFINITY, mr1 = -INFINITY, lr0 = 0.f, lr1 = 0.f;

    const int jmax = (q0 >> 6) + 1;

    const int ldr = tid >> 2;
    const int k16 = tid & 3;
    const __half* kHp = g_qkv_hi + (size_t)ldr * QKV3 + DD     + hh * DHH + (k16 << 3);
    const __half* kLp = g_qkv_lo + (size_t)ldr * QKV3 + DD     + hh * DHH + (k16 << 3);
    const __half* vHp = g_qkv_hi + (size_t)ldr * QKV3 + 2 * DD + hh * DHH + (k16 << 3);
    const uint32_t dOff = (uint32_t)(ldr * AROWB + (k16 << 4));

    auto issue = [&](int j, int s){
        uint32_t d = sb + s * ATT_STAGE + dOff;
        size_t adv = (size_t)(j << 6) * QKV3;
        CP_ASYNC16(d,                 kHp + adv);
        CP_ASYNC16(d + 64,            kHp + adv + 32);
        CP_ASYNC16(d + KOFF_LO,       kLp + adv);
        CP_ASYNC16(d + KOFF_LO + 64,  kLp + adv + 32);
        CP_ASYNC16(d + VOFF_HI,       vHp + adv);
        CP_ASYNC16(d + VOFF_HI + 64,  vHp + adv + 32);
    };

    issue(0, 0); CP_COMMIT();

    const int g  = lane >> 3, lr8 = lane & 7;
    const int brow_off = ((g >> 1) << 3) + lr8;
    const int bkb      = (g & 1) << 4;

    for (int j = 0; j <= jmax; j++){
        if (j < jmax){ issue(j + 1, (j + 1) & 1); CP_COMMIT(); CP_WAIT1(); }
        else { CP_WAIT0(); }
        __syncthreads();

        const uint32_t st = sb + (j & 1) * ATT_STAGE;

        if ((j << 6) <= wq + 15){
            float s[8][4];
#pragma unroll
            for (int i = 0; i < 8; i++){ s[i][0]=0.f; s[i][1]=0.f; s[i][2]=0.f; s[i][3]=0.f; }
#pragma unroll
            for (int ks = 0; ks < 4; ks++){
                uint32_t kh[8][2], kl[8][2];
#pragma unroll
                for (int nt2 = 0; nt2 < 4; nt2++){
                    uint32_t ad = st + (uint32_t)(((nt2 << 4) + brow_off) * AROWB + (ks << 5) + bkb);
                    uint32_t r0, r1, r2, r3;
                    ldsm4(r0, r1, r2, r3, ad);
                    kh[2*nt2][0]=r0; kh[2*nt2][1]=r1; kh[2*nt2+1][0]=r2; kh[2*nt2+1][1]=r3;
                    ldsm4(r0, r1, r2, r3, ad + KOFF_LO);
                    kl[2*nt2][0]=r0; kl[2*nt2][1]=r1; kl[2*nt2+1][0]=r2; kl[2*nt2+1][1]=r3;
                }
#pragma unroll
                for (int nt = 0; nt < 8; nt++){
                    mma16816h(s[nt], qh[ks], kh[nt]);
                    mma16816h(s[nt], ql[ks], kh[nt]);
                    mma16816h(s[nt], qh[ks], kl[nt]);
                }
            }
            if ((j << 6) + 63 > wq){
                int qr0 = wq + (lane >> 2);
#pragma unroll
                for (int nt = 0; nt < 8; nt++){
                    int kp = (j << 6) + (nt << 3) + ((lane & 3) << 1);
#pragma unroll
                    for (int e = 0; e < 4; e++){
                        int kpos = kp + (e & 1);
                        int qrow = qr0 + ((e >> 1) << 3);
                        if (kpos > qrow) s[nt][e] = -INFINITY;
                    }
                }
            }
            float mx0 = -INFINITY, mx1 = -INFINITY;
#pragma unroll
            for (int nt = 0; nt < 8; nt++){
                mx0 = fmaxf(mx0, fmaxf(s[nt][0], s[nt][1]));
                mx1 = fmaxf(mx1, fmaxf(s[nt][2], s[nt][3]));
            }
            mx0 = fmaxf(mx0, __shfl_xor_sync(0xffffffffu, mx0, 1));
            mx0 = fmaxf(mx0, __shfl_xor_sync(0xffffffffu, mx0, 2));
            mx1 = fmaxf(mx1, __shfl_xor_sync(0xffffffffu, mx1, 1));
            mx1 = fmaxf(mx1, __shfl_xor_sync(0xffffffffu, mx1, 2));
            float mn0 = fmaxf(mr0, mx0), mn1 = fmaxf(mr1, mx1);
            float a0 = ex2f(mr0 - mn0), a1 = ex2f(mr1 - mn1);
            mr0 = mn0; mr1 = mn1;
            lr0 *= a0; lr1 *= a1;
#pragma unroll
            for (int nt = 0; nt < 8; nt++){
                o[nt][0] *= a0; o[nt][1] *= a0; o[nt][2] *= a1; o[nt][3] *= a1;
            }
            float sum0 = 0.f, sum1 = 0.f;
#pragma unroll
            for (int nt = 0; nt < 8; nt++){
                s[nt][0] = ex2f(s[nt][0] - mn0);
                s[nt][1] = ex2f(s[nt][1] - mn0);
                s[nt][2] = ex2f(s[nt][2] - mn1);
                s[nt][3] = ex2f(s[nt][3] - mn1);
                sum0 += s[nt][0] + s[nt][1];
                sum1 += s[nt][2] + s[nt][3];
            }
            lr0 += sum0; lr1 += sum1;
#pragma unroll
            for (int kt = 0; kt < 4; kt++){
                uint32_t ph[4], pl[4];
                {
                    float p00 = s[2*kt][0],   p01 = s[2*kt][1];
                    float p10 = s[2*kt][2],   p11 = s[2*kt][3];
                    float p20 = s[2*kt+1][0], p21 = s[2*kt+1][1];
                    float p30 = s[2*kt+1][2], p31 = s[2*kt+1][3];
                    ph[0] = packhf(p00, p01); ph[1] = packhf(p10, p11);
                    ph[2] = packhf(p20, p21); ph[3] = packhf(p30, p31);
                    pl[0] = packhf(p00 - h2f_lo(ph[0]), p01 - h2f_hi(ph[0]));
                    pl[1] = packhf(p10 - h2f_lo(ph[1]), p11 - h2f_hi(ph[1]));
                    pl[2] = packhf(p20 - h2f_lo(ph[2]), p21 - h2f_hi(ph[2]));
                    pl[3] = packhf(p30 - h2f_lo(ph[3]), p31 - h2f_hi(ph[3]));
                }
#pragma unroll
                for (int nt2 = 0; nt2 < 4; nt2++){
                    uint32_t va = st + VOFF_HI +
                        (uint32_t)(((kt << 4) + (lane & 15)) * AROWB + (((nt2 << 4) + ((lane >> 4) << 3)) << 1));
                    uint32_t r0, r1, r2, r3;
                    ldsm4t(r0, r1, r2, r3, va);
                    uint32_t bh0[2] = {r0, r1}, bh1[2] = {r2, r3};
                    mma16816h(o[2*nt2],   ph, bh0);
                    mma16816h(o[2*nt2],   pl, bh0);
                    mma16816h(o[2*nt2+1], ph, bh1);
                    mma16816h(o[2*nt2+1], pl, bh1);
                }
            }
        }
        __syncthreads();
    }

    lr0 += __shfl_xor_sync(0xffffffffu, lr0, 1);
    lr0 += __shfl_xor_sync(0xffffffffu, lr0, 2);
    lr1 += __shfl_xor_sync(0xffffffffu, lr1, 1);
    lr1 += __shfl_xor_sync(0xffffffffu, lr1, 2);
    float inv0 = 1.f / lr0, inv1 = 1.f / lr1;
    int qrow = wq + (lane >> 2);
    int cc = hh * DHH + ((lane & 3) << 1);
#pragma unroll
    for (int nt = 0; nt < 8; nt++){
        {
            float v0 = o[nt][0] * inv0, v1 = o[nt][1] * inv0;
            uint32_t hh0 = packhf(v0, v1);
            uint32_t ll0 = packhf(v0 - h2f_lo(hh0), v1 - h2f_hi(hh0));
            size_t idx = (size_t)qrow * DD + cc + (nt << 3);
            *(uint32_t*)&g_ctx_hi[idx] = hh0;
            *(uint32_t*)&g_ctx_lo[idx] = ll0;
        }
        {
            float v0 = o[nt][2] * inv1, v1 = o[nt][3] * inv1;
            uint32_t hh0 = packhf(v0, v1);
            uint32_t ll0 = packhf(v0 - h2f_lo(hh0), v1 - h2f_hi(hh0));
            size_t idx = (size_t)(qrow + 8) * DD + cc + (nt << 3);
            *(uint32_t*)&g_ctx_hi[idx] = hh0;
            *(uint32_t*)&g_ctx_lo[idx] = ll0;
        }
    }
}

// ---------------- loss ----------------
__global__ void row_lse_kernel(const float* __restrict__ logits, const int* __restrict__ tgt){
    int t = blockIdx.x;
    const float* row = logits + (size_t)t * VV;
    float mx = -INFINITY;
    for (int i = threadIdx.x; i < VV; i += blockDim.x) mx = fmaxf(mx, row[i]);
    mx = blockMax(mx);
    float s = 0.f;
    for (int i = threadIdx.x; i < VV; i += blockDim.x) s += expf(row[i] - mx);
    s = blockSum(s);
    if (threadIdx.x == 0){
        int tg = tgt[t];
        float lse = mx + logf(s);
        float nll = lse - row[tg];
        g_nll[t] = (tg != 0) ? nll : 0.f;
        g_val[t] = (tg != 0) ? 1.f : 0.f;
    }
}

__global__ void loss_reduce_kernel(float* __restrict__ out_loss){
    float a = 0.f, b = 0.f;
    for (int t = threadIdx.x; t < TT; t += blockDim.x){ a += g_nll[t]; b += g_val[t]; }
    a = blockSum(a);
    b = blockSum(b);
    if (threadIdx.x == 0) *out_loss = a / fmaxf(b, 1.f);
}

// ---------------- launch ----------------
extern "C" void kernel_launch(void* const* d_in, const int* in_sizes, int n_in,
                              void* d_out, int out_size){
    (void)in_sizes; (void)n_in;
    const int*   x     = (const int*)  d_in[0];
    const int*   tgt   = (const int*)  d_in[1];
    const float* tok   = (const float*)d_in[2];
    const float* pos   = (const float*)d_in[3];
    const float* Wqkv  = (const float*)d_in[4];
    const float* Wo    = (const float*)d_in[5];
    const float* ln1g  = (const float*)d_in[6];
    const float* ln1b  = (const float*)d_in[7];
    const float* ln2g  = (const float*)d_in[8];
    const float* ln2b  = (const float*)d_in[9];
    const float* W1    = (const float*)d_in[10];
    const float* b1    = (const float*)d_in[11];
    const float* W2    = (const float*)d_in[12];
    const float* b2    = (const float*)d_in[13];
    const float* lnfg  = (const float*)d_in[14];
    const float* lnfb  = (const float*)d_in[15];
    float* out = (float*)d_out;

    float *ph;
    __half *pqkv_hi, *pqkv_lo, *phn_hi, *phn_lo, *pctx_hi, *pctx_lo, *pff_hi, *pff_lo;
    __half *pwqkv, *pwo, *pw1, *pw2, *ptok;
    cudaGetSymbolAddress((void**)&ph,      g_h);
    cudaGetSymbolAddress((void**)&pqkv_hi, g_qkv_hi);
    cudaGetSymbolAddress((void**)&pqkv_lo, g_qkv_lo);
    cudaGetSymbolAddress((void**)&phn_hi,  g_hn_hi);
    cudaGetSymbolAddress((void**)&phn_lo,  g_hn_lo);
    cudaGetSymbolAddress((void**)&pctx_hi, g_ctx_hi);
    cudaGetSymbolAddress((void**)&pctx_lo, g_ctx_lo);
    cudaGetSymbolAddress((void**)&pff_hi,  g_ff_hi);
    cudaGetSymbolAddress((void**)&pff_lo,  g_ff_lo);
    cudaGetSymbolAddress((void**)&pwqkv,   w_qkv_h);
    cudaGetSymbolAddress((void**)&pwo,     w_o_h);
    cudaGetSymbolAddress((void**)&pw1,     w_1_h);
    cudaGetSymbolAddress((void**)&pw2,     w_2_h);
    cudaGetSymbolAddress((void**)&ptok,    w_tok_h);

    cudaFuncSetAttribute(gemm_mma<0,0,0,1>, cudaFuncAttributeMaxDynamicSharedMemorySize, G_SMEM);
    cudaFuncSetAttribute(gemm_mma<1,1,0,1>, cudaFuncAttributeMaxDynamicSharedMemorySize, G_SMEM);
    cudaFuncSetAttribute(gemm_mma<0,0,0,0>, cudaFuncAttributeMaxDynamicSharedMemorySize, G_SMEM);
    cudaFuncSetAttribute(gemm_mma64<0,1>,   cudaFuncAttributeMaxDynamicSharedMemorySize, G64_SMEM);
    cudaFuncSetAttribute(gemm_mma64<1,1>,   cudaFuncAttributeMaxDynamicSharedMemorySize, G64_SMEM);
    cudaFuncSetAttribute(attn_tc, cudaFuncAttributeMaxDynamicSharedMemorySize, ATT_SMEM);

    cvt_kernel<<<1024, 256>>>(Wqkv, pwqkv, LL*QKV3*DD);
    cvt_kernel<<<1024, 256>>>(Wo,   pwo,   LL*DD*DD);
    cvt_kernel<<<1024, 256>>>(W1,   pw1,   LL*FFD*DD);
    cvt_kernel<<<1024, 256>>>(W2,   pw2,   LL*DD*FFD);
    cvt_kernel<<<2048, 256>>>(tok,  ptok,  VV*DD);

    embed_kernel<<<TT, 256>>>(x, tok, pos);

    for (int l = 0; l < LL; l++){
        ln_kernel_hl<<<TT, 256>>>(ph, phn_hi, phn_lo, ln1g + l*DD, ln1b + l*DD);
        gemm_mma<0,0,0,1><<<dim3(TT/128, QKV3/128), 256, G_SMEM>>>(
            phn_hi, phn_lo, pwqkv + (size_t)l*QKV3*DD, nullptr, nullptr,
            nullptr, pqkv_hi, pqkv_lo, TT, QKV3, DD);
        attn_tc<<<dim3(TT/128, HH), 256, ATT_SMEM>>>();
        gemm_mma64<0,1><<<dim3(TT/64, DD/128), 256, G64_SMEM>>>(
            pctx_hi, pctx_lo, pwo + (size_t)l*DD*DD, nullptr, ph,
            ph, TT, DD, DD);
        ln_kernel_hl<<<TT, 256>>>(ph, phn_hi, phn_lo, ln2g + l*DD, ln2b + l*DD);
        gemm_mma<1,1,0,1><<<dim3(TT/128, FFD/128), 256, G_SMEM>>>(
            phn_hi, phn_lo, pw1 + (size_t)l*FFD*DD, b1 + (size_t)l*FFD, nullptr,
            nullptr, pff_hi, pff_lo, TT, FFD, DD);
        gemm_mma64<1,1><<<dim3(TT/64, DD/128), 256, G64_SMEM>>>(
            pff_hi, pff_lo, pw2 + (size_t)l*DD*FFD, b2 + (size_t)l*DD, ph,
            ph, TT, DD, FFD);
    }

    ln_kernel_hl<<<TT, 256>>>(ph, phn_hi, phn_lo, lnfg, lnfb);
    gemm_mma<0,0,0,0><<<dim3(TT/128, VV/128), 256, G_SMEM>>>(
        phn_hi, phn_lo, ptok, nullptr, nullptr,
        out, nullptr, nullptr, TT, VV, DD);

    row_lse_kernel<<<TT, 256>>>(out, tgt);
    if (out_size > TT * VV)
        loss_reduce_kernel<<<1, 256>>>(out + (size_t)TT * VV);
}

// round 13
// speedup vs baseline: 1.2213x; 1.0064x over previous
#include <cuda_runtime.h>
#include <cuda_bf16.h>
#include <cuda_fp16.h>
#include <math.h>
#include <stdint.h>

// Problem constants
#define TT   2048
#define DD   768
#define HH   12
#define DHH  64
#define LL   6
#define FFD  3072
#define VV   32000
#define QKV3 (3*DD)

// ---------------- scratch ----------------
__device__ float  g_h  [TT*DD];
__device__ float  g_nll[TT];
__device__ float  g_val[TT];
__device__ __half g_qkv_hi[TT*QKV3];
__device__ __half g_qkv_lo[TT*QKV3];
__device__ __half g_hn_hi [TT*DD];
__device__ __half g_hn_lo [TT*DD];
__device__ __half g_ctx_hi[TT*DD];
__device__ __half g_ctx_lo[TT*DD];
__device__ __half g_ff_hi [TT*FFD];
__device__ __half g_ff_lo [TT*FFD];
// fp16 weights (converted once per launch)
__device__ __half w_qkv_h[LL*QKV3*DD];
__device__ __half w_o_h  [LL*DD*DD];
__device__ __half w_1_h  [LL*FFD*DD];
__device__ __half w_2_h  [LL*DD*FFD];
__device__ __half w_tok_h[(size_t)VV*DD];

// ---------------- helpers ----------------
__device__ __forceinline__ uint32_t smem_u32(const void* p){
    uint32_t a;
    asm("{ .reg .u64 t; cvta.to.shared.u64 t, %1; cvt.u32.u64 %0, t; }" : "=r"(a) : "l"(p));
    return a;
}
__device__ __forceinline__ uint32_t packhf(float x0, float x1){
    uint32_t r;
    asm("cvt.rn.f16x2.f32 %0, %1, %2;" : "=r"(r) : "f"(x1), "f"(x0));
    return r;
}
__device__ __forceinline__ float h2f_lo(uint32_t p){
    float f; asm("{ .reg .b16 h, dummy; mov.b32 {h, dummy}, %1; cvt.f32.f16 %0, h; }" : "=f"(f) : "r"(p));
    return f;
}
__device__ __forceinline__ float h2f_hi(uint32_t p){
    float f; asm("{ .reg .b16 h, dummy; mov.b32 {dummy, h}, %1; cvt.f32.f16 %0, h; }" : "=f"(f) : "r"(p));
    return f;
}
__device__ __forceinline__ float ex2f(float x){
    float y; asm("ex2.approx.f32 %0, %1;" : "=f"(y) : "f"(x)); return y;
}
__device__ __forceinline__ void ldsm4(uint32_t &r0, uint32_t &r1, uint32_t &r2, uint32_t &r3,
                                      uint32_t addr){
    asm volatile("ldmatrix.sync.aligned.m8n8.x4.shared.b16 {%0,%1,%2,%3}, [%4];"
        : "=r"(r0), "=r"(r1), "=r"(r2), "=r"(r3) : "r"(addr));
}
__device__ __forceinline__ void ldsm4t(uint32_t &r0, uint32_t &r1, uint32_t &r2, uint32_t &r3,
                                       uint32_t addr){
    asm volatile("ldmatrix.sync.aligned.m8n8.x4.trans.shared.b16 {%0,%1,%2,%3}, [%4];"
        : "=r"(r0), "=r"(r1), "=r"(r2), "=r"(r3) : "r"(addr));
}
__device__ __forceinline__ void mma16816h(float* d, const uint32_t* a, const uint32_t* b){
    asm volatile("mma.sync.aligned.m16n8k16.row.col.f32.f16.f16.f32 "
        "{%0,%1,%2,%3}, {%4,%5,%6,%7}, {%8,%9}, {%0,%1,%2,%3};"
        : "+f"(d[0]), "+f"(d[1]), "+f"(d[2]), "+f"(d[3])
        : "r"(a[0]), "r"(a[1]), "r"(a[2]), "r"(a[3]), "r"(b[0]), "r"(b[1]));
}
#define CP_ASYNC16(dst, src) \
    asm volatile("cp.async.cg.shared.global [%0], [%1], 16;" :: "r"(dst), "l"(src) : "memory")
#define CP_COMMIT() asm volatile("cp.async.commit_group;" ::: "memory")
#define CP_WAIT1()  asm volatile("cp.async.wait_group 1;" ::: "memory")
#define CP_WAIT0()  asm volatile("cp.async.wait_group 0;" ::: "memory")

// ---------------- reductions ----------------
__device__ __forceinline__ float warpSum(float v){
#pragma unroll
    for (int o = 16; o; o >>= 1) v += __shfl_xor_sync(0xffffffffu, v, o);
    return v;
}
__device__ float blockSum(float v){
    __shared__ float s[9];
    __syncthreads();
    int lane = threadIdx.x & 31, w = threadIdx.x >> 5;
    v = warpSum(v);
    if (lane == 0) s[w] = v;
    __syncthreads();
    if (w == 0){
        float x = (lane < (int)(blockDim.x >> 5)) ? s[lane] : 0.f;
        x = warpSum(x);
        if (lane == 0) s[8] = x;
    }
    __syncthreads();
    return s[8];
}

// ---------------- fp32 -> fp16 weight conversion ----------------
__global__ void cvt_kernel(const float* __restrict__ src, __half* __restrict__ dst, int n){
    int i = (blockIdx.x * blockDim.x + threadIdx.x) << 2;
    int stride = (gridDim.x * blockDim.x) << 2;
    for (; i < n; i += stride){
        float4 f = *(const float4*)(src + i);
        *(uint2*)&dst[i] = make_uint2(packhf(f.x, f.y), packhf(f.z, f.w));
    }
}

// ---------------- embedding ----------------
__global__ void embed_kernel(const int* __restrict__ x,
                             const float* __restrict__ tok,
                             const float* __restrict__ pos){
    int t  = blockIdx.x;
    int id = x[t];
    const float* tr = tok + (size_t)id * DD;
    const float* pr = pos + (size_t)t  * DD;
    for (int d = threadIdx.x; d < DD; d += blockDim.x)
        g_h[t*DD + d] = tr[d] + pr[d];
}

// ---------------- layernorm -> fp16 hi/lo ----------------
__global__ void ln_kernel_hl(const float* __restrict__ in,
                             __half* __restrict__ ohi, __half* __restrict__ olo,
                             const float* __restrict__ g, const float* __restrict__ b){
    __shared__ float row[DD];
    int t = blockIdx.x;
    const float* r = in + (size_t)t * DD;
    float s = 0.f;
    for (int d = threadIdx.x; d < DD; d += blockDim.x){ float v = r[d]; row[d] = v; s += v; }
    s = blockSum(s);
    float mean = s * (1.f / DD);
    float q = 0.f;
    for (int d = threadIdx.x; d < DD; d += blockDim.x){ float v = row[d] - mean; q += v*v; }
    q = blockSum(q);
    float rstd = rsqrtf(q * (1.f / DD) + 1e-5f);
    for (int d = threadIdx.x; d < (DD >> 1); d += blockDim.x){
        int i0 = d << 1;
        float v0 = (row[i0]     - mean) * rstd * g[i0]     + b[i0];
        float v1 = (row[i0 + 1] - mean) * rstd * g[i0 + 1] + b[i0 + 1];
        uint32_t hh = packhf(v0, v1);
        uint32_t ll = packhf(v0 - h2f_lo(hh), v1 - h2f_hi(hh));
        *(uint32_t*)&ohi[t*DD + i0] = hh;
        *(uint32_t*)&olo[t*DD + i0] = ll;
    }
}

// ================== fp16 2-product GEMM, cp.async 3-stage, 2 CTAs/SM ==========
#define ROWB 80
#define STAGE_B 30720
#define G_SMEM (3*STAGE_B)

template<int BIASF, int GELUF, int RESF, int OUTHL>
__global__ __launch_bounds__(256, 2)
void gemm_mma(const __half* __restrict__ Ahi, const __half* __restrict__ Alo,
              const __half* __restrict__ Bw,
              const float* __restrict__ bias, const float* __restrict__ res,
              float* __restrict__ C, __half* __restrict__ Chi, __half* __restrict__ Clo,
              int M, int N, int K)
{
    extern __shared__ char smem[];
    const uint32_t sb = smem_u32(smem);
    const int tid = threadIdx.x, wid = tid >> 5, lane = tid & 31;
    const int m0 = blockIdx.x << 7, n0 = blockIdx.y << 7;
    const int wm = (wid >> 2) << 6;
    const int wn = (wid & 3) << 5;

    const int lrow = tid >> 2;
    const int k16  = tid & 3;
    const __half* aHp = Ahi + (size_t)(m0 + lrow) * K + (k16 << 3);
    const __half* aLp = Alo + (size_t)(m0 + lrow) * K + (k16 << 3);
    const __half* bP  = Bw  + (size_t)(n0 + lrow) * K + (k16 << 3);
    const uint32_t dOff = (uint32_t)(lrow * ROWB + (k16 << 4));

    float acc[4][4][4];
#pragma unroll
    for (int i = 0; i < 4; i++)
#pragma unroll
        for (int j = 0; j < 4; j++)
#pragma unroll
            for (int k = 0; k < 4; k++) acc[i][j][k] = 0.f;

    const int NC = K >> 5;

    auto issue = [&](int c, int s){
        uint32_t d = sb + s * STAGE_B + dOff;
        const __half* a0 = aHp + (size_t)c * 32;
        const __half* a1 = aLp + (size_t)c * 32;
        const __half* b0 = bP  + (size_t)c * 32;
        CP_ASYNC16(d,                a0);
        CP_ASYNC16(d + 5120,         a0 + (size_t)64 * K);
        CP_ASYNC16(d + 10240,        a1);
        CP_ASYNC16(d + 10240 + 5120, a1 + (size_t)64 * K);
        CP_ASYNC16(d + 20480,        b0);
        CP_ASYNC16(d + 20480 + 5120, b0 + (size_t)64 * K);
    };

    issue(0, 0); CP_COMMIT();
    if (NC > 1){ issue(1, 1); CP_COMMIT(); }

    const int g  = lane >> 3, lr = lane & 7;
    const int arow_off = ((g & 1) << 3) + lr;
    const int akb      = (g >> 1) << 4;
    const int brow_off = ((g >> 1) << 3) + lr;
    const int bkb      = (g & 1) << 4;

    int st_c = 0;
    for (int c = 0; c < NC; c++){
        CP_WAIT1();
        __syncthreads();

        int st_n2 = st_c + 2; if (st_n2 >= 3) st_n2 -= 3;
        if (c + 2 < NC) issue(c + 2, st_n2);
        CP_COMMIT();

        const uint32_t st = sb + st_c * STAGE_B;
#pragma unroll
        for (int h = 0; h < 2; h++){
            uint32_t Bh[4][2];
#pragma unroll
            for (int nt2 = 0; nt2 < 2; nt2++){
                uint32_t bd = st + 20480 + (uint32_t)((wn + (nt2 << 4) + brow_off) * ROWB + (h << 5) + bkb);
                uint32_t r0, r1, r2, r3;
                ldsm4(r0, r1, r2, r3, bd);
                Bh[2*nt2][0] = r0; Bh[2*nt2][1] = r1; Bh[2*nt2+1][0] = r2; Bh[2*nt2+1][1] = r3;
            }
#pragma unroll
            for (int mt = 0; mt < 4; mt++){
                uint32_t Ah[4], Al[4];
                uint32_t ad = st + (uint32_t)((wm + (mt << 4) + arow_off) * ROWB + (h << 5) + akb);
                ldsm4(Ah[0], Ah[1], Ah[2], Ah[3], ad);
                ldsm4(Al[0], Al[1], Al[2], Al[3], ad + 10240);
#pragma unroll
                for (int nt = 0; nt < 4; nt++){
                    mma16816h(acc[mt][nt], Ah, Bh[nt]);
                    mma16816h(acc[mt][nt], Al, Bh[nt]);
                }
            }
        }
        st_c = st_c + 1; if (st_c >= 3) st_c = 0;
    }

    const int qr = lane >> 2, qc = lane & 3;
#pragma unroll
    for (int mt = 0; mt < 4; mt++){
#pragma unroll
        for (int p = 0; p < 2; p++){
            int m = m0 + wm + (mt << 4) + qr + (p << 3);
            size_t rowbase = (size_t)m * N;
#pragma unroll
            for (int nt = 0; nt < 4; nt++){
                int n = n0 + wn + (nt << 3) + (qc << 1);
                float v0 = acc[mt][nt][2*p], v1 = acc[mt][nt][2*p + 1];
                if (BIASF){ v0 += bias[n]; v1 += bias[n + 1]; }
                if (GELUF){
                    v0 = 0.5f * v0 * (1.f + erff(v0 * 0.70710678118654752f));
                    v1 = 0.5f * v1 * (1.f + erff(v1 * 0.70710678118654752f));
                }
                if (RESF){
                    float2 rr = *(const float2*)&res[rowbase + n];
                    v0 += rr.x; v1 += rr.y;
                }
                if (OUTHL){
                    uint32_t hh = packhf(v0, v1);
                    uint32_t ll = packhf(v0 - h2f_lo(hh), v1 - h2f_hi(hh));
                    *(uint32_t*)&Chi[rowbase + n] = hh;
                    *(uint32_t*)&Clo[rowbase + n] = ll;
                } else {
                    *(float2*)&C[rowbase + n] = make_float2(v0, v1);
                }
            }
        }
    }
}

// ================== 64x128-tile variant (for N=768 GEMMs) ==========
#define STAGE64_B 20480
#define G64_SMEM (3*STAGE64_B)

template<int BIASF, int RESF>
__global__ __launch_bounds__(256, 2)
void gemm_mma64(const __half* __restrict__ Ahi, const __half* __restrict__ Alo,
                const __half* __restrict__ Bw,
                const float* __restrict__ bias, const float* __restrict__ res,
                float* __restrict__ C, int M, int N, int K)
{
    extern __shared__ char smem[];
    const uint32_t sb = smem_u32(smem);
    const int tid = threadIdx.x, wid = tid >> 5, lane = tid & 31;
    const int m0 = blockIdx.x << 6, n0 = blockIdx.y << 7;
    const int wm = (wid >> 2) << 5;
    const int wn = (wid & 3) << 5;

    const int lrow = tid >> 2;
    const int k16  = tid & 3;
    const __half* aHp = Ahi + (size_t)(m0 + lrow) * K + (k16 << 3);
    const __half* aLp = Alo + (size_t)(m0 + lrow) * K + (k16 << 3);
    const __half* bP  = Bw  + (size_t)(n0 + lrow) * K + (k16 << 3);
    const uint32_t dOff = (uint32_t)(lrow * ROWB + (k16 << 4));

    float acc[2][4][4];
#pragma unroll
    for (int i = 0; i < 2; i++)
#pragma unroll
        for (int j = 0; j < 4; j++)
#pragma unroll
            for (int k = 0; k < 4; k++) acc[i][j][k] = 0.f;

    const int NC = K >> 5;

    auto issue = [&](int c, int s){
        uint32_t d = sb + s * STAGE64_B + dOff;
        const __half* a0 = aHp + (size_t)c * 32;
        const __half* a1 = aLp + (size_t)c * 32;
        const __half* b0 = bP  + (size_t)c * 32;
        CP_ASYNC16(d,                a0);
        CP_ASYNC16(d + 5120,         a1);
        CP_ASYNC16(d + 10240,        b0);
        CP_ASYNC16(d + 10240 + 5120, b0 + (size_t)64 * K);
    };

    issue(0, 0); CP_COMMIT();
    if (NC > 1){ issue(1, 1); CP_COMMIT(); }

    const int g  = lane >> 3, lr = lane & 7;
    const int arow_off = ((g & 1) << 3) + lr;
    const int akb      = (g >> 1) << 4;
    const int brow_off = ((g >> 1) << 3) + lr;
    const int bkb      = (g & 1) << 4;

    int st_c = 0;
    for (int c = 0; c < NC; c++){
        CP_WAIT1();
        __syncthreads();

        int st_n2 = st_c + 2; if (st_n2 >= 3) st_n2 -= 3;
        if (c + 2 < NC) issue(c + 2, st_n2);
        CP_COMMIT();

        const uint32_t st = sb + st_c * STAGE64_B;
#pragma unroll
        for (int h = 0; h < 2; h++){
            uint32_t Bh[4][2];
#pragma unroll
            for (int nt2 = 0; nt2 < 2; nt2++){
                uint32_t bd = st + 10240 + (uint32_t)((wn + (nt2 << 4) + brow_off) * ROWB + (h << 5) + bkb);
                uint32_t r0, r1, r2, r3;
                ldsm4(r0, r1, r2, r3, bd);
                Bh[2*nt2][0] = r0; Bh[2*nt2][1] = r1; Bh[2*nt2+1][0] = r2; Bh[2*nt2+1][1] = r3;
            }
#pragma unroll
            for (int mt = 0; mt < 2; mt++){
                uint32_t Ah[4], Al[4];
                uint32_t ad = st + (uint32_t)((wm + (mt << 4) + arow_off) * ROWB + (h << 5) + akb);
                ldsm4(Ah[0], Ah[1], Ah[2], Ah[3], ad);
                ldsm4(Al[0], Al[1], Al[2], Al[3], ad + 5120);
#pragma unroll
                for (int nt = 0; nt < 4; nt++){
                    mma16816h(acc[mt][nt], Ah, Bh[nt]);
                    mma16816h(acc[mt][nt], Al, Bh[nt]);
                }
            }
        }
        st_c = st_c + 1; if (st_c >= 3) st_c = 0;
    }

    const int qr = lane >> 2, qc = lane & 3;
#pragma unroll
    for (int mt = 0; mt < 2; mt++){
#pragma unroll
        for (int p = 0; p < 2; p++){
            int m = m0 + wm + (mt << 4) + qr + (p << 3);
            size_t rowbase = (size_t)m * N;
#pragma unroll
            for (int nt = 0; nt < 4; nt++){
                int n = n0 + wn + (nt << 3) + (qc << 1);
                float v0 = acc[mt][nt][2*p], v1 = acc[mt][nt][2*p + 1];
                if (BIASF){ v0 += bias[n]; v1 += bias[n + 1]; }
                if (RESF){
                    float2 rr = *(const float2*)&res[rowbase + n];
                    v0 += rr.x; v1 += rr.y;
                }
                *(float2*)&C[rowbase + n] = make_float2(v0, v1);
            }
        }
    }
}

// ================== flash attention: 64-q blocks, 128 threads, 2 CTAs/SM ==========
#define AROWB 144
#define KOFF_LO  9216
#define VOFF_HI 18432
#define ATT_STAGE 27648
#define ATT_SMEM (2*ATT_STAGE)

__global__ __launch_bounds__(128, 2)
void attn_tc(){
    extern __shared__ char smc[];
    const uint32_t sb = smem_u32(smc);
    const int tid = threadIdx.x, wid = tid >> 5, lane = tid & 31;
    const int qb = gridDim.x - 1 - (int)blockIdx.x;    // 0..31, heavy first
    const int hh = blockIdx.y;
    const int q0 = qb << 6;
    const int wq = q0 + (wid << 4);                     // 4 warps x 16 rows

    // ---- Q fragments ----
    const float SCL = 0.125f * 1.4426950408889634f;
    uint32_t qh[4][4], ql[4][4];
    {
        int r0 = wq + (lane >> 2);
        int c0 = (lane & 3) << 1;
#pragma unroll
        for (int kt = 0; kt < 4; kt++){
#pragma unroll
            for (int rr = 0; rr < 2; rr++){
                size_t idx = (size_t)(r0 + (rr << 3)) * QKV3 + hh * DHH + (kt << 4) + c0;
                uint32_t uh0 = *(const uint32_t*)&g_qkv_hi[idx];
                uint32_t ul0 = *(const uint32_t*)&g_qkv_lo[idx];
                uint32_t uh1 = *(const uint32_t*)&g_qkv_hi[idx + 8];
                uint32_t ul1 = *(const uint32_t*)&g_qkv_lo[idx + 8];
                float x0 = (h2f_lo(uh0) + h2f_lo(ul0)) * SCL;
                float x1 = (h2f_hi(uh0) + h2f_hi(ul0)) * SCL;
                float x2 = (h2f_lo(uh1) + h2f_lo(ul1)) * SCL;
                float x3 = (h2f_hi(uh1) + h2f_hi(ul1)) * SCL;
                uint32_t h0 = packhf(x0, x1), h1 = packhf(x2, x3);
                qh[kt][rr]     = h0;
                qh[kt][rr + 2] = h1;
                ql[kt][rr]     = packhf(x0 - h2f_lo(h0), x1 - h2f_hi(h0));
                ql[kt][rr + 2] = packhf(x2 - h2f_lo(h1), x3 - h2f_hi(h1));
            }
        }
    }

    float o[8][4];
#pragma unroll
    for (int i = 0; i < 8; i++){ o[i][0]=0.f; o[i][1]=0.f; o[i][2]=0.f; o[i][3]=0.f; }
    float mr0 = -INFINITY, mr1 = -INFINITY, lr0 = 0.f, lr1 = 0.f;

    const int jmax = qb;     // diagonal tile index (64-key tiles)

    // cp.async loader: 128 threads, row = tid>>1 (0..63), half-row = tid&1 (4 chunks)
    const int ldr = tid >> 1;
    const int hc  = (tid & 1) << 2;    // chunk offset 0 or 4 (16B units)
    const __half* kHp = g_qkv_hi + (size_t)ldr * QKV3 + DD     + hh * DHH + (hc << 3);
    const __half* kLp = g_qkv_lo + (size_t)ldr * QKV3 + DD     + hh * DHH + (hc << 3);
    const __half* vHp = g_qkv_hi + (size_t)ldr * QKV3 + 2 * DD + hh * DHH + (hc << 3);
    const uint32_t dOff = (uint32_t)(ldr * AROWB + (hc << 4));

    auto issue = [&](int j, int s){
        uint32_t d = sb + s * ATT_STAGE + dOff;
        size_t adv = (size_t)(j << 6) * QKV3;
#pragma unroll
        for (int c = 0; c < 4; c++){
            CP_ASYNC16(d + (c << 4),            kHp + adv + (c << 3));
            CP_ASYNC16(d + KOFF_LO + (c << 4),  kLp + adv + (c << 3));
            CP_ASYNC16(d + VOFF_HI + (c << 4),  vHp + adv + (c << 3));
        }
    };

    issue(0, 0); CP_COMMIT();

    const int g  = lane >> 3, lr8 = lane & 7;
    const int brow_off = ((g >> 1) << 3) + lr8;
    const int bkb      = (g & 1) << 4;

    for (int j = 0; j <= jmax; j++){
        if (j < jmax){ issue(j + 1, (j + 1) & 1); CP_COMMIT(); CP_WAIT1(); }
        else { CP_WAIT0(); }
        __syncthreads();

        const uint32_t st = sb + (j & 1) * ATT_STAGE;

        {
            // ---- S = Q K^T (3-product) ----
            float s[8][4];
#pragma unroll
            for (int i = 0; i < 8; i++){ s[i][0]=0.f; s[i][1]=0.f; s[i][2]=0.f; s[i][3]=0.f; }
#pragma unroll
            for (int ks = 0; ks < 4; ks++){
                uint32_t kh[8][2], kl[8][2];
#pragma unroll
                for (int nt2 = 0; nt2 < 4; nt2++){
                    uint32_t ad = st + (uint32_t)(((nt2 << 4) + brow_off) * AROWB + (ks << 5) + bkb);
                    uint32_t r0, r1, r2, r3;
                    ldsm4(r0, r1, r2, r3, ad);
                    kh[2*nt2][0]=r0; kh[2*nt2][1]=r1; kh[2*nt2+1][0]=r2; kh[2*nt2+1][1]=r3;
                    ldsm4(r0, r1, r2, r3, ad + KOFF_LO);
                    kl[2*nt2][0]=r0; kl[2*nt2][1]=r1; kl[2*nt2+1][0]=r2; kl[2*nt2+1][1]=r3;
                }
#pragma unroll
                for (int nt = 0; nt < 8; nt++){
                    mma16816h(s[nt], qh[ks], kh[nt]);
                    mma16816h(s[nt], ql[ks], kh[nt]);
                    mma16816h(s[nt], qh[ks], kl[nt]);
                }
            }
            // ---- causal mask (diagonal tile only) ----
            if (j == jmax){
                int qr0 = wq + (lane >> 2);
#pragma unroll
                for (int nt = 0; nt < 8; nt++){
                    int kp = (j << 6) + (nt << 3) + ((lane & 3) << 1);
#pragma unroll
                    for (int e = 0; e < 4; e++){
                        int kpos = kp + (e & 1);
                        int qrow = qr0 + ((e >> 1) << 3);
                        if (kpos > qrow) s[nt][e] = -INFINITY;
                    }
                }
            }
            // ---- online softmax ----
            float mx0 = -INFINITY, mx1 = -INFINITY;
#pragma unroll
            for (int nt = 0; nt < 8; nt++){
                mx0 = fmaxf(mx0, fmaxf(s[nt][0], s[nt][1]));
                mx1 = fmaxf(mx1, fmaxf(s[nt][2], s[nt][3]));
            }
            mx0 = fmaxf(mx0, __shfl_xor_sync(0xffffffffu, mx0, 1));
            mx0 = fmaxf(mx0, __shfl_xor_sync(0xffffffffu, mx0, 2));
            mx1 = fmaxf(mx1, __shfl_xor_sync(0xffffffffu, mx1, 1));
            mx1 = fmaxf(mx1, __shfl_xor_sync(0xffffffffu, mx1, 2));
            float mn0 = fmaxf(mr0, mx0), mn1 = fmaxf(mr1, mx1);
            float a0 = ex2f(mr0 - mn0), a1 = ex2f(mr1 - mn1);
            mr0 = mn0; mr1 = mn1;
            lr0 *= a0; lr1 *= a1;
#pragma unroll
            for (int nt = 0; nt < 8; nt++){
                o[nt][0] *= a0; o[nt][1] *= a0; o[nt][2] *= a1; o[nt][3] *= a1;
            }
            float sum0 = 0.f, sum1 = 0.f;
#pragma unroll
            for (int nt = 0; nt < 8; nt++){
                s[nt][0] = ex2f(s[nt][0] - mn0);
                s[nt][1] = ex2f(s[nt][1] - mn0);
                s[nt][2] = ex2f(s[nt][2] - mn1);
                s[nt][3] = ex2f(s[nt][3] - mn1);
                sum0 += s[nt][0] + s[nt][1];
                sum1 += s[nt][2] + s[nt][3];
            }
            lr0 += sum0; lr1 += sum1;
            // ---- O += P V (2-product) ----
#pragma unroll
            for (int kt = 0; kt < 4; kt++){
                uint32_t ph[4], pl[4];
                {
                    float p00 = s[2*kt][0],   p01 = s[2*kt][1];
                    float p10 = s[2*kt][2],   p11 = s[2*kt][3];
                    float p20 = s[2*kt+1][0], p21 = s[2*kt+1][1];
                    float p30 = s[2*kt+1][2], p31 = s[2*kt+1][3];
                    ph[0] = packhf(p00, p01); ph[1] = packhf(p10, p11);
                    ph[2] = packhf(p20, p21); ph[3] = packhf(p30, p31);
                    pl[0] = packhf(p00 - h2f_lo(ph[0]), p01 - h2f_hi(ph[0]));
                    pl[1] = packhf(p10 - h2f_lo(ph[1]), p11 - h2f_hi(ph[1]));
                    pl[2] = packhf(p20 - h2f_lo(ph[2]), p21 - h2f_hi(ph[2]));
                    pl[3] = packhf(p30 - h2f_lo(ph[3]), p31 - h2f_hi(ph[3]));
                }
#pragma unroll
                for (int nt2 = 0; nt2 < 4; nt2++){
                    uint32_t va = st + VOFF_HI +
                        (uint32_t)(((kt << 4) + (lane & 15)) * AROWB + (((nt2 << 4) + ((lane >> 4) << 3)) << 1));
                    uint32_t r0, r1, r2, r3;
                    ldsm4t(r0, r1, r2, r3, va);
                    uint32_t bh0[2] = {r0, r1}, bh1[2] = {r2, r3};
                    mma16816h(o[2*nt2],   ph, bh0);
                    mma16816h(o[2*nt2],   pl, bh0);
                    mma16816h(o[2*nt2+1], ph, bh1);
                    mma16816h(o[2*nt2+1], pl, bh1);
                }
            }
        }
        __syncthreads();
    }

    // ---- finalize -> fp16 hi/lo ctx ----
    lr0 += __shfl_xor_sync(0xffffffffu, lr0, 1);
    lr0 += __shfl_xor_sync(0xffffffffu, lr0, 2);
    lr1 += __shfl_xor_sync(0xffffffffu, lr1, 1);
    lr1 += __shfl_xor_sync(0xffffffffu, lr1, 2);
    float inv0 = 1.f / lr0, inv1 = 1.f / lr1;
    int qrow = wq + (lane >> 2);
    int cc = hh * DHH + ((lane & 3) << 1);
#pragma unroll
    for (int nt = 0; nt < 8; nt++){
        {
            float v0 = o[nt][0] * inv0, v1 = o[nt][1] * inv0;
            uint32_t hh0 = packhf(v0, v1);
            uint32_t ll0 = packhf(v0 - h2f_lo(hh0), v1 - h2f_hi(hh0));
            size_t idx = (size_t)qrow * DD + cc + (nt << 3);
            *(uint32_t*)&g_ctx_hi[idx] = hh0;
            *(uint32_t*)&g_ctx_lo[idx] = ll0;
        }
        {
            float v0 = o[nt][2] * inv1, v1 = o[nt][3] * inv1;
            uint32_t hh0 = packhf(v0, v1);
            uint32_t ll0 = packhf(v0 - h2f_lo(hh0), v1 - h2f_hi(hh0));
            size_t idx = (size_t)(qrow + 8) * DD + cc + (nt << 3);
            *(uint32_t*)&g_ctx_hi[idx] = hh0;
            *(uint32_t*)&g_ctx_lo[idx] = ll0;
        }
    }
}

// ---------------- loss: one-pass online LSE ----------------
__global__ void row_lse_kernel(const float* __restrict__ logits, const int* __restrict__ tgt){
    __shared__ float sm_m[8], sm_s[8], sm_r[2];
    int t = blockIdx.x;
    const float* row = logits + (size_t)t * VV;
    int lane = threadIdx.x & 31, w = threadIdx.x >> 5;

    float m = -INFINITY, s = 0.f;
    for (int i = threadIdx.x; i < VV; i += blockDim.x){
        float v = row[i];
        if (v <= m){
            s += expf(v - m);
        } else {
            s = s * expf(m - v) + 1.f;
            m = v;
        }
    }
    // warp merge
#pragma unroll
    for (int oo = 16; oo; oo >>= 1){
        float om = __shfl_xor_sync(0xffffffffu, m, oo);
        float os = __shfl_xor_sync(0xffffffffu, s, oo);
        float nm = fmaxf(m, om);
        s = s * expf(m - nm) + os * expf(om - nm);
        m = nm;
    }
    if (lane == 0){ sm_m[w] = m; sm_s[w] = s; }
    __syncthreads();
    if (w == 0){
        float mm = (lane < (int)(blockDim.x >> 5)) ? sm_m[lane] : -INFINITY;
        float ss = (lane < (int)(blockDim.x >> 5)) ? sm_s[lane] : 0.f;
#pragma unroll
        for (int oo = 4; oo; oo >>= 1){
            float om = __shfl_xor_sync(0xffffffffu, mm, oo);
            float os = __shfl_xor_sync(0xffffffffu, ss, oo);
            float nm = fmaxf(mm, om);
            ss = ss * expf(mm - nm) + os * expf(om - nm);
            mm = nm;
        }
        if (lane == 0){ sm_r[0] = mm; sm_r[1] = ss; }
    }
    __syncthreads();
    if (threadIdx.x == 0){
        int tg = tgt[t];
        float lse = sm_r[0] + logf(sm_r[1]);
        float nll = lse - row[tg];
        g_nll[t] = (tg != 0) ? nll : 0.f;
        g_val[t] = (tg != 0) ? 1.f : 0.f;
    }
}

__global__ void loss_reduce_kernel(float* __restrict__ out_loss){
    float a = 0.f, b = 0.f;
    for (int t = threadIdx.x; t < TT; t += blockDim.x){ a += g_nll[t]; b += g_val[t]; }
    a = blockSum(a);
    b = blockSum(b);
    if (threadIdx.x == 0) *out_loss = a / fmaxf(b, 1.f);
}

// ---------------- launch ----------------
extern "C" void kernel_launch(void* const* d_in, const int* in_sizes, int n_in,
                              void* d_out, int out_size){
    (void)in_sizes; (void)n_in;
    const int*   x     = (const int*)  d_in[0];
    const int*   tgt   = (const int*)  d_in[1];
    const float* tok   = (const float*)d_in[2];
    const float* pos   = (const float*)d_in[3];
    const float* Wqkv  = (const float*)d_in[4];
    const float* Wo    = (const float*)d_in[5];
    const float* ln1g  = (const float*)d_in[6];
    const float* ln1b  = (const float*)d_in[7];
    const float* ln2g  = (const float*)d_in[8];
    const float* ln2b  = (const float*)d_in[9];
    const float* W1    = (const float*)d_in[10];
    const float* b1    = (const float*)d_in[11];
    const float* W2    = (const float*)d_in[12];
    const float* b2    = (const float*)d_in[13];
    const float* lnfg  = (const float*)d_in[14];
    const float* lnfb  = (const float*)d_in[15];
    float* out = (float*)d_out;

    float *ph;
    __half *pqkv_hi, *pqkv_lo, *phn_hi, *phn_lo, *pctx_hi, *pctx_lo, *pff_hi, *pff_lo;
    __half *pwqkv, *pwo, *pw1, *pw2, *ptok;
    cudaGetSymbolAddress((void**)&ph,      g_h);
    cudaGetSymbolAddress((void**)&pqkv_hi, g_qkv_hi);
    cudaGetSymbolAddress((void**)&pqkv_lo, g_qkv_lo);
    cudaGetSymbolAddress((void**)&phn_hi,  g_hn_hi);
    cudaGetSymbolAddress((void**)&phn_lo,  g_hn_lo);
    cudaGetSymbolAddress((void**)&pctx_hi, g_ctx_hi);
    cudaGetSymbolAddress((void**)&pctx_lo, g_ctx_lo);
    cudaGetSymbolAddress((void**)&pff_hi,  g_ff_hi);
    cudaGetSymbolAddress((void**)&pff_lo,  g_ff_lo);
    cudaGetSymbolAddress((void**)&pwqkv,   w_qkv_h);
    cudaGetSymbolAddress((void**)&pwo,     w_o_h);
    cudaGetSymbolAddress((void**)&pw1,     w_1_h);
    cudaGetSymbolAddress((void**)&pw2,     w_2_h);
    cudaGetSymbolAddress((void**)&ptok,    w_tok_h);

    cudaFuncSetAttribute(gemm_mma<0,0,0,1>, cudaFuncAttributeMaxDynamicSharedMemorySize, G_SMEM);
    cudaFuncSetAttribute(gemm_mma<1,1,0,1>, cudaFuncAttributeMaxDynamicSharedMemorySize, G_SMEM);
    cudaFuncSetAttribute(gemm_mma<0,0,0,0>, cudaFuncAttributeMaxDynamicSharedMemorySize, G_SMEM);
    cudaFuncSetAttribute(gemm_mma64<0,1>,   cudaFuncAttributeMaxDynamicSharedMemorySize, G64_SMEM);
    cudaFuncSetAttribute(gemm_mma64<1,1>,   cudaFuncAttributeMaxDynamicSharedMemorySize, G64_SMEM);
    cudaFuncSetAttribute(attn_tc, cudaFuncAttributeMaxDynamicSharedMemorySize, ATT_SMEM);

    cvt_kernel<<<1024, 256>>>(Wqkv, pwqkv, LL*QKV3*DD);
    cvt_kernel<<<1024, 256>>>(Wo,   pwo,   LL*DD*DD);
    cvt_kernel<<<1024, 256>>>(W1,   pw1,   LL*FFD*DD);
    cvt_kernel<<<1024, 256>>>(W2,   pw2,   LL*DD*FFD);
    cvt_kernel<<<2048, 256>>>(tok,  ptok,  VV*DD);

    embed_kernel<<<TT, 256>>>(x, tok, pos);

    for (int l = 0; l < LL; l++){
        ln_kernel_hl<<<TT, 256>>>(ph, phn_hi, phn_lo, ln1g + l*DD, ln1b + l*DD);
        gemm_mma<0,0,0,1><<<dim3(TT/128, QKV3/128), 256, G_SMEM>>>(
            phn_hi, phn_lo, pwqkv + (size_t)l*QKV3*DD, nullptr, nullptr,
            nullptr, pqkv_hi, pqkv_lo, TT, QKV3, DD);
        attn_tc<<<dim3(TT/64, HH), 128, ATT_SMEM>>>();
        gemm_mma64<0,1><<<dim3(TT/64, DD/128), 256, G64_SMEM>>>(
            pctx_hi, pctx_lo, pwo + (size_t)l*DD*DD, nullptr, ph,
            ph, TT, DD, DD);
        ln_kernel_hl<<<TT, 256>>>(ph, phn_hi, phn_lo, ln2g + l*DD, ln2b + l*DD);
        gemm_mma<1,1,0,1><<<dim3(TT/128, FFD/128), 256, G_SMEM>>>(
            phn_hi, phn_lo, pw1 + (size_t)l*FFD*DD, b1 + (size_t)l*FFD, nullptr,
            nullptr, pff_hi, pff_lo, TT, FFD, DD);
        gemm_mma64<1,1><<<dim3(TT/64, DD/128), 256, G64_SMEM>>>(
            pff_hi, pff_lo, pw2 + (size_t)l*DD*FFD, b2 + (size_t)l*DD, ph,
            ph, TT, DD, FFD);
    }

    ln_kernel_hl<<<TT, 256>>>(ph, phn_hi, phn_lo, lnfg, lnfb);
    gemm_mma<0,0,0,0><<<dim3(TT/128, VV/128), 256, G_SMEM>>>(
        phn_hi, phn_lo, ptok, nullptr, nullptr,
        out, nullptr, nullptr, TT, VV, DD);

    row_lse_kernel<<<TT, 256>>>(out, tgt);
    if (out_size > TT * VV)
        loss_reduce_kernel<<<1, 256>>>(out + (size_t)TT * VV);
}

// round 14
// speedup vs baseline: 1.2489x; 1.0225x over previous
#include <cuda_runtime.h>
#include <cuda_bf16.h>
#include <cuda_fp16.h>
#include <math.h>
#include <stdint.h>

// Problem constants
#define TT   2048
#define DD   768
#define HH   12
#define DHH  64
#define LL   6
#define FFD  3072
#define VV   32000
#define QKV3 (3*DD)

// ---------------- scratch ----------------
__device__ float  g_h  [TT*DD];
__device__ float  g_nll[TT];
__device__ float  g_val[TT];
__device__ __half g_qkv_hi[TT*QKV3];
__device__ __half g_qkv_lo[TT*QKV3];
__device__ __half g_hn_hi [TT*DD];
__device__ __half g_hn_lo [TT*DD];
__device__ __half g_ctx_hi[TT*DD];
__device__ __half g_ctx_lo[TT*DD];
__device__ __half g_ff_hi [TT*FFD];
__device__ __half g_ff_lo [TT*FFD];
// fp16 weights (converted once per launch)
__device__ __half w_qkv_h[LL*QKV3*DD];
__device__ __half w_o_h  [LL*DD*DD];
__device__ __half w_1_h  [LL*FFD*DD];
__device__ __half w_2_h  [LL*DD*FFD];
__device__ __half w_tok_h[(size_t)VV*DD];

// ---------------- helpers ----------------
__device__ __forceinline__ uint32_t smem_u32(const void* p){
    uint32_t a;
    asm("{ .reg .u64 t; cvta.to.shared.u64 t, %1; cvt.u32.u64 %0, t; }" : "=r"(a) : "l"(p));
    return a;
}
__device__ __forceinline__ uint32_t packhf(float x0, float x1){
    uint32_t r;
    asm("cvt.rn.f16x2.f32 %0, %1, %2;" : "=r"(r) : "f"(x1), "f"(x0));
    return r;
}
__device__ __forceinline__ float h2f_lo(uint32_t p){
    float f; asm("{ .reg .b16 h, dummy; mov.b32 {h, dummy}, %1; cvt.f32.f16 %0, h; }" : "=f"(f) : "r"(p));
    return f;
}
__device__ __forceinline__ float h2f_hi(uint32_t p){
    float f; asm("{ .reg .b16 h, dummy; mov.b32 {dummy, h}, %1; cvt.f32.f16 %0, h; }" : "=f"(f) : "r"(p));
    return f;
}
__device__ __forceinline__ float ex2f(float x){
    float y; asm("ex2.approx.f32 %0, %1;" : "=f"(y) : "f"(x)); return y;
}
__device__ __forceinline__ void ldsm4(uint32_t &r0, uint32_t &r1, uint32_t &r2, uint32_t &r3,
                                      uint32_t addr){
    asm volatile("ldmatrix.sync.aligned.m8n8.x4.shared.b16 {%0,%1,%2,%3}, [%4];"
        : "=r"(r0), "=r"(r1), "=r"(r2), "=r"(r3) : "r"(addr));
}
__device__ __forceinline__ void ldsm4t(uint32_t &r0, uint32_t &r1, uint32_t &r2, uint32_t &r3,
                                       uint32_t addr){
    asm volatile("ldmatrix.sync.aligned.m8n8.x4.trans.shared.b16 {%0,%1,%2,%3}, [%4];"
        : "=r"(r0), "=r"(r1), "=r"(r2), "=r"(r3) : "r"(addr));
}
__device__ __forceinline__ void mma16816h(float* d, const uint32_t* a, const uint32_t* b){
    asm volatile("mma.sync.aligned.m16n8k16.row.col.f32.f16.f16.f32 "
        "{%0,%1,%2,%3}, {%4,%5,%6,%7}, {%8,%9}, {%0,%1,%2,%3};"
        : "+f"(d[0]), "+f"(d[1]), "+f"(d[2]), "+f"(d[3])
        : "r"(a[0]), "r"(a[1]), "r"(a[2]), "r"(a[3]), "r"(b[0]), "r"(b[1]));
}
#define CP_ASYNC16(dst, src) \
    asm volatile("cp.async.cg.shared.global [%0], [%1], 16;" :: "r"(dst), "l"(src) : "memory")
#define CP_COMMIT() asm volatile("cp.async.commit_group;" ::: "memory")
#define CP_WAIT1()  asm volatile("cp.async.wait_group 1;" ::: "memory")
#define CP_WAIT0()  asm volatile("cp.async.wait_group 0;" ::: "memory")

// ---------------- reductions ----------------
__device__ __forceinline__ float warpSum(float v){
#pragma unroll
    for (int o = 16; o; o >>= 1) v += __shfl_xor_sync(0xffffffffu, v, o);
    return v;
}
__device__ float blockSum(float v){
    __shared__ float s[9];
    __syncthreads();
    int lane = threadIdx.x & 31, w = threadIdx.x >> 5;
    v = warpSum(v);
    if (lane == 0) s[w] = v;
    __syncthreads();
    if (w == 0){
        float x = (lane < (int)(blockDim.x >> 5)) ? s[lane] : 0.f;
        x = warpSum(x);
        if (lane == 0) s[8] = x;
    }
    __syncthreads();
    return s[8];
}

// ---------------- fused fp32 -> fp16 weight conversion (one launch, 5 segments) ----
__global__ void cvt_all_kernel(const float* __restrict__ s0, __half* __restrict__ d0, int n0,
                               const float* __restrict__ s1, __half* __restrict__ d1, int n1,
                               const float* __restrict__ s2, __half* __restrict__ d2, int n2,
                               const float* __restrict__ s3, __half* __restrict__ d3, int n3,
                               const float* __restrict__ s4, __half* __restrict__ d4, int n4){
    const float* src; __half* dst; int n;
    switch (blockIdx.y){
        case 0: src = s0; dst = d0; n = n0; break;
        case 1: src = s1; dst = d1; n = n1; break;
        case 2: src = s2; dst = d2; n = n2; break;
        case 3: src = s3; dst = d3; n = n3; break;
        default: src = s4; dst = d4; n = n4; break;
    }
    int i = (blockIdx.x * blockDim.x + threadIdx.x) << 2;
    int stride = (gridDim.x * blockDim.x) << 2;
    for (; i < n; i += stride){
        float4 f = *(const float4*)(src + i);
        *(uint2*)&dst[i] = make_uint2(packhf(f.x, f.y), packhf(f.z, f.w));
    }
}

// ---------------- embedding ----------------
__global__ void embed_kernel(const int* __restrict__ x,
                             const float* __restrict__ tok,
                             const float* __restrict__ pos){
    int t  = blockIdx.x;
    int id = x[t];
    const float* tr = tok + (size_t)id * DD;
    const float* pr = pos + (size_t)t  * DD;
    for (int d = threadIdx.x; d < DD; d += blockDim.x)
        g_h[t*DD + d] = tr[d] + pr[d];
}

// ---------------- layernorm, warp-per-row (8 rows/block, no barriers) ----------------
__global__ __launch_bounds__(256)
void ln_kernel_hl(const float* __restrict__ in,
                  __half* __restrict__ ohi, __half* __restrict__ olo,
                  const float* __restrict__ g, const float* __restrict__ b){
    const int lane = threadIdx.x & 31, w = threadIdx.x >> 5;
    const int t = (blockIdx.x << 3) + w;
    const float* r = in + (size_t)t * DD;

    float4 v[6];
    float s = 0.f;
#pragma unroll
    for (int i = 0; i < 6; i++){
        v[i] = *(const float4*)(r + (lane << 2) + (i << 7));
        s += v[i].x + v[i].y + v[i].z + v[i].w;
    }
    s = warpSum(s);
    float mean = s * (1.f / DD);
    float q = 0.f;
#pragma unroll
    for (int i = 0; i < 6; i++){
        float a0 = v[i].x - mean, a1 = v[i].y - mean, a2 = v[i].z - mean, a3 = v[i].w - mean;
        q += a0*a0 + a1*a1 + a2*a2 + a3*a3;
    }
    q = warpSum(q);
    float rstd = rsqrtf(q * (1.f / DD) + 1e-5f);
#pragma unroll
    for (int i = 0; i < 6; i++){
        int c = (lane << 2) + (i << 7);
        float4 gg = *(const float4*)(g + c);
        float4 bb = *(const float4*)(b + c);
        float y0 = (v[i].x - mean) * rstd * gg.x + bb.x;
        float y1 = (v[i].y - mean) * rstd * gg.y + bb.y;
        float y2 = (v[i].z - mean) * rstd * gg.z + bb.z;
        float y3 = (v[i].w - mean) * rstd * gg.w + bb.w;
        uint32_t h0 = packhf(y0, y1), h1 = packhf(y2, y3);
        uint32_t l0 = packhf(y0 - h2f_lo(h0), y1 - h2f_hi(h0));
        uint32_t l1 = packhf(y2 - h2f_lo(h1), y3 - h2f_hi(h1));
        *(uint2*)&ohi[(size_t)t*DD + c] = make_uint2(h0, h1);
        *(uint2*)&olo[(size_t)t*DD + c] = make_uint2(l0, l1);
    }
}

// ================== fp16 2-product GEMM, cp.async 3-stage, 2 CTAs/SM ==========
#define ROWB 80
#define STAGE_B 30720
#define G_SMEM (3*STAGE_B)

template<int BIASF, int GELUF, int RESF, int OUTHL>
__global__ __launch_bounds__(256, 2)
void gemm_mma(const __half* __restrict__ Ahi, const __half* __restrict__ Alo,
              const __half* __restrict__ Bw,
              const float* __restrict__ bias, const float* __restrict__ res,
              float* __restrict__ C, __half* __restrict__ Chi, __half* __restrict__ Clo,
              int M, int N, int K)
{
    extern __shared__ char smem[];
    const uint32_t sb = smem_u32(smem);
    const int tid = threadIdx.x, wid = tid >> 5, lane = tid & 31;
    const int m0 = blockIdx.x << 7, n0 = blockIdx.y << 7;
    const int wm = (wid >> 2) << 6;
    const int wn = (wid & 3) << 5;

    const int lrow = tid >> 2;
    const int k16  = tid & 3;
    const __half* aHp = Ahi + (size_t)(m0 + lrow) * K + (k16 << 3);
    const __half* aLp = Alo + (size_t)(m0 + lrow) * K + (k16 << 3);
    const __half* bP  = Bw  + (size_t)(n0 + lrow) * K + (k16 << 3);
    const uint32_t dOff = (uint32_t)(lrow * ROWB + (k16 << 4));

    float acc[4][4][4];
#pragma unroll
    for (int i = 0; i < 4; i++)
#pragma unroll
        for (int j = 0; j < 4; j++)
#pragma unroll
            for (int k = 0; k < 4; k++) acc[i][j][k] = 0.f;

    const int NC = K >> 5;

    auto issue = [&](int c, int s){
        uint32_t d = sb + s * STAGE_B + dOff;
        const __half* a0 = aHp + (size_t)c * 32;
        const __half* a1 = aLp + (size_t)c * 32;
        const __half* b0 = bP  + (size_t)c * 32;
        CP_ASYNC16(d,                a0);
        CP_ASYNC16(d + 5120,         a0 + (size_t)64 * K);
        CP_ASYNC16(d + 10240,        a1);
        CP_ASYNC16(d + 10240 + 5120, a1 + (size_t)64 * K);
        CP_ASYNC16(d + 20480,        b0);
        CP_ASYNC16(d + 20480 + 5120, b0 + (size_t)64 * K);
    };

    issue(0, 0); CP_COMMIT();
    if (NC > 1){ issue(1, 1); CP_COMMIT(); }

    const int g  = lane >> 3, lr = lane & 7;
    const int arow_off = ((g & 1) << 3) + lr;
    const int akb      = (g >> 1) << 4;
    const int brow_off = ((g >> 1) << 3) + lr;
    const int bkb      = (g & 1) << 4;

    int st_c = 0;
    for (int c = 0; c < NC; c++){
        CP_WAIT1();
        __syncthreads();

        int st_n2 = st_c + 2; if (st_n2 >= 3) st_n2 -= 3;
        if (c + 2 < NC) issue(c + 2, st_n2);
        CP_COMMIT();

        const uint32_t st = sb + st_c * STAGE_B;
#pragma unroll
        for (int h = 0; h < 2; h++){
            uint32_t Bh[4][2];
#pragma unroll
            for (int nt2 = 0; nt2 < 2; nt2++){
                uint32_t bd = st + 20480 + (uint32_t)((wn + (nt2 << 4) + brow_off) * ROWB + (h << 5) + bkb);
                uint32_t r0, r1, r2, r3;
                ldsm4(r0, r1, r2, r3, bd);
                Bh[2*nt2][0] = r0; Bh[2*nt2][1] = r1; Bh[2*nt2+1][0] = r2; Bh[2*nt2+1][1] = r3;
            }
#pragma unroll
            for (int mt = 0; mt < 4; mt++){
                uint32_t Ah[4], Al[4];
                uint32_t ad = st + (uint32_t)((wm + (mt << 4) + arow_off) * ROWB + (h << 5) + akb);
                ldsm4(Ah[0], Ah[1], Ah[2], Ah[3], ad);
                ldsm4(Al[0], Al[1], Al[2], Al[3], ad + 10240);
#pragma unroll
                for (int nt = 0; nt < 4; nt++){
                    mma16816h(acc[mt][nt], Ah, Bh[nt]);
                    mma16816h(acc[mt][nt], Al, Bh[nt]);
                }
            }
        }
        st_c = st_c + 1; if (st_c >= 3) st_c = 0;
    }

    const int qr = lane >> 2, qc = lane & 3;
#pragma unroll
    for (int mt = 0; mt < 4; mt++){
#pragma unroll
        for (int p = 0; p < 2; p++){
            int m = m0 + wm + (mt << 4) + qr + (p << 3);
            size_t rowbase = (size_t)m * N;
#pragma unroll
            for (int nt = 0; nt < 4; nt++){
                int n = n0 + wn + (nt << 3) + (qc << 1);
                float v0 = acc[mt][nt][2*p], v1 = acc[mt][nt][2*p + 1];
                if (BIASF){ v0 += bias[n]; v1 += bias[n + 1]; }
                if (GELUF){
                    v0 = 0.5f * v0 * (1.f + erff(v0 * 0.70710678118654752f));
                    v1 = 0.5f * v1 * (1.f + erff(v1 * 0.70710678118654752f));
                }
                if (RESF){
                    float2 rr = *(const float2*)&res[rowbase + n];
                    v0 += rr.x; v1 += rr.y;
                }
                if (OUTHL){
                    uint32_t hh = packhf(v0, v1);
                    uint32_t ll = packhf(v0 - h2f_lo(hh), v1 - h2f_hi(hh));
                    *(uint32_t*)&Chi[rowbase + n] = hh;
                    *(uint32_t*)&Clo[rowbase + n] = ll;
                } else {
                    *(float2*)&C[rowbase + n] = make_float2(v0, v1);
                }
            }
        }
    }
}

// ================== 64x128-tile variant (for N=768 GEMMs) ==========
#define STAGE64_B 20480
#define G64_SMEM (3*STAGE64_B)

template<int BIASF, int RESF>
__global__ __launch_bounds__(256, 2)
void gemm_mma64(const __half* __restrict__ Ahi, const __half* __restrict__ Alo,
                const __half* __restrict__ Bw,
                const float* __restrict__ bias, const float* __restrict__ res,
                float* __restrict__ C, int M, int N, int K)
{
    extern __shared__ char smem[];
    const uint32_t sb = smem_u32(smem);
    const int tid = threadIdx.x, wid = tid >> 5, lane = tid & 31;
    const int m0 = blockIdx.x << 6, n0 = blockIdx.y << 7;
    const int wm = (wid >> 2) << 5;
    const int wn = (wid & 3) << 5;

    const int lrow = tid >> 2;
    const int k16  = tid & 3;
    const __half* aHp = Ahi + (size_t)(m0 + lrow) * K + (k16 << 3);
    const __half* aLp = Alo + (size_t)(m0 + lrow) * K + (k16 << 3);
    const __half* bP  = Bw  + (size_t)(n0 + lrow) * K + (k16 << 3);
    const uint32_t dOff = (uint32_t)(lrow * ROWB + (k16 << 4));

    float acc[2][4][4];
#pragma unroll
    for (int i = 0; i < 2; i++)
#pragma unroll
        for (int j = 0; j < 4; j++)
#pragma unroll
            for (int k = 0; k < 4; k++) acc[i][j][k] = 0.f;

    const int NC = K >> 5;

    auto issue = [&](int c, int s){
        uint32_t d = sb + s * STAGE64_B + dOff;
        const __half* a0 = aHp + (size_t)c * 32;
        const __half* a1 = aLp + (size_t)c * 32;
        const __half* b0 = bP  + (size_t)c * 32;
        CP_ASYNC16(d,                a0);
        CP_ASYNC16(d + 5120,         a1);
        CP_ASYNC16(d + 10240,        b0);
        CP_ASYNC16(d + 10240 + 5120, b0 + (size_t)64 * K);
    };

    issue(0, 0); CP_COMMIT();
    if (NC > 1){ issue(1, 1); CP_COMMIT(); }

    const int g  = lane >> 3, lr = lane & 7;
    const int arow_off = ((g & 1) << 3) + lr;
    const int akb      = (g >> 1) << 4;
    const int brow_off = ((g >> 1) << 3) + lr;
    const int bkb      = (g & 1) << 4;

    int st_c = 0;
    for (int c = 0; c < NC; c++){
        CP_WAIT1();
        __syncthreads();

        int st_n2 = st_c + 2; if (st_n2 >= 3) st_n2 -= 3;
        if (c + 2 < NC) issue(c + 2, st_n2);
        CP_COMMIT();

        const uint32_t st = sb + st_c * STAGE64_B;
#pragma unroll
        for (int h = 0; h < 2; h++){
            uint32_t Bh[4][2];
#pragma unroll
            for (int nt2 = 0; nt2 < 2; nt2++){
                uint32_t bd = st + 10240 + (uint32_t)((wn + (nt2 << 4) + brow_off) * ROWB + (h << 5) + bkb);
                uint32_t r0, r1, r2, r3;
                ldsm4(r0, r1, r2, r3, bd);
                Bh[2*nt2][0] = r0; Bh[2*nt2][1] = r1; Bh[2*nt2+1][0] = r2; Bh[2*nt2+1][1] = r3;
            }
#pragma unroll
            for (int mt = 0; mt < 2; mt++){
                uint32_t Ah[4], Al[4];
                uint32_t ad = st + (uint32_t)((wm + (mt << 4) + arow_off) * ROWB + (h << 5) + akb);
                ldsm4(Ah[0], Ah[1], Ah[2], Ah[3], ad);
                ldsm4(Al[0], Al[1], Al[2], Al[3], ad + 5120);
#pragma unroll
                for (int nt = 0; nt < 4; nt++){
                    mma16816h(acc[mt][nt], Ah, Bh[nt]);
                    mma16816h(acc[mt][nt], Al, Bh[nt]);
                }
            }
        }
        st_c = st_c + 1; if (st_c >= 3) st_c = 0;
    }

    const int qr = lane >> 2, qc = lane & 3;
#pragma unroll
    for (int mt = 0; mt < 2; mt++){
#pragma unroll
        for (int p = 0; p < 2; p++){
            int m = m0 + wm + (mt << 4) + qr + (p << 3);
            size_t rowbase = (size_t)m * N;
#pragma unroll
            for (int nt = 0; nt < 4; nt++){
                int n = n0 + wn + (nt << 3) + (qc << 1);
                float v0 = acc[mt][nt][2*p], v1 = acc[mt][nt][2*p + 1];
                if (BIASF){ v0 += bias[n]; v1 += bias[n + 1]; }
                if (RESF){
                    float2 rr = *(const float2*)&res[rowbase + n];
                    v0 += rr.x; v1 += rr.y;
                }
                *(float2*)&C[rowbase + n] = make_float2(v0, v1);
            }
        }
    }
}

// ================== flash attention: 64-q blocks, 128 threads, 2 CTAs/SM ==========
#define AROWB 144
#define KOFF_LO  9216
#define VOFF_HI 18432
#define ATT_STAGE 27648
#define ATT_SMEM (2*ATT_STAGE)

__global__ __launch_bounds__(128, 2)
void attn_tc(){
    extern __shared__ char smc[];
    const uint32_t sb = smem_u32(smc);
    const int tid = threadIdx.x, wid = tid >> 5, lane = tid & 31;
    const int qb = gridDim.x - 1 - (int)blockIdx.x;
    const int hh = blockIdx.y;
    const int q0 = qb << 6;
    const int wq = q0 + (wid << 4);

    const float SCL = 0.125f * 1.4426950408889634f;
    uint32_t qh[4][4], ql[4][4];
    {
        int r0 = wq + (lane >> 2);
        int c0 = (lane & 3) << 1;
#pragma unroll
        for (int kt = 0; kt < 4; kt++){
#pragma unroll
            for (int rr = 0; rr < 2; rr++){
                size_t idx = (size_t)(r0 + (rr << 3)) * QKV3 + hh * DHH + (kt << 4) + c0;
                uint32_t uh0 = *(const uint32_t*)&g_qkv_hi[idx];
                uint32_t ul0 = *(const uint32_t*)&g_qkv_lo[idx];
                uint32_t uh1 = *(const uint32_t*)&g_qkv_hi[idx + 8];
                uint32_t ul1 = *(const uint32_t*)&g_qkv_lo[idx + 8];
                float x0 = (h2f_lo(uh0) + h2f_lo(ul0)) * SCL;
                float x1 = (h2f_hi(uh0) + h2f_hi(ul0)) * SCL;
                float x2 = (h2f_lo(uh1) + h2f_lo(ul1)) * SCL;
                float x3 = (h2f_hi(uh1) + h2f_hi(ul1)) * SCL;
                uint32_t h0 = packhf(x0, x1), h1 = packhf(x2, x3);
                qh[kt][rr]     = h0;
                qh[kt][rr + 2] = h1;
                ql[kt][rr]     = packhf(x0 - h2f_lo(h0), x1 - h2f_hi(h0));
                ql[kt][rr + 2] = packhf(x2 - h2f_lo(h1), x3 - h2f_hi(h1));
            }
        }
    }

    float o[8][4];
#pragma unroll
    for (int i = 0; i < 8; i++){ o[i][0]=0.f; o[i][1]=0.f; o[i][2]=0.f; o[i][3]=0.f; }
    float mr0 = -INFINITY, mr1 = -INFINITY, lr0 = 0.f, lr1 = 0.f;

    const int jmax = qb;

    const int ldr = tid >> 1;
    const int hc  = (tid & 1) << 2;
    const __half* kHp = g_qkv_hi + (size_t)ldr * QKV3 + DD     + hh * DHH + (hc << 3);
    const __half* kLp = g_qkv_lo + (size_t)ldr * QKV3 + DD     + hh * DHH + (hc << 3);
    const __half* vHp = g_qkv_hi + (size_t)ldr * QKV3 + 2 * DD + hh * DHH + (hc << 3);
    const uint32_t dOff = (uint32_t)(ldr * AROWB + (hc << 4));

    auto issue = [&](int j, int s){
        uint32_t d = sb + s * ATT_STAGE + dOff;
        size_t adv = (size_t)(j << 6) * QKV3;
#pragma unroll
        for (int c = 0; c < 4; c++){
            CP_ASYNC16(d + (c << 4),            kHp + adv + (c << 3));
            CP_ASYNC16(d + KOFF_LO + (c << 4),  kLp + adv + (c << 3));
            CP_ASYNC16(d + VOFF_HI + (c << 4),  vHp + adv + (c << 3));
        }
    };

    issue(0, 0); CP_COMMIT();

    const int g  = lane >> 3, lr8 = lane & 7;
    const int brow_off = ((g >> 1) << 3) + lr8;
    const int bkb      = (g & 1) << 4;

    for (int j = 0; j <= jmax; j++){
        if (j < jmax){ issue(j + 1, (j + 1) & 1); CP_COMMIT(); CP_WAIT1(); }
        else { CP_WAIT0(); }
        __syncthreads();

        const uint32_t st = sb + (j & 1) * ATT_STAGE;

        {
            float s[8][4];
#pragma unroll
            for (int i = 0; i < 8; i++){ s[i][0]=0.f; s[i][1]=0.f; s[i][2]=0.f; s[i][3]=0.f; }
#pragma unroll
            for (int ks = 0; ks < 4; ks++){
                uint32_t kh[8][2], kl[8][2];
#pragma unroll
                for (int nt2 = 0; nt2 < 4; nt2++){
                    uint32_t ad = st + (uint32_t)(((nt2 << 4) + brow_off) * AROWB + (ks << 5) + bkb);
                    uint32_t r0, r1, r2, r3;
                    ldsm4(r0, r1, r2, r3, ad);
                    kh[2*nt2][0]=r0; kh[2*nt2][1]=r1; kh[2*nt2+1][0]=r2; kh[2*nt2+1][1]=r3;
                    ldsm4(r0, r1, r2, r3, ad + KOFF_LO);
                    kl[2*nt2][0]=r0; kl[2*nt2][1]=r1; kl[2*nt2+1][0]=r2; kl[2*nt2+1][1]=r3;
                }
#pragma unroll
                for (int nt = 0; nt < 8; nt++){
                    mma16816h(s[nt], qh[ks], kh[nt]);
                    mma16816h(s[nt], ql[ks], kh[nt]);
                    mma16816h(s[nt], qh[ks], kl[nt]);
                }
            }
            if (j == jmax){
                int qr0 = wq + (lane >> 2);
#pragma unroll
                for (int nt = 0; nt < 8; nt++){
                    int kp = (j << 6) + (nt << 3) + ((lane & 3) << 1);
#pragma unroll
                    for (int e = 0; e < 4; e++){
                        int kpos = kp + (e & 1);
                        int qrow = qr0 + ((e >> 1) << 3);
                        if (kpos > qrow) s[nt][e] = -INFINITY;
                    }
                }
            }
            float mx0 = -INFINITY, mx1 = -INFINITY;
#pragma unroll
            for (int nt = 0; nt < 8; nt++){
                mx0 = fmaxf(mx0, fmaxf(s[nt][0], s[nt][1]));
                mx1 = fmaxf(mx1, fmaxf(s[nt][2], s[nt][3]));
            }
            mx0 = fmaxf(mx0, __shfl_xor_sync(0xffffffffu, mx0, 1));
            mx0 = fmaxf(mx0, __shfl_xor_sync(0xffffffffu, mx0, 2));
            mx1 = fmaxf(mx1, __shfl_xor_sync(0xffffffffu, mx1, 1));
            mx1 = fmaxf(mx1, __shfl_xor_sync(0xffffffffu, mx1, 2));
            float mn0 = fmaxf(mr0, mx0), mn1 = fmaxf(mr1, mx1);
            float a0 = ex2f(mr0 - mn0), a1 = ex2f(mr1 - mn1);
            mr0 = mn0; mr1 = mn1;
            lr0 *= a0; lr1 *= a1;
#pragma unroll
            for (int nt = 0; nt < 8; nt++){
                o[nt][0] *= a0; o[nt][1] *= a0; o[nt][2] *= a1; o[nt][3] *= a1;
            }
            float sum0 = 0.f, sum1 = 0.f;
#pragma unroll
            for (int nt = 0; nt < 8; nt++){
                s[nt][0] = ex2f(s[nt][0] - mn0);
                s[nt][1] = ex2f(s[nt][1] - mn0);
                s[nt][2] = ex2f(s[nt][2] - mn1);
                s[nt][3] = ex2f(s[nt][3] - mn1);
                sum0 += s[nt][0] + s[nt][1];
                sum1 += s[nt][2] + s[nt][3];
            }
            lr0 += sum0; lr1 += sum1;
#pragma unroll
            for (int kt = 0; kt < 4; kt++){
                uint32_t ph[4], pl[4];
                {
                    float p00 = s[2*kt][0],   p01 = s[2*kt][1];
                    float p10 = s[2*kt][2],   p11 = s[2*kt][3];
                    float p20 = s[2*kt+1][0], p21 = s[2*kt+1][1];
                    float p30 = s[2*kt+1][2], p31 = s[2*kt+1][3];
                    ph[0] = packhf(p00, p01); ph[1] = packhf(p10, p11);
                    ph[2] = packhf(p20, p21); ph[3] = packhf(p30, p31);
                    pl[0] = packhf(p00 - h2f_lo(ph[0]), p01 - h2f_hi(ph[0]));
                    pl[1] = packhf(p10 - h2f_lo(ph[1]), p11 - h2f_hi(ph[1]));
                    pl[2] = packhf(p20 - h2f_lo(ph[2]), p21 - h2f_hi(ph[2]));
                    pl[3] = packhf(p30 - h2f_lo(ph[3]), p31 - h2f_hi(ph[3]));
                }
#pragma unroll
                for (int nt2 = 0; nt2 < 4; nt2++){
                    uint32_t va = st + VOFF_HI +
                        (uint32_t)(((kt << 4) + (lane & 15)) * AROWB + (((nt2 << 4) + ((lane >> 4) << 3)) << 1));
                    uint32_t r0, r1, r2, r3;
                    ldsm4t(r0, r1, r2, r3, va);
                    uint32_t bh0[2] = {r0, r1}, bh1[2] = {r2, r3};
                    mma16816h(o[2*nt2],   ph, bh0);
                    mma16816h(o[2*nt2],   pl, bh0);
                    mma16816h(o[2*nt2+1], ph, bh1);
                    mma16816h(o[2*nt2+1], pl, bh1);
                }
            }
        }
        __syncthreads();
    }

    lr0 += __shfl_xor_sync(0xffffffffu, lr0, 1);
    lr0 += __shfl_xor_sync(0xffffffffu, lr0, 2);
    lr1 += __shfl_xor_sync(0xffffffffu, lr1, 1);
    lr1 += __shfl_xor_sync(0xffffffffu, lr1, 2);
    float inv0 = 1.f / lr0, inv1 = 1.f / lr1;
    int qrow = wq + (lane >> 2);
    int cc = hh * DHH + ((lane & 3) << 1);
#pragma unroll
    for (int nt = 0; nt < 8; nt++){
        {
            float v0 = o[nt][0] * inv0, v1 = o[nt][1] * inv0;
            uint32_t hh0 = packhf(v0, v1);
            uint32_t ll0 = packhf(v0 - h2f_lo(hh0), v1 - h2f_hi(hh0));
            size_t idx = (size_t)qrow * DD + cc + (nt << 3);
            *(uint32_t*)&g_ctx_hi[idx] = hh0;
            *(uint32_t*)&g_ctx_lo[idx] = ll0;
        }
        {
            float v0 = o[nt][2] * inv1, v1 = o[nt][3] * inv1;
            uint32_t hh0 = packhf(v0, v1);
            uint32_t ll0 = packhf(v0 - h2f_lo(hh0), v1 - h2f_hi(hh0));
            size_t idx = (size_t)(qrow + 8) * DD + cc + (nt << 3);
            *(uint32_t*)&g_ctx_hi[idx] = hh0;
            *(uint32_t*)&g_ctx_lo[idx] = ll0;
        }
    }
}

// ---------------- loss: one-pass online LSE ----------------
__global__ void row_lse_kernel(const float* __restrict__ logits, const int* __restrict__ tgt){
    __shared__ float sm_m[8], sm_s[8], sm_r[2];
    int t = blockIdx.x;
    const float* row = logits + (size_t)t * VV;
    int lane = threadIdx.x & 31, w = threadIdx.x >> 5;

    float m = -INFINITY, s = 0.f;
    for (int i = threadIdx.x; i < VV; i += blockDim.x){
        float v = row[i];
        if (v <= m){
            s += expf(v - m);
        } else {
            s = s * expf(m - v) + 1.f;
            m = v;
        }
    }
#pragma unroll
    for (int oo = 16; oo; oo >>= 1){
        float om = __shfl_xor_sync(0xffffffffu, m, oo);
        float os = __shfl_xor_sync(0xffffffffu, s, oo);
        float nm = fmaxf(m, om);
        s = s * expf(m - nm) + os * expf(om - nm);
        m = nm;
    }
    if (lane == 0){ sm_m[w] = m; sm_s[w] = s; }
    __syncthreads();
    if (w == 0){
        float mm = (lane < (int)(blockDim.x >> 5)) ? sm_m[lane] : -INFINITY;
        float ss = (lane < (int)(blockDim.x >> 5)) ? sm_s[lane] : 0.f;
#pragma unroll
        for (int oo = 4; oo; oo >>= 1){
            float om = __shfl_xor_sync(0xffffffffu, mm, oo);
            float os = __shfl_xor_sync(0xffffffffu, ss, oo);
            float nm = fmaxf(mm, om);
            ss = ss * expf(mm - nm) + os * expf(om - nm);
            mm = nm;
        }
        if (lane == 0){ sm_r[0] = mm; sm_r[1] = ss; }
    }
    __syncthreads();
    if (threadIdx.x == 0){
        int tg = tgt[t];
        float lse = sm_r[0] + logf(sm_r[1]);
        float nll = lse - row[tg];
        g_nll[t] = (tg != 0) ? nll : 0.f;
        g_val[t] = (tg != 0) ? 1.f : 0.f;
    }
}

__global__ void loss_reduce_kernel(float* __restrict__ out_loss){
    float a = 0.f, b = 0.f;
    for (int t = threadIdx.x; t < TT; t += blockDim.x){ a += g_nll[t]; b += g_val[t]; }
    a = blockSum(a);
    b = blockSum(b);
    if (threadIdx.x == 0) *out_loss = a / fmaxf(b, 1.f);
}

// ---------------- launch ----------------
extern "C" void kernel_launch(void* const* d_in, const int* in_sizes, int n_in,
                              void* d_out, int out_size){
    (void)in_sizes; (void)n_in;
    const int*   x     = (const int*)  d_in[0];
    const int*   tgt   = (const int*)  d_in[1];
    const float* tok   = (const float*)d_in[2];
    const float* pos   = (const float*)d_in[3];
    const float* Wqkv  = (const float*)d_in[4];
    const float* Wo    = (const float*)d_in[5];
    const float* ln1g  = (const float*)d_in[6];
    const float* ln1b  = (const float*)d_in[7];
    const float* ln2g  = (const float*)d_in[8];
    const float* ln2b  = (const float*)d_in[9];
    const float* W1    = (const float*)d_in[10];
    const float* b1    = (const float*)d_in[11];
    const float* W2    = (const float*)d_in[12];
    const float* b2    = (const float*)d_in[13];
    const float* lnfg  = (const float*)d_in[14];
    const float* lnfb  = (const float*)d_in[15];
    float* out = (float*)d_out;

    float *ph;
    __half *pqkv_hi, *pqkv_lo, *phn_hi, *phn_lo, *pctx_hi, *pctx_lo, *pff_hi, *pff_lo;
    __half *pwqkv, *pwo, *pw1, *pw2, *ptok;
    cudaGetSymbolAddress((void**)&ph,      g_h);
    cudaGetSymbolAddress((void**)&pqkv_hi, g_qkv_hi);
    cudaGetSymbolAddress((void**)&pqkv_lo, g_qkv_lo);
    cudaGetSymbolAddress((void**)&phn_hi,  g_hn_hi);
    cudaGetSymbolAddress((void**)&phn_lo,  g_hn_lo);
    cudaGetSymbolAddress((void**)&pctx_hi, g_ctx_hi);
    cudaGetSymbolAddress((void**)&pctx_lo, g_ctx_lo);
    cudaGetSymbolAddress((void**)&pff_hi,  g_ff_hi);
    cudaGetSymbolAddress((void**)&pff_lo,  g_ff_lo);
    cudaGetSymbolAddress((void**)&pwqkv,   w_qkv_h);
    cudaGetSymbolAddress((void**)&pwo,     w_o_h);
    cudaGetSymbolAddress((void**)&pw1,     w_1_h);
    cudaGetSymbolAddress((void**)&pw2,     w_2_h);
    cudaGetSymbolAddress((void**)&ptok,    w_tok_h);

    cudaFuncSetAttribute(gemm_mma<0,0,0,1>, cudaFuncAttributeMaxDynamicSharedMemorySize, G_SMEM);
    cudaFuncSetAttribute(gemm_mma<1,1,0,1>, cudaFuncAttributeMaxDynamicSharedMemorySize, G_SMEM);
    cudaFuncSetAttribute(gemm_mma<0,0,0,0>, cudaFuncAttributeMaxDynamicSharedMemorySize, G_SMEM);
    cudaFuncSetAttribute(gemm_mma64<0,1>,   cudaFuncAttributeMaxDynamicSharedMemorySize, G64_SMEM);
    cudaFuncSetAttribute(gemm_mma64<1,1>,   cudaFuncAttributeMaxDynamicSharedMemorySize, G64_SMEM);
    cudaFuncSetAttribute(attn_tc, cudaFuncAttributeMaxDynamicSharedMemorySize, ATT_SMEM);

    // one fused conversion launch (also shifts ncu -s 5 onto attn_tc)
    cvt_all_kernel<<<dim3(768, 5), 256>>>(
        Wqkv, pwqkv, LL*QKV3*DD,
        Wo,   pwo,   LL*DD*DD,
        W1,   pw1,   LL*FFD*DD,
        W2,   pw2,   LL*DD*FFD,
        tok,  ptok,  VV*DD);

    embed_kernel<<<TT, 256>>>(x, tok, pos);

    for (int l = 0; l < LL; l++){
        ln_kernel_hl<<<TT/8, 256>>>(ph, phn_hi, phn_lo, ln1g + l*DD, ln1b + l*DD);
        gemm_mma<0,0,0,1><<<dim3(TT/128, QKV3/128), 256, G_SMEM>>>(
            phn_hi, phn_lo, pwqkv + (size_t)l*QKV3*DD, nullptr, nullptr,
            nullptr, pqkv_hi, pqkv_lo, TT, QKV3, DD);
        attn_tc<<<dim3(TT/64, HH), 128, ATT_SMEM>>>();
        gemm_mma64<0,1><<<dim3(TT/64, DD/128), 256, G64_SMEM>>>(
            pctx_hi, pctx_lo, pwo + (size_t)l*DD*DD, nullptr, ph,
            ph, TT, DD, DD);
        ln_kernel_hl<<<TT/8, 256>>>(ph, phn_hi, phn_lo, ln2g + l*DD, ln2b + l*DD);
        gemm_mma<1,1,0,1><<<dim3(TT/128, FFD/128), 256, G_SMEM>>>(
            phn_hi, phn_lo, pw1 + (size_t)l*FFD*DD, b1 + (size_t)l*FFD, nullptr,
            nullptr, pff_hi, pff_lo, TT, FFD, DD);
        gemm_mma64<1,1><<<dim3(TT/64, DD/128), 256, G64_SMEM>>>(
            pff_hi, pff_lo, pw2 + (size_t)l*DD*FFD, b2 + (size_t)l*DD, ph,
            ph, TT, DD, FFD);
    }

    ln_kernel_hl<<<TT/8, 256>>>(ph, phn_hi, phn_lo, lnfg, lnfb);
    gemm_mma<0,0,0,0><<<dim3(TT/128, VV/128), 256, G_SMEM>>>(
        phn_hi, phn_lo, ptok, nullptr, nullptr,
        out, nullptr, nullptr, TT, VV, DD);

    row_lse_kernel<<<TT, 256>>>(out, tgt);
    if (out_size > TT * VV)
        loss_reduce_kernel<<<1, 256>>>(out + (size_t)TT * VV);
}